// round 1
// baseline (speedup 1.0000x reference)
#include <cuda_runtime.h>
#include <math.h>

#define NB 64
#define CB 256
#define SB 64
#define PB 16
#define KCL 4
#define HH 4
#define DD 64
#define BB (NB*PB)

// Scratch (device globals: allocation-free)
__device__ float g_xb[BB*SB*CB];        // (b, s, c)  64 MB
__device__ float g_clu[PB*NB*KCL*CB];   // (p, n, j*256+c)  4 MB
__device__ unsigned char g_hidx[PB*NB*SB];

// ---------------------------------------------------------------- K0: transpose
// x (n, c, s, p) -> g_xb (b = n*16+p, s, c)
__global__ __launch_bounds__(256) void k0_transpose(const float* __restrict__ x) {
    extern __shared__ float tile[];          // [s][p][17]  (ci dim padded 16->17)
    const int cchunk = blockIdx.x, n = blockIdx.y;
    const int t = threadIdx.x;
    const int c0 = cchunk * 16;
    #pragma unroll
    for (int it = 0; it < 16; it++) {
        int idx = it * 256 + t;              // float4 index (4096 total)
        int ci = idx >> 8;
        int rem = idx & 255;
        int s = rem >> 2;
        int p4 = rem & 3;
        const float4 v = *(const float4*)(x + (((size_t)n*CB + c0 + ci)*SB + s)*PB + p4*4);
        int base = (s*16 + p4*4)*17 + ci;
        tile[base] = v.x; tile[base+17] = v.y; tile[base+34] = v.z; tile[base+51] = v.w;
    }
    __syncthreads();
    #pragma unroll
    for (int it = 0; it < 16; it++) {
        int idx = it * 256 + t;
        int pair = idx >> 2, vec = idx & 3;
        int s = pair >> 4, p = pair & 15;
        int sb = (s*16 + p)*17 + vec*4;
        float4 v = make_float4(tile[sb], tile[sb+1], tile[sb+2], tile[sb+3]);
        *(float4*)(g_xb + (((size_t)n*16 + p)*SB + s)*CB + c0 + vec*4) = v;
    }
}

// ---------------------------------------------------------------- K1: instnorm + argmax assignment
__global__ __launch_bounds__(256) void k1_assign(const float* __restrict__ proto) {
    extern __shared__ float sm1[];
    float* xs = sm1;               // 64*257
    float* pn = xs + 64*257;       // 4*257
    float* mu = pn + 4*257;        // 256
    float* rv = mu + 256;          // 256
    __shared__ float nrm[4];
    const int b = blockIdx.x;
    const int n = b >> 4, p = b & 15;
    const int t = threadIdx.x;

    #pragma unroll
    for (int it = 0; it < 4; it++) {
        int i = it*256 + t; int k = i >> 8; int c = i & 255;
        pn[k*257 + c] = proto[((size_t)p*4 + k)*256 + c];
    }
    __syncthreads();
    if (t < 128) {
        int k = t >> 5, lane = t & 31; float s = 0.f;
        #pragma unroll
        for (int j = 0; j < 8; j++) { float v = pn[k*257 + lane + j*32]; s += v*v; }
        #pragma unroll
        for (int o = 16; o > 0; o >>= 1) s += __shfl_down_sync(0xffffffffu, s, o);
        if (lane == 0) nrm[k] = rsqrtf(s);
    }
    __syncthreads();
    #pragma unroll
    for (int it = 0; it < 4; it++) {
        int i = it*256 + t; int k = i >> 8; int c = i & 255;
        pn[k*257 + c] *= nrm[k];
    }
    const float* xg = g_xb + (size_t)b * SB * CB;
    for (int it = 0; it < 64; it++) {
        int i = it*256 + t; int s = i >> 8; int c = i & 255;
        xs[s*257 + c] = xg[i];
    }
    __syncthreads();
    { // stats per channel (two-pass variance, matches jnp.var)
        int c = t; float sum = 0.f;
        #pragma unroll 8
        for (int s = 0; s < 64; s++) sum += xs[s*257 + c];
        float m = sum * (1.f/64.f);
        float sq = 0.f;
        #pragma unroll 8
        for (int s = 0; s < 64; s++) { float d = xs[s*257 + c] - m; sq += d*d; }
        mu[c] = m;
        rv[c] = rsqrtf(sq * (1.f/64.f) + 1e-5f);
    }
    __syncthreads();
    { // sim + argmax (row norm drops out of argmax)
        int s = t >> 2, k = t & 3;
        float acc = 0.f;
        #pragma unroll 8
        for (int c = 0; c < 256; c++)
            acc += (xs[s*257 + c] - mu[c]) * rv[c] * pn[k*257 + c];
        float a1 = __shfl_down_sync(0xffffffffu, acc, 1);
        float a2 = __shfl_down_sync(0xffffffffu, acc, 2);
        float a3 = __shfl_down_sync(0xffffffffu, acc, 3);
        if (k == 0) {
            int bi = 0; float bv = acc;
            if (a1 > bv) { bv = a1; bi = 1; }
            if (a2 > bv) { bv = a2; bi = 2; }
            if (a3 > bv) { bv = a3; bi = 3; }
            g_hidx[((size_t)p*64 + n)*64 + s] = (unsigned char)bi;
        }
    }
}

// ---------------------------------------------------------------- K2: mode over parts
__global__ void k2_mode(float* __restrict__ out, int doWrite) {
    int id = blockIdx.x * 256 + threadIdx.x;   // (n, s), 4096 total
    int n = id >> 6, s = id & 63;
    int cnt[4] = {0,0,0,0};
    #pragma unroll
    for (int p = 0; p < 16; p++) cnt[g_hidx[((size_t)p*64 + n)*64 + s]]++;
    int bi = 0, bv = cnt[0];
    if (cnt[1] > bv) { bv = cnt[1]; bi = 1; }
    if (cnt[2] > bv) { bv = cnt[2]; bi = 2; }
    if (cnt[3] > bv) { bv = cnt[3]; bi = 3; }
    if (doWrite) out[NB*CB*PB + id] = (float)bi;
}

// ---------------------------------------------------------------- K3: attention + residual + pooled max
struct __align__(16) AttnSmem {
    float xs[64*260];   // input tile (also residual)
    float O [64*260];   // concat head outputs
    float Q [64*65];
    float Kv[64*65];
    float V [64*65];
    float Sc[64*65];    // scores / probs / Y-tile
    float Wb[64*64];    // streamed weight chunk
    float bb[64];
    int   idxs[64];
};

__device__ __forceinline__ void gemm64(
    const float* __restrict__ Asm, int lda,     // smem A, K = 256 at cols 0..255
    const float* __restrict__ Wg, int col0,     // global 256x256 weight, 64-col block
    const float* __restrict__ bias_g,
    float* __restrict__ Outp, int ldo,
    const float* __restrict__ res, int ldr,     // optional residual (smem)
    float* Wb, float* bb, int t)
{
    const int tx = t & 15, ty = t >> 4;
    const int d0 = tx*4, s0 = ty*4;
    float acc[4][4] = {};
    __syncthreads();                 // previous consumers of bb/Out done
    if (t < 64) bb[t] = bias_g[col0 + t];
    for (int c0 = 0; c0 < 256; c0 += 64) {
        __syncthreads();             // previous readers of Wb done
        #pragma unroll
        for (int it = 0; it < 4; it++) {
            int idx = it*256 + t;    // 1024 float4
            int kk = idx >> 4, d4 = idx & 15;
            *(float4*)(Wb + kk*64 + d4*4) =
                *(const float4*)(Wg + (size_t)(c0 + kk)*256 + col0 + d4*4);
        }
        __syncthreads();
        #pragma unroll 4
        for (int kk = 0; kk < 64; kk++) {
            float a[4];
            #pragma unroll
            for (int ii = 0; ii < 4; ii++) a[ii] = Asm[(s0+ii)*lda + c0 + kk];
            float4 bv = *(const float4*)(Wb + kk*64 + d0);
            float bj[4] = {bv.x, bv.y, bv.z, bv.w};
            #pragma unroll
            for (int ii = 0; ii < 4; ii++)
                #pragma unroll
                for (int jj = 0; jj < 4; jj++) acc[ii][jj] += a[ii]*bj[jj];
        }
    }
    __syncthreads();
    #pragma unroll
    for (int ii = 0; ii < 4; ii++)
        #pragma unroll
        for (int jj = 0; jj < 4; jj++) {
            float v = acc[ii][jj] + bb[d0 + jj];
            if (res) v += res[(s0+ii)*ldr + d0 + jj];
            Outp[(s0+ii)*ldo + d0 + jj] = v;
        }
}

__global__ __launch_bounds__(256, 1) void k3_attn(
    const float* __restrict__ Wq, const float* __restrict__ bq,
    const float* __restrict__ Wk, const float* __restrict__ bk,
    const float* __restrict__ Wv, const float* __restrict__ bv,
    const float* __restrict__ Wo, const float* __restrict__ bo)
{
    extern __shared__ char smraw[];
    AttnSmem& sm = *(AttnSmem*)smraw;
    const int b = blockIdx.x;
    const int n = b >> 4, p = b & 15;
    const int t = threadIdx.x;
    const int tx = t & 15, ty = t >> 4;

    const float* xg = g_xb + (size_t)b * SB * CB;
    #pragma unroll
    for (int it = 0; it < 16; it++) {
        int idx = it*256 + t; int s = idx >> 6; int c4 = idx & 63;
        *(float4*)(sm.xs + s*260 + c4*4) = *(const float4*)(xg + s*256 + c4*4);
    }
    if (t < 64) sm.idxs[t] = (int)g_hidx[((size_t)p*64 + n)*64 + t];
    __syncthreads();

    for (int h = 0; h < 4; h++) {
        gemm64(sm.xs, 260, Wq, h*64, bq, sm.Q , 65, nullptr, 0, sm.Wb, sm.bb, t);
        gemm64(sm.xs, 260, Wk, h*64, bk, sm.Kv, 65, nullptr, 0, sm.Wb, sm.bb, t);
        gemm64(sm.xs, 260, Wv, h*64, bv, sm.V , 65, nullptr, 0, sm.Wb, sm.bb, t);
        __syncthreads();
        { // scores = Q K^T / 8
            int j0 = tx*4, i0 = ty*4;
            float acc[4][4] = {};
            #pragma unroll 8
            for (int d = 0; d < 64; d++) {
                float a[4], bj[4];
                #pragma unroll
                for (int ii = 0; ii < 4; ii++) a[ii]  = sm.Q [(i0+ii)*65 + d];
                #pragma unroll
                for (int jj = 0; jj < 4; jj++) bj[jj] = sm.Kv[(j0+jj)*65 + d];
                #pragma unroll
                for (int ii = 0; ii < 4; ii++)
                    #pragma unroll
                    for (int jj = 0; jj < 4; jj++) acc[ii][jj] += a[ii]*bj[jj];
            }
            #pragma unroll
            for (int ii = 0; ii < 4; ii++)
                #pragma unroll
                for (int jj = 0; jj < 4; jj++)
                    sm.Sc[(i0+ii)*65 + j0+jj] = acc[ii][jj] * 0.125f;
        }
        __syncthreads();
        if (t < 64) { // causal softmax per row
            int i = t;
            float m = -1e30f;
            for (int j = 0; j <= i; j++) m = fmaxf(m, sm.Sc[i*65 + j]);
            float sum = 0.f;
            for (int j = 0; j <= i; j++) { float e = __expf(sm.Sc[i*65 + j] - m); sm.Sc[i*65 + j] = e; sum += e; }
            float inv = 1.f / sum;
            for (int j = 0; j <= i; j++) sm.Sc[i*65 + j] *= inv;
            for (int j = i+1; j < 64; j++) sm.Sc[i*65 + j] = 0.f;
        }
        __syncthreads();
        { // O[:, h*64:] = P @ V
            int d0 = tx*4, i0 = ty*4;
            float acc[4][4] = {};
            #pragma unroll 8
            for (int j = 0; j < 64; j++) {
                float a[4], bj[4];
                #pragma unroll
                for (int ii = 0; ii < 4; ii++) a[ii]  = sm.Sc[(i0+ii)*65 + j];
                #pragma unroll
                for (int jj = 0; jj < 4; jj++) bj[jj] = sm.V [j*65 + d0 + jj];
                #pragma unroll
                for (int ii = 0; ii < 4; ii++)
                    #pragma unroll
                    for (int jj = 0; jj < 4; jj++) acc[ii][jj] += a[ii]*bj[jj];
            }
            #pragma unroll
            for (int ii = 0; ii < 4; ii++)
                #pragma unroll
                for (int jj = 0; jj < 4; jj++)
                    sm.O[(i0+ii)*260 + h*64 + d0 + jj] = acc[ii][jj];
        }
        // next gemm64's entry sync orders PV stores vs reuse
    }

    // Y = O @ Wo + bo + residual, fused with cluster-max pooling per 64-col tile
    for (int ot = 0; ot < 4; ot++) {
        gemm64(sm.O, 260, Wo, ot*64, bo, sm.Sc, 65, sm.xs + ot*64, 260, sm.Wb, sm.bb, t);
        __syncthreads();
        {
            int o = t & 63, j = t >> 6;
            float m = -1e30f;
            #pragma unroll 8
            for (int s = 0; s < 64; s++) {
                float val = (sm.idxs[s] == j) ? sm.Sc[s*65 + o] : 0.f;
                m = fmaxf(m, val);
            }
            g_clu[((size_t)p*64 + n)*1024 + j*256 + ot*64 + o] = m;
        }
        // next gemm64's entry sync orders pooling reads vs Sc overwrite
    }
}

// ---------------------------------------------------------------- K4: per-part FC  out[n,o,p]
__global__ __launch_bounds__(256) void k4_fc(const float* __restrict__ fc, float* __restrict__ out) {
    __shared__ float As[64*68];
    __shared__ float Bs[64*64];
    const int p = blockIdx.x, ot = blockIdx.y;
    const int t = threadIdx.x;
    const int tx = t & 15, ty = t >> 4;
    const int o0 = tx*4, n0 = ty*4;
    float acc[4][4] = {};
    for (int k0 = 0; k0 < 1024; k0 += 64) {
        __syncthreads();
        #pragma unroll
        for (int it = 0; it < 4; it++) {
            int idx = it*256 + t;         // A: 1024 float4
            int nn = idx >> 4, k4 = idx & 15;
            *(float4*)(As + nn*68 + k4*4) =
                *(const float4*)(g_clu + ((size_t)p*64 + nn)*1024 + k0 + k4*4);
        }
        #pragma unroll
        for (int it = 0; it < 4; it++) {
            int idx = it*256 + t;         // B: 1024 float4
            int kk = idx >> 4, d4 = idx & 15;
            *(float4*)(Bs + kk*64 + d4*4) =
                *(const float4*)(fc + ((size_t)p*1024 + k0 + kk)*256 + ot*64 + d4*4);
        }
        __syncthreads();
        #pragma unroll 4
        for (int kk = 0; kk < 64; kk++) {
            float a[4];
            #pragma unroll
            for (int ii = 0; ii < 4; ii++) a[ii] = As[(n0+ii)*68 + kk];
            float4 bv = *(const float4*)(Bs + kk*64 + o0);
            float bj[4] = {bv.x, bv.y, bv.z, bv.w};
            #pragma unroll
            for (int ii = 0; ii < 4; ii++)
                #pragma unroll
                for (int jj = 0; jj < 4; jj++) acc[ii][jj] += a[ii]*bj[jj];
        }
    }
    #pragma unroll
    for (int ii = 0; ii < 4; ii++)
        #pragma unroll
        for (int jj = 0; jj < 4; jj++)
            out[((size_t)(n0+ii)*256 + ot*64 + o0 + jj)*16 + p] = acc[ii][jj];
}

// ---------------------------------------------------------------- launch
extern "C" void kernel_launch(void* const* d_in, const int* in_sizes, int n_in,
                              void* d_out, int out_size) {
    const float* x     = (const float*)d_in[0];
    const float* proto = (const float*)d_in[1];
    const float* Wq    = (const float*)d_in[2];
    const float* bq    = (const float*)d_in[3];
    const float* Wk    = (const float*)d_in[4];
    const float* bk    = (const float*)d_in[5];
    const float* Wv    = (const float*)d_in[6];
    const float* bv    = (const float*)d_in[7];
    const float* Wo    = (const float*)d_in[8];
    const float* bo    = (const float*)d_in[9];
    const float* fc    = (const float*)d_in[10];
    float* out = (float*)d_out;

    cudaFuncSetAttribute(k0_transpose, cudaFuncAttributeMaxDynamicSharedMemorySize, 69632);
    cudaFuncSetAttribute(k1_assign,    cudaFuncAttributeMaxDynamicSharedMemorySize, 73728);
    cudaFuncSetAttribute(k3_attn,      cudaFuncAttributeMaxDynamicSharedMemorySize, (int)sizeof(AttnSmem));

    k0_transpose<<<dim3(16, 64), 256, 69632>>>(x);
    k1_assign<<<BB, 256, (64*257 + 4*257 + 512) * sizeof(float)>>>(proto);
    int wtail = (out_size >= NB*CB*PB + NB*SB) ? 1 : 0;
    k2_mode<<<16, 256>>>(out, wtail);
    k3_attn<<<BB, 256, sizeof(AttnSmem)>>>(Wq, bq, Wk, bk, Wv, bv, Wo, bo);
    k4_fc<<<dim3(16, 4), 256>>>(fc, out);
}

// round 5
// speedup vs baseline: 1.9999x; 1.9999x over previous
#include <cuda_runtime.h>
#include <cuda_bf16.h>
#include <math.h>
#include <stdint.h>

#define NB 64
#define CB 256
#define SB 64
#define PB 16
#define KCL 4
#define RT (NB*PB*SB)          // 65536 total rows (b = n*16+p, s)

// ------------------------------------------------------------------ globals
__device__ float         g_xb[(size_t)RT*CB];     // X fp32 (b,s,c) exact
__device__ __nv_bfloat16 g_xh[(size_t)RT*CB];     // X hi
__device__ __nv_bfloat16 g_xl[(size_t)RT*CB];     // X lo
__device__ float         g_qkv[(size_t)RT*768];   // Q|K|V fp32
__device__ __nv_bfloat16 g_oh[(size_t)RT*CB];     // attn out hi
__device__ __nv_bfloat16 g_ol[(size_t)RT*CB];     // attn out lo
__device__ __nv_bfloat16 g_wh[1024*CB];           // weights hi: rows 0..767 = Wq|Wk|Wv^T, 768..1023 = Wo^T   [n][k]
__device__ __nv_bfloat16 g_wl[1024*CB];           // lo
__device__ float         g_biasv[1024];           // bq|bk|bv|bo
__device__ float         g_clu[PB*NB*KCL*CB];
__device__ unsigned char g_hidx[PB*NB*SB];

// ------------------------------------------------------------------ helpers
__device__ __forceinline__ uint32_t smem_u32(const void* p) {
    uint32_t a;
    asm("{ .reg .u64 t; cvta.to.shared.u64 t, %1; cvt.u32.u64 %0, t; }" : "=r"(a) : "l"(p));
    return a;
}
__device__ __forceinline__ void ldsm4(uint32_t a, uint32_t& r0, uint32_t& r1, uint32_t& r2, uint32_t& r3) {
    asm volatile("ldmatrix.sync.aligned.m8n8.x4.shared.b16 {%0,%1,%2,%3}, [%4];"
        : "=r"(r0), "=r"(r1), "=r"(r2), "=r"(r3) : "r"(a));
}
__device__ __forceinline__ void mma16816(float* d, const uint32_t* a, uint32_t b0, uint32_t b1) {
    asm volatile("mma.sync.aligned.m16n8k16.row.col.f32.bf16.bf16.f32 "
        "{%0,%1,%2,%3}, {%4,%5,%6,%7}, {%8,%9}, {%0,%1,%2,%3};"
        : "+f"(d[0]), "+f"(d[1]), "+f"(d[2]), "+f"(d[3])
        : "r"(a[0]), "r"(a[1]), "r"(a[2]), "r"(a[3]), "r"(b0), "r"(b1));
}

// ------------------------------------------------------------------ K0: transpose + bf16 split
// x (n, c, s, p) -> g_xb (fp32) + g_xh/g_xl (b = n*16+p, s, c)
__global__ __launch_bounds__(256) void k0_transpose(const float* __restrict__ x) {
    extern __shared__ float tile[];          // [(s*16+p)][17]
    const int cchunk = blockIdx.x, n = blockIdx.y;
    const int t = threadIdx.x;
    const int c0 = cchunk * 16;
    #pragma unroll
    for (int it = 0; it < 16; it++) {
        int idx = it * 256 + t;
        int ci = idx >> 8;
        int rem = idx & 255;
        int s = rem >> 2;
        int p4 = rem & 3;
        const float4 v = *(const float4*)(x + (((size_t)n*CB + c0 + ci)*SB + s)*PB + p4*4);
        int base = (s*16 + p4*4)*17 + ci;
        tile[base] = v.x; tile[base+17] = v.y; tile[base+34] = v.z; tile[base+51] = v.w;
    }
    __syncthreads();
    #pragma unroll
    for (int it = 0; it < 8; it++) {
        int idx = it * 256 + t;              // 2048: (s,p,vec8)
        int vec = idx & 1;
        int pr = idx >> 1;
        int s = pr >> 4, p = pr & 15;
        int base = (s*16 + p)*17 + vec*8;
        __align__(16) float f[8];
        __align__(16) __nv_bfloat16 hi[8];
        __align__(16) __nv_bfloat16 lo[8];
        #pragma unroll
        for (int u = 0; u < 8; u++) {
            float v = tile[base + u];
            f[u] = v;
            hi[u] = __float2bfloat16(v);
            lo[u] = __float2bfloat16(v - __bfloat162float(hi[u]));
        }
        size_t off = (((size_t)n*16 + p)*64 + s)*256 + c0 + vec*8;
        *(uint4*)(g_xb + off)     = *(uint4*)f;
        *(uint4*)(g_xb + off + 4) = *(uint4*)(f + 4);
        *(uint4*)(g_xh + off) = *(uint4*)hi;
        *(uint4*)(g_xl + off) = *(uint4*)lo;
    }
}

// ------------------------------------------------------------------ K_wprep: weights -> bf16 hi/lo, [n][k] layout
__global__ __launch_bounds__(256) void k_wprep(
    const float* __restrict__ Wq, const float* __restrict__ Wk,
    const float* __restrict__ Wv, const float* __restrict__ Wo,
    const float* __restrict__ bq, const float* __restrict__ bk,
    const float* __restrict__ bv, const float* __restrict__ bo)
{
    int nrow = blockIdx.x;     // 0..1023
    int k = threadIdx.x;       // 0..255
    float w;
    if (nrow < 256)      w = Wq[k*256 + nrow];
    else if (nrow < 512) w = Wk[k*256 + (nrow-256)];
    else if (nrow < 768) w = Wv[k*256 + (nrow-512)];
    else                 w = Wo[k*256 + (nrow-768)];
    __nv_bfloat16 h = __float2bfloat16(w);
    __nv_bfloat16 l = __float2bfloat16(w - __bfloat162float(h));
    g_wh[nrow*256 + k] = h;
    g_wl[nrow*256 + k] = l;
    if (k == 0) {
        float b;
        if (nrow < 256)      b = bq[nrow];
        else if (nrow < 512) b = bk[nrow-256];
        else if (nrow < 768) b = bv[nrow-512];
        else                 b = bo[nrow-768];
        g_biasv[nrow] = b;
    }
}

// ------------------------------------------------------------------ K1: instnorm + argmax assignment (exact fp32 input)
__global__ __launch_bounds__(256) void k1_assign(const float* __restrict__ proto) {
    extern __shared__ float sm1[];
    float* xs = sm1;               // 64*257
    float* pn = xs + 64*257;       // 4*257
    float* mu = pn + 4*257;        // 256
    float* rv = mu + 256;          // 256
    __shared__ float nrm[4];
    const int b = blockIdx.x;
    const int n = b >> 4, p = b & 15;
    const int t = threadIdx.x;

    #pragma unroll
    for (int it = 0; it < 4; it++) {
        int i = it*256 + t; int k = i >> 8; int c = i & 255;
        pn[k*257 + c] = proto[((size_t)p*4 + k)*256 + c];
    }
    __syncthreads();
    if (t < 128) {
        int k = t >> 5, lane = t & 31; float s = 0.f;
        #pragma unroll
        for (int j = 0; j < 8; j++) { float v = pn[k*257 + lane + j*32]; s += v*v; }
        #pragma unroll
        for (int o = 16; o > 0; o >>= 1) s += __shfl_down_sync(0xffffffffu, s, o);
        if (lane == 0) nrm[k] = rsqrtf(s);
    }
    __syncthreads();
    #pragma unroll
    for (int it = 0; it < 4; it++) {
        int i = it*256 + t; int k = i >> 8; int c = i & 255;
        pn[k*257 + c] *= nrm[k];
    }
    const float* xg = g_xb + (size_t)b * SB * CB;
    for (int it = 0; it < 64; it++) {
        int i = it*256 + t; int s = i >> 8; int c = i & 255;
        xs[s*257 + c] = xg[i];
    }
    __syncthreads();
    {
        int c = t; float sum = 0.f;
        #pragma unroll 8
        for (int s = 0; s < 64; s++) sum += xs[s*257 + c];
        float m = sum * (1.f/64.f);
        float sq = 0.f;
        #pragma unroll 8
        for (int s = 0; s < 64; s++) { float d = xs[s*257 + c] - m; sq += d*d; }
        mu[c] = m;
        rv[c] = rsqrtf(sq * (1.f/64.f) + 1e-5f);
    }
    __syncthreads();
    {
        int s = t >> 2, k = t & 3;
        float acc = 0.f;
        #pragma unroll 8
        for (int c = 0; c < 256; c++)
            acc += (xs[s*257 + c] - mu[c]) * rv[c] * pn[k*257 + c];
        float a1 = __shfl_down_sync(0xffffffffu, acc, 1);
        float a2 = __shfl_down_sync(0xffffffffu, acc, 2);
        float a3 = __shfl_down_sync(0xffffffffu, acc, 3);
        if (k == 0) {
            int bi = 0; float bv = acc;
            if (a1 > bv) { bv = a1; bi = 1; }
            if (a2 > bv) { bv = a2; bi = 2; }
            if (a3 > bv) { bv = a3; bi = 3; }
            g_hidx[((size_t)p*64 + n)*64 + s] = (unsigned char)bi;
        }
    }
}

// ------------------------------------------------------------------ K2: mode over parts
__global__ void k2_mode(float* __restrict__ out, int doWrite) {
    int id = blockIdx.x * 256 + threadIdx.x;
    int n = id >> 6, s = id & 63;
    int cnt[4] = {0,0,0,0};
    #pragma unroll
    for (int p = 0; p < 16; p++) cnt[g_hidx[((size_t)p*64 + n)*64 + s]]++;
    int bi = 0, bv = cnt[0];
    if (cnt[1] > bv) { bv = cnt[1]; bi = 1; }
    if (cnt[2] > bv) { bv = cnt[2]; bi = 2; }
    if (cnt[3] > bv) { bv = cnt[3]; bi = 3; }
    if (doWrite) out[NB*CB*PB + id] = (float)bi;
}

// ------------------------------------------------------------------ k_gemm: warp-MMA (HMMA bf16 m16n8k16, 3-term split)
// CTA tile: M=128, N=128, K=256 (2 staged chunks of 128).
// smem tiles padded to LDT=136 bf16/row (272B: conflict-free ldmatrix).
#define LDT 136
#define TILE_B (128*LDT*2)      // 34816
#define SM_AHo 0
#define SM_ALo TILE_B
#define SM_BHo (2*TILE_B)
#define SM_BLo (3*TILE_B)
#define GEMM_SMEM (4*TILE_B)    // 139264
#define YLD 132

__device__ __forceinline__ void load_tile_bf16(const __nv_bfloat16* __restrict__ src,
        size_t row0, int k0, char* dst, int t) {
    #pragma unroll
    for (int it = 0; it < 8; it++) {
        int v = it*256 + t;                  // 2048 16B-vectors: 128 rows x 16
        int r = v >> 4, kv = (v & 15) << 3;
        *(uint4*)(dst + (r*LDT + kv)*2) = *(const uint4*)(src + (row0 + r)*256 + k0 + kv);
    }
}

__global__ __launch_bounds__(256, 1) void k_gemm(int mode) {
    extern __shared__ char sm[];
    const uint32_t sb = smem_u32(sm);
    const int t = threadIdx.x;
    const int w = t >> 5, lane = t & 31;
    const int m0 = blockIdx.x * 128;
    const int ncta = blockIdx.y;             // 128-col block
    const int wy = w >> 1, wx = w & 1;
    const int m_base = wy*32, n_base = wx*64;
    __shared__ unsigned char sidx[128];

    if (mode == 1 && t < 128) {
        int b = (m0 >> 6) + (t >> 6);
        sidx[t] = g_hidx[((size_t)(b & 15)*64 + (b >> 4))*64 + (t & 63)];
    }

    const __nv_bfloat16* Ah_src = (mode == 0) ? g_xh : g_oh;
    const __nv_bfloat16* Al_src = (mode == 0) ? g_xl : g_ol;
    const int brow0 = (mode == 0) ? ncta*128 : 768 + ncta*128;

    float acc[2][8][4];
    #pragma unroll
    for (int i = 0; i < 2; i++)
        #pragma unroll
        for (int j = 0; j < 8; j++)
            #pragma unroll
            for (int q = 0; q < 4; q++) acc[i][j][q] = 0.f;

    // ldmatrix row addresses (per-thread), as offsets within a tile
    const int li = lane >> 3, lr = lane & 7;
    // A: matrix i -> (m + (i&1)*8 + r, k + (i>>1)*8)
    const int a_row = (li & 1)*8 + lr, a_kof = (li >> 1)*8;
    // B: matrix i -> (n + (i>>1)*8 + r, k + (i&1)*8)
    const int b_row = (li >> 1)*8 + lr, b_kof = (li & 1)*8;

    for (int chunk = 0; chunk < 2; chunk++) {
        int k0 = chunk * 128;
        __syncthreads();                     // previous chunk's readers done
        load_tile_bf16(Ah_src, (size_t)m0, k0, sm + SM_AHo, t);
        load_tile_bf16(Al_src, (size_t)m0, k0, sm + SM_ALo, t);
        load_tile_bf16(g_wh, (size_t)brow0, k0, sm + SM_BHo, t);
        load_tile_bf16(g_wl, (size_t)brow0, k0, sm + SM_BLo, t);
        __syncthreads();
        #pragma unroll
        for (int ks = 0; ks < 8; ks++) {
            const int kk = ks * 16;
            uint32_t ah[2][4], al[2][4];
            #pragma unroll
            for (int mf = 0; mf < 2; mf++) {
                uint32_t off = ((m_base + mf*16 + a_row)*LDT + kk + a_kof)*2;
                ldsm4(sb + SM_AHo + off, ah[mf][0], ah[mf][1], ah[mf][2], ah[mf][3]);
                ldsm4(sb + SM_ALo + off, al[mf][0], al[mf][1], al[mf][2], al[mf][3]);
            }
            #pragma unroll
            for (int nb = 0; nb < 4; nb++) {
                uint32_t off = ((n_base + nb*16 + b_row)*LDT + kk + b_kof)*2;
                uint32_t bh0, bh1, bh2, bh3, bl0, bl1, bl2, bl3;
                ldsm4(sb + SM_BHo + off, bh0, bh1, bh2, bh3);
                ldsm4(sb + SM_BLo + off, bl0, bl1, bl2, bl3);
                #pragma unroll
                for (int mf = 0; mf < 2; mf++) {
                    mma16816(acc[mf][nb*2],     ah[mf], bh0, bh1);
                    mma16816(acc[mf][nb*2 + 1], ah[mf], bh2, bh3);
                    mma16816(acc[mf][nb*2],     ah[mf], bl0, bl1);
                    mma16816(acc[mf][nb*2 + 1], ah[mf], bl2, bl3);
                    mma16816(acc[mf][nb*2],     al[mf], bh0, bh1);
                    mma16816(acc[mf][nb*2 + 1], al[mf], bh2, bh3);
                }
            }
        }
    }
    __syncthreads();                         // all mma readers done; reuse smem as Ys

    // write accumulators + bias into Ys [128][YLD]
    float* Ys = (float*)sm;
    {
        const int mr = lane >> 2, nc = (lane & 3)*2;
        #pragma unroll
        for (int mf = 0; mf < 2; mf++)
            #pragma unroll
            for (int nf = 0; nf < 8; nf++) {
                int m = m_base + mf*16 + mr;
                int n = n_base + nf*8 + nc;
                float b0 = g_biasv[brow0 + n], b1 = g_biasv[brow0 + n + 1];
                Ys[m*YLD + n]         = acc[mf][nf][0] + b0;
                Ys[m*YLD + n + 1]     = acc[mf][nf][1] + b1;
                Ys[(m + 8)*YLD + n]     = acc[mf][nf][2] + b0;
                Ys[(m + 8)*YLD + n + 1] = acc[mf][nf][3] + b1;
            }
    }
    __syncthreads();

    if (mode == 0) {
        for (int v = t; v < 4096; v += 256) {           // 128 rows x 32 float4
            int r = v >> 5, c4 = (v & 31) << 2;
            float4 val = make_float4(Ys[r*YLD + c4], Ys[r*YLD + c4 + 1],
                                     Ys[r*YLD + c4 + 2], Ys[r*YLD + c4 + 3]);
            *(float4*)(g_qkv + (size_t)(m0 + r)*768 + ncta*128 + c4) = val;
        }
    } else {
        // exact residual add
        for (int v = t; v < 4096; v += 256) {
            int r = v >> 5, c4 = (v & 31) << 2;
            float4 rx = *(const float4*)(g_xb + (size_t)(m0 + r)*256 + ncta*128 + c4);
            Ys[r*YLD + c4]     += rx.x;
            Ys[r*YLD + c4 + 1] += rx.y;
            Ys[r*YLD + c4 + 2] += rx.z;
            Ys[r*YLD + c4 + 3] += rx.w;
        }
        __syncthreads();
        // cluster-max pooling: 2 b's x 4 clusters x 128 local cols
        for (int id = t; id < 1024; id += 256) {
            int bl = id >> 9, j = (id >> 7) & 3, c = id & 127;
            float m = -1e30f;
            #pragma unroll 8
            for (int s = 0; s < 64; s++) {
                float v = (sidx[bl*64 + s] == j) ? Ys[(bl*64 + s)*YLD + c] : 0.f;
                m = fmaxf(m, v);
            }
            int b = (m0 >> 6) + bl;
            int n = b >> 4, p = b & 15;
            g_clu[((size_t)p*64 + n)*1024 + j*256 + ncta*128 + c] = m;
        }
    }
}

// ------------------------------------------------------------------ K_attn: SIMT attention core per (b, h)
__global__ __launch_bounds__(256) void k_attn() {
    extern __shared__ float sma[];
    float* Qs = sma;
    float* Ks = sma + 64*65;
    float* Vs = sma + 2*64*65;
    float* Ps = sma + 3*64*65;
    const int bid = blockIdx.x;
    const int b = bid >> 2, h = bid & 3;
    const int t = threadIdx.x;
    const size_t rbase = (size_t)b * 64;

    #pragma unroll
    for (int it = 0; it < 4; it++) {
        int idx = it*256 + t;                // 1024 = 64 s x 16 d4
        int s = idx >> 4, d4 = (idx & 15) << 2;
        const float* src = g_qkv + (rbase + s)*768 + h*64 + d4;
        float4 q = *(const float4*)src;
        float4 k = *(const float4*)(src + 256);
        float4 v = *(const float4*)(src + 512);
        Qs[s*65 + d4] = q.x; Qs[s*65 + d4 + 1] = q.y; Qs[s*65 + d4 + 2] = q.z; Qs[s*65 + d4 + 3] = q.w;
        Ks[s*65 + d4] = k.x; Ks[s*65 + d4 + 1] = k.y; Ks[s*65 + d4 + 2] = k.z; Ks[s*65 + d4 + 3] = k.w;
        Vs[s*65 + d4] = v.x; Vs[s*65 + d4 + 1] = v.y; Vs[s*65 + d4 + 2] = v.z; Vs[s*65 + d4 + 3] = v.w;
    }
    __syncthreads();
    const int tx = t & 15, ty = t >> 4;
    { // scores = Q K^T / 8
        int j0 = tx*4, i0 = ty*4;
        float acc[4][4] = {};
        #pragma unroll 8
        for (int d = 0; d < 64; d++) {
            float a[4], bj[4];
            #pragma unroll
            for (int ii = 0; ii < 4; ii++) a[ii]  = Qs[(i0+ii)*65 + d];
            #pragma unroll
            for (int jj = 0; jj < 4; jj++) bj[jj] = Ks[(j0+jj)*65 + d];
            #pragma unroll
            for (int ii = 0; ii < 4; ii++)
                #pragma unroll
                for (int jj = 0; jj < 4; jj++) acc[ii][jj] += a[ii]*bj[jj];
        }
        #pragma unroll
        for (int ii = 0; ii < 4; ii++)
            #pragma unroll
            for (int jj = 0; jj < 4; jj++)
                Ps[(i0+ii)*65 + j0 + jj] = acc[ii][jj] * 0.125f;
    }
    __syncthreads();
    { // causal softmax: warp w handles rows w*8..w*8+7
        int w = t >> 5, lane = t & 31;
        #pragma unroll
        for (int rr = 0; rr < 8; rr++) {
            int i = w*8 + rr;
            float v0 = (lane <= i) ? Ps[i*65 + lane] : -1e30f;
            float v1 = (lane + 32 <= i) ? Ps[i*65 + lane + 32] : -1e30f;
            float m = fmaxf(v0, v1);
            #pragma unroll
            for (int o = 16; o > 0; o >>= 1) m = fmaxf(m, __shfl_xor_sync(0xffffffffu, m, o));
            float e0 = (lane <= i) ? __expf(v0 - m) : 0.f;
            float e1 = (lane + 32 <= i) ? __expf(v1 - m) : 0.f;
            float ssum = e0 + e1;
            #pragma unroll
            for (int o = 16; o > 0; o >>= 1) ssum += __shfl_xor_sync(0xffffffffu, ssum, o);
            float inv = 1.f / ssum;
            Ps[i*65 + lane] = e0 * inv;
            Ps[i*65 + lane + 32] = e1 * inv;
        }
    }
    __syncthreads();
    { // O = P V, convert to bf16 hi/lo, store
        int d0 = tx*4, i0 = ty*4;
        float acc[4][4] = {};
        #pragma unroll 8
        for (int j = 0; j < 64; j++) {
            float a[4], bj[4];
            #pragma unroll
            for (int ii = 0; ii < 4; ii++) a[ii]  = Ps[(i0+ii)*65 + j];
            #pragma unroll
            for (int jj = 0; jj < 4; jj++) bj[jj] = Vs[j*65 + d0 + jj];
            #pragma unroll
            for (int ii = 0; ii < 4; ii++)
                #pragma unroll
                for (int jj = 0; jj < 4; jj++) acc[ii][jj] += a[ii]*bj[jj];
        }
        #pragma unroll
        for (int ii = 0; ii < 4; ii++) {
            size_t base = (rbase + i0 + ii)*256 + h*64 + d0;
            __nv_bfloat16 hi[4], lo[4];
            #pragma unroll
            for (int jj = 0; jj < 4; jj++) {
                float o = acc[ii][jj];
                hi[jj] = __float2bfloat16(o);
                lo[jj] = __float2bfloat16(o - __bfloat162float(hi[jj]));
            }
            __nv_bfloat162 h0; h0.x = hi[0]; h0.y = hi[1];
            __nv_bfloat162 h1; h1.x = hi[2]; h1.y = hi[3];
            __nv_bfloat162 l0; l0.x = lo[0]; l0.y = lo[1];
            __nv_bfloat162 l1; l1.x = lo[2]; l1.y = lo[3];
            *(__nv_bfloat162*)(g_oh + base) = h0;
            *(__nv_bfloat162*)(g_oh + base + 2) = h1;
            *(__nv_bfloat162*)(g_ol + base) = l0;
            *(__nv_bfloat162*)(g_ol + base + 2) = l1;
        }
    }
}

// ------------------------------------------------------------------ K4: per-part FC  out[n,o,p]
__global__ __launch_bounds__(256) void k4_fc(const float* __restrict__ fc, float* __restrict__ out) {
    __shared__ float As[64*68];
    __shared__ float Bs[64*64];
    const int p = blockIdx.x, ot = blockIdx.y;
    const int t = threadIdx.x;
    const int tx = t & 15, ty = t >> 4;
    const int o0 = tx*4, n0 = ty*4;
    float acc[4][4] = {};
    for (int k0 = 0; k0 < 1024; k0 += 64) {
        __syncthreads();
        #pragma unroll
        for (int it = 0; it < 4; it++) {
            int idx = it*256 + t;
            int nn = idx >> 4, k4 = idx & 15;
            *(float4*)(As + nn*68 + k4*4) =
                *(const float4*)(g_clu + ((size_t)p*64 + nn)*1024 + k0 + k4*4);
        }
        #pragma unroll
        for (int it = 0; it < 4; it++) {
            int idx = it*256 + t;
            int kk = idx >> 4, d4 = idx & 15;
            *(float4*)(Bs + kk*64 + d4*4) =
                *(const float4*)(fc + ((size_t)p*1024 + k0 + kk)*256 + ot*64 + d4*4);
        }
        __syncthreads();
        #pragma unroll 4
        for (int kk = 0; kk < 64; kk++) {
            float a[4];
            #pragma unroll
            for (int ii = 0; ii < 4; ii++) a[ii] = As[(n0+ii)*68 + kk];
            float4 bv = *(const float4*)(Bs + kk*64 + o0);
            float bj[4] = {bv.x, bv.y, bv.z, bv.w};
            #pragma unroll
            for (int ii = 0; ii < 4; ii++)
                #pragma unroll
                for (int jj = 0; jj < 4; jj++) acc[ii][jj] += a[ii]*bj[jj];
        }
    }
    #pragma unroll
    for (int ii = 0; ii < 4; ii++)
        #pragma unroll
        for (int jj = 0; jj < 4; jj++)
            out[((size_t)(n0+ii)*256 + ot*64 + o0 + jj)*16 + p] = acc[ii][jj];
}

// ------------------------------------------------------------------ launch
extern "C" void kernel_launch(void* const* d_in, const int* in_sizes, int n_in,
                              void* d_out, int out_size) {
    const float* x     = (const float*)d_in[0];
    const float* proto = (const float*)d_in[1];
    const float* Wq    = (const float*)d_in[2];
    const float* bq    = (const float*)d_in[3];
    const float* Wk    = (const float*)d_in[4];
    const float* bk    = (const float*)d_in[5];
    const float* Wv    = (const float*)d_in[6];
    const float* bv    = (const float*)d_in[7];
    const float* Wo    = (const float*)d_in[8];
    const float* bo    = (const float*)d_in[9];
    const float* fc    = (const float*)d_in[10];
    float* out = (float*)d_out;

    cudaFuncSetAttribute(k0_transpose, cudaFuncAttributeMaxDynamicSharedMemorySize, 69632);
    cudaFuncSetAttribute(k1_assign,    cudaFuncAttributeMaxDynamicSharedMemorySize, 73728);
    cudaFuncSetAttribute(k_gemm,       cudaFuncAttributeMaxDynamicSharedMemorySize, GEMM_SMEM);
    cudaFuncSetAttribute(k_attn,       cudaFuncAttributeMaxDynamicSharedMemorySize, 4*64*65*4);

    k_wprep<<<1024, 256>>>(Wq, Wk, Wv, Wo, bq, bk, bv, bo);
    k0_transpose<<<dim3(16, 64), 256, 69632>>>(x);
    k1_assign<<<NB*PB, 256, (64*257 + 4*257 + 512) * sizeof(float)>>>(proto);
    int wtail = (out_size >= NB*CB*PB + NB*SB) ? 1 : 0;
    k2_mode<<<16, 256>>>(out, wtail);
    k_gemm<<<dim3(512, 6), 256, GEMM_SMEM>>>(0);                 // QKV projections
    k_attn<<<4096, 256, 4*64*65*4>>>();                          // attention core
    k_gemm<<<dim3(512, 2), 256, GEMM_SMEM>>>(1);                 // O@Wo + residual + pooling
    k4_fc<<<dim3(16, 4), 256>>>(fc, out);
}

// round 6
// speedup vs baseline: 2.1248x; 1.0625x over previous
#include <cuda_runtime.h>
#include <cuda_bf16.h>
#include <math.h>
#include <stdint.h>

#define NB 64
#define CB 256
#define SB 64
#define PB 16
#define KCL 4
#define RT (NB*PB*SB)          // 65536 total rows (b = n*16+p, s)

// ------------------------------------------------------------------ globals
__device__ float         g_xb[(size_t)RT*CB];     // X fp32 (b,s,c) exact
__device__ __nv_bfloat16 g_xh[(size_t)RT*CB];     // X hi
__device__ __nv_bfloat16 g_xl[(size_t)RT*CB];     // X lo
__device__ float         g_qkv[(size_t)RT*768];   // Q|K|V fp32
__device__ __nv_bfloat16 g_oh[(size_t)RT*CB];     // attn out hi
__device__ __nv_bfloat16 g_ol[(size_t)RT*CB];     // attn out lo
__device__ __nv_bfloat16 g_wh[1024*CB];           // weights hi: rows 0..767 = Wq|Wk|Wv^T, 768..1023 = Wo^T   [n][k]
__device__ __nv_bfloat16 g_wl[1024*CB];           // lo
__device__ float         g_biasv[1024];           // bq|bk|bv|bo
__device__ float         g_clu[PB*NB*KCL*CB];
__device__ unsigned char g_hidx[PB*NB*SB];

// ------------------------------------------------------------------ helpers
__device__ __forceinline__ uint32_t smem_u32(const void* p) {
    uint32_t a;
    asm("{ .reg .u64 t; cvta.to.shared.u64 t, %1; cvt.u32.u64 %0, t; }" : "=r"(a) : "l"(p));
    return a;
}
__device__ __forceinline__ void ldsm4(uint32_t a, uint32_t& r0, uint32_t& r1, uint32_t& r2, uint32_t& r3) {
    asm volatile("ldmatrix.sync.aligned.m8n8.x4.shared.b16 {%0,%1,%2,%3}, [%4];"
        : "=r"(r0), "=r"(r1), "=r"(r2), "=r"(r3) : "r"(a));
}
__device__ __forceinline__ void mma16816(float* d, const uint32_t* a, uint32_t b0, uint32_t b1) {
    asm volatile("mma.sync.aligned.m16n8k16.row.col.f32.bf16.bf16.f32 "
        "{%0,%1,%2,%3}, {%4,%5,%6,%7}, {%8,%9}, {%0,%1,%2,%3};"
        : "+f"(d[0]), "+f"(d[1]), "+f"(d[2]), "+f"(d[3])
        : "r"(a[0]), "r"(a[1]), "r"(a[2]), "r"(a[3]), "r"(b0), "r"(b1));
}
__device__ __forceinline__ void cp16(uint32_t sa, const void* ga) {
    asm volatile("cp.async.cg.shared.global [%0], [%1], 16;" :: "r"(sa), "l"(ga));
}

// ------------------------------------------------------------------ K0: transpose + bf16 split
__global__ __launch_bounds__(256) void k0_transpose(const float* __restrict__ x) {
    extern __shared__ float tile[];          // [(s*16+p)][17]
    const int cchunk = blockIdx.x, n = blockIdx.y;
    const int t = threadIdx.x;
    const int c0 = cchunk * 16;
    #pragma unroll
    for (int it = 0; it < 16; it++) {
        int idx = it * 256 + t;
        int ci = idx >> 8;
        int rem = idx & 255;
        int s = rem >> 2;
        int p4 = rem & 3;
        const float4 v = *(const float4*)(x + (((size_t)n*CB + c0 + ci)*SB + s)*PB + p4*4);
        int base = (s*16 + p4*4)*17 + ci;
        tile[base] = v.x; tile[base+17] = v.y; tile[base+34] = v.z; tile[base+51] = v.w;
    }
    __syncthreads();
    #pragma unroll
    for (int it = 0; it < 8; it++) {
        int idx = it * 256 + t;              // 2048: (s,p,vec8)
        int vec = idx & 1;
        int pr = idx >> 1;
        int s = pr >> 4, p = pr & 15;
        int base = (s*16 + p)*17 + vec*8;
        __align__(16) float f[8];
        __align__(16) __nv_bfloat16 hi[8];
        __align__(16) __nv_bfloat16 lo[8];
        #pragma unroll
        for (int u = 0; u < 8; u++) {
            float v = tile[base + u];
            f[u] = v;
            hi[u] = __float2bfloat16(v);
            lo[u] = __float2bfloat16(v - __bfloat162float(hi[u]));
        }
        size_t off = (((size_t)n*16 + p)*64 + s)*256 + c0 + vec*8;
        *(uint4*)(g_xb + off)     = *(uint4*)f;
        *(uint4*)(g_xb + off + 4) = *(uint4*)(f + 4);
        *(uint4*)(g_xh + off) = *(uint4*)hi;
        *(uint4*)(g_xl + off) = *(uint4*)lo;
    }
}

// ------------------------------------------------------------------ K_wprep
__global__ __launch_bounds__(256) void k_wprep(
    const float* __restrict__ Wq, const float* __restrict__ Wk,
    const float* __restrict__ Wv, const float* __restrict__ Wo,
    const float* __restrict__ bq, const float* __restrict__ bk,
    const float* __restrict__ bv, const float* __restrict__ bo)
{
    int nrow = blockIdx.x;     // 0..1023
    int k = threadIdx.x;       // 0..255
    float w;
    if (nrow < 256)      w = Wq[k*256 + nrow];
    else if (nrow < 512) w = Wk[k*256 + (nrow-256)];
    else if (nrow < 768) w = Wv[k*256 + (nrow-512)];
    else                 w = Wo[k*256 + (nrow-768)];
    __nv_bfloat16 h = __float2bfloat16(w);
    __nv_bfloat16 l = __float2bfloat16(w - __bfloat162float(h));
    g_wh[nrow*256 + k] = h;
    g_wl[nrow*256 + k] = l;
    if (k == 0) {
        float b;
        if (nrow < 256)      b = bq[nrow];
        else if (nrow < 512) b = bk[nrow-256];
        else if (nrow < 768) b = bv[nrow-512];
        else                 b = bo[nrow-768];
        g_biasv[nrow] = b;
    }
}

// ------------------------------------------------------------------ K1: instnorm + argmax assignment
__global__ __launch_bounds__(256) void k1_assign(const float* __restrict__ proto) {
    extern __shared__ float sm1[];
    float* xs = sm1;               // 64*257
    float* pn = xs + 64*257;       // 4*257
    float* mu = pn + 4*257;        // 256
    float* rv = mu + 256;          // 256
    __shared__ float nrm[4];
    const int b = blockIdx.x;
    const int n = b >> 4, p = b & 15;
    const int t = threadIdx.x;

    #pragma unroll
    for (int it = 0; it < 4; it++) {
        int i = it*256 + t; int k = i >> 8; int c = i & 255;
        pn[k*257 + c] = proto[((size_t)p*4 + k)*256 + c];
    }
    __syncthreads();
    if (t < 128) {
        int k = t >> 5, lane = t & 31; float s = 0.f;
        #pragma unroll
        for (int j = 0; j < 8; j++) { float v = pn[k*257 + lane + j*32]; s += v*v; }
        #pragma unroll
        for (int o = 16; o > 0; o >>= 1) s += __shfl_down_sync(0xffffffffu, s, o);
        if (lane == 0) nrm[k] = rsqrtf(s);
    }
    __syncthreads();
    #pragma unroll
    for (int it = 0; it < 4; it++) {
        int i = it*256 + t; int k = i >> 8; int c = i & 255;
        pn[k*257 + c] *= nrm[k];
    }
    const float* xg = g_xb + (size_t)b * SB * CB;
    for (int it = 0; it < 64; it++) {
        int i = it*256 + t; int s = i >> 8; int c = i & 255;
        xs[s*257 + c] = xg[i];
    }
    __syncthreads();
    {
        int c = t; float sum = 0.f;
        #pragma unroll 8
        for (int s = 0; s < 64; s++) sum += xs[s*257 + c];
        float m = sum * (1.f/64.f);
        float sq = 0.f;
        #pragma unroll 8
        for (int s = 0; s < 64; s++) { float d = xs[s*257 + c] - m; sq += d*d; }
        mu[c] = m;
        rv[c] = rsqrtf(sq * (1.f/64.f) + 1e-5f);
    }
    __syncthreads();
    {
        int s = t >> 2, k = t & 3;
        float acc = 0.f;
        #pragma unroll 8
        for (int c = 0; c < 256; c++)
            acc += (xs[s*257 + c] - mu[c]) * rv[c] * pn[k*257 + c];
        float a1 = __shfl_down_sync(0xffffffffu, acc, 1);
        float a2 = __shfl_down_sync(0xffffffffu, acc, 2);
        float a3 = __shfl_down_sync(0xffffffffu, acc, 3);
        if (k == 0) {
            int bi = 0; float bv = acc;
            if (a1 > bv) { bv = a1; bi = 1; }
            if (a2 > bv) { bv = a2; bi = 2; }
            if (a3 > bv) { bv = a3; bi = 3; }
            g_hidx[((size_t)p*64 + n)*64 + s] = (unsigned char)bi;
        }
    }
}

// ------------------------------------------------------------------ K2: mode over parts
__global__ void k2_mode(float* __restrict__ out, int doWrite) {
    int id = blockIdx.x * 256 + threadIdx.x;
    int n = id >> 6, s = id & 63;
    int cnt[4] = {0,0,0,0};
    #pragma unroll
    for (int p = 0; p < 16; p++) cnt[g_hidx[((size_t)p*64 + n)*64 + s]]++;
    int bi = 0, bv = cnt[0];
    if (cnt[1] > bv) { bv = cnt[1]; bi = 1; }
    if (cnt[2] > bv) { bv = cnt[2]; bi = 2; }
    if (cnt[3] > bv) { bv = cnt[3]; bi = 3; }
    if (doWrite) out[NB*CB*PB + id] = (float)bi;
}

// ------------------------------------------------------------------ k_gemm: cp.async double-buffered warp-MMA
// CTA tile M=128, N=128; K chunked at 64 (4 chunks), 2 stages.
// LDT=72 bf16/row (144B): ldmatrix rows hit word-banks {0,4,...,28} -> conflict-free.
#define KC 64
#define LDT 72
#define TILE_B (128*LDT*2)      // 18432
#define STAGE_B (4*TILE_B)      // 73728
#define GEMM_SMEM (2*STAGE_B)   // 147456
#define YLD 132

__device__ __forceinline__ void load_tile_ca(const __nv_bfloat16* __restrict__ src,
        size_t row0, int k0, uint32_t dst_s, int t) {
    #pragma unroll
    for (int it = 0; it < 4; it++) {
        int v = it*256 + t;                  // 1024 vecs: 128 rows x 8
        int r = v >> 3, kv = (v & 7) << 3;
        cp16(dst_s + (uint32_t)(r*LDT + kv)*2, src + (row0 + r)*256 + k0 + kv);
    }
}

__global__ __launch_bounds__(256, 1) void k_gemm(int mode) {
    extern __shared__ char sm[];
    const uint32_t sb = smem_u32(sm);
    const int t = threadIdx.x;
    const int w = t >> 5, lane = t & 31;
    const int m0 = blockIdx.x * 128;
    const int ncta = blockIdx.y;             // 128-col block
    const int wy = w >> 1, wx = w & 1;
    const int m_base = wy*32, n_base = wx*64;
    __shared__ unsigned char sidx[128];

    if (mode == 1 && t < 128) {
        int b = (m0 >> 6) + (t >> 6);
        sidx[t] = g_hidx[((size_t)(b & 15)*64 + (b >> 4))*64 + (t & 63)];
    }

    const __nv_bfloat16* Ah_src = (mode == 0) ? g_xh : g_oh;
    const __nv_bfloat16* Al_src = (mode == 0) ? g_xl : g_ol;
    const int brow0 = (mode == 0) ? ncta*128 : 768 + ncta*128;

    float acc[2][8][4];
    #pragma unroll
    for (int i = 0; i < 2; i++)
        #pragma unroll
        for (int j = 0; j < 8; j++)
            #pragma unroll
            for (int q = 0; q < 4; q++) acc[i][j][q] = 0.f;

    const int li = lane >> 3, lr = lane & 7;
    const int a_row = (li & 1)*8 + lr, a_kof = (li >> 1)*8;
    const int b_row = (li >> 1)*8 + lr, b_kof = (li & 1)*8;

    // prefetch chunk 0 into stage 0
    {
        uint32_t st = sb;
        load_tile_ca(Ah_src, (size_t)m0, 0, st, t);
        load_tile_ca(Al_src, (size_t)m0, 0, st + TILE_B, t);
        load_tile_ca(g_wh, (size_t)brow0, 0, st + 2*TILE_B, t);
        load_tile_ca(g_wl, (size_t)brow0, 0, st + 3*TILE_B, t);
        asm volatile("cp.async.commit_group;" ::: "memory");
    }

    #pragma unroll
    for (int c = 0; c < 4; c++) {
        if (c < 3) {
            int k0 = (c + 1) * KC;
            uint32_t st = sb + ((c + 1) & 1) * STAGE_B;
            load_tile_ca(Ah_src, (size_t)m0, k0, st, t);
            load_tile_ca(Al_src, (size_t)m0, k0, st + TILE_B, t);
            load_tile_ca(g_wh, (size_t)brow0, k0, st + 2*TILE_B, t);
            load_tile_ca(g_wl, (size_t)brow0, k0, st + 3*TILE_B, t);
            asm volatile("cp.async.commit_group;" ::: "memory");
            asm volatile("cp.async.wait_group 1;" ::: "memory");
        } else {
            asm volatile("cp.async.wait_group 0;" ::: "memory");
        }
        __syncthreads();
        const uint32_t st = sb + (c & 1) * STAGE_B;
        #pragma unroll
        for (int ks = 0; ks < 4; ks++) {
            const int kk = ks * 16;
            uint32_t ah[2][4], al[2][4];
            #pragma unroll
            for (int mf = 0; mf < 2; mf++) {
                uint32_t off = (uint32_t)((m_base + mf*16 + a_row)*LDT + kk + a_kof)*2;
                ldsm4(st + off, ah[mf][0], ah[mf][1], ah[mf][2], ah[mf][3]);
                ldsm4(st + TILE_B + off, al[mf][0], al[mf][1], al[mf][2], al[mf][3]);
            }
            #pragma unroll
            for (int nb = 0; nb < 4; nb++) {
                uint32_t off = (uint32_t)((n_base + nb*16 + b_row)*LDT + kk + b_kof)*2;
                uint32_t bh0, bh1, bh2, bh3, bl0, bl1, bl2, bl3;
                ldsm4(st + 2*TILE_B + off, bh0, bh1, bh2, bh3);
                ldsm4(st + 3*TILE_B + off, bl0, bl1, bl2, bl3);
                #pragma unroll
                for (int mf = 0; mf < 2; mf++) {
                    mma16816(acc[mf][nb*2],     ah[mf], bh0, bh1);
                    mma16816(acc[mf][nb*2 + 1], ah[mf], bh2, bh3);
                    mma16816(acc[mf][nb*2],     ah[mf], bl0, bl1);
                    mma16816(acc[mf][nb*2 + 1], ah[mf], bl2, bl3);
                    mma16816(acc[mf][nb*2],     al[mf], bh0, bh1);
                    mma16816(acc[mf][nb*2 + 1], al[mf], bh2, bh3);
                }
            }
        }
        __syncthreads();                     // readers done before next-iter prefetch overwrites
    }

    // write accumulators + bias into Ys [128][YLD]
    float* Ys = (float*)sm;
    {
        const int mr = lane >> 2, nc = (lane & 3)*2;
        #pragma unroll
        for (int mf = 0; mf < 2; mf++)
            #pragma unroll
            for (int nf = 0; nf < 8; nf++) {
                int m = m_base + mf*16 + mr;
                int n = n_base + nf*8 + nc;
                float b0 = g_biasv[brow0 + n], b1 = g_biasv[brow0 + n + 1];
                Ys[m*YLD + n]         = acc[mf][nf][0] + b0;
                Ys[m*YLD + n + 1]     = acc[mf][nf][1] + b1;
                Ys[(m + 8)*YLD + n]     = acc[mf][nf][2] + b0;
                Ys[(m + 8)*YLD + n + 1] = acc[mf][nf][3] + b1;
            }
    }
    __syncthreads();

    if (mode == 0) {
        for (int v = t; v < 4096; v += 256) {           // 128 rows x 32 float4
            int r = v >> 5, c4 = (v & 31) << 2;
            float4 val = make_float4(Ys[r*YLD + c4], Ys[r*YLD + c4 + 1],
                                     Ys[r*YLD + c4 + 2], Ys[r*YLD + c4 + 3]);
            *(float4*)(g_qkv + (size_t)(m0 + r)*768 + ncta*128 + c4) = val;
        }
    } else {
        for (int v = t; v < 4096; v += 256) {
            int r = v >> 5, c4 = (v & 31) << 2;
            float4 rx = *(const float4*)(g_xb + (size_t)(m0 + r)*256 + ncta*128 + c4);
            Ys[r*YLD + c4]     += rx.x;
            Ys[r*YLD + c4 + 1] += rx.y;
            Ys[r*YLD + c4 + 2] += rx.z;
            Ys[r*YLD + c4 + 3] += rx.w;
        }
        __syncthreads();
        for (int id = t; id < 1024; id += 256) {
            int bl = id >> 9, j = (id >> 7) & 3, c = id & 127;
            float m = -1e30f;
            #pragma unroll 8
            for (int s = 0; s < 64; s++) {
                float v = (sidx[bl*64 + s] == j) ? Ys[(bl*64 + s)*YLD + c] : 0.f;
                m = fmaxf(m, v);
            }
            int b = (m0 >> 6) + bl;
            int n = b >> 4, p = b & 15;
            g_clu[((size_t)p*64 + n)*1024 + j*256 + ncta*128 + c] = m;
        }
    }
}

// ------------------------------------------------------------------ K_attn: SIMT attention core per (b, h)
__global__ __launch_bounds__(256) void k_attn() {
    extern __shared__ float sma[];
    float* Qs = sma;
    float* Ks = sma + 64*65;
    float* Vs = sma + 2*64*65;
    float* Ps = sma + 3*64*65;
    const int bid = blockIdx.x;
    const int b = bid >> 2, h = bid & 3;
    const int t = threadIdx.x;
    const size_t rbase = (size_t)b * 64;

    #pragma unroll
    for (int it = 0; it < 4; it++) {
        int idx = it*256 + t;                // 1024 = 64 s x 16 d4
        int s = idx >> 4, d4 = (idx & 15) << 2;
        const float* src = g_qkv + (rbase + s)*768 + h*64 + d4;
        float4 q = *(const float4*)src;
        float4 k = *(const float4*)(src + 256);
        float4 v = *(const float4*)(src + 512);
        Qs[s*65 + d4] = q.x; Qs[s*65 + d4 + 1] = q.y; Qs[s*65 + d4 + 2] = q.z; Qs[s*65 + d4 + 3] = q.w;
        Ks[s*65 + d4] = k.x; Ks[s*65 + d4 + 1] = k.y; Ks[s*65 + d4 + 2] = k.z; Ks[s*65 + d4 + 3] = k.w;
        Vs[s*65 + d4] = v.x; Vs[s*65 + d4 + 1] = v.y; Vs[s*65 + d4 + 2] = v.z; Vs[s*65 + d4 + 3] = v.w;
    }
    __syncthreads();
    const int tx = t & 15, ty = t >> 4;
    { // scores = Q K^T / 8
        int j0 = tx*4, i0 = ty*4;
        float acc[4][4] = {};
        #pragma unroll 8
        for (int d = 0; d < 64; d++) {
            float a[4], bj[4];
            #pragma unroll
            for (int ii = 0; ii < 4; ii++) a[ii]  = Qs[(i0+ii)*65 + d];
            #pragma unroll
            for (int jj = 0; jj < 4; jj++) bj[jj] = Ks[(j0+jj)*65 + d];
            #pragma unroll
            for (int ii = 0; ii < 4; ii++)
                #pragma unroll
                for (int jj = 0; jj < 4; jj++) acc[ii][jj] += a[ii]*bj[jj];
        }
        #pragma unroll
        for (int ii = 0; ii < 4; ii++)
            #pragma unroll
            for (int jj = 0; jj < 4; jj++)
                Ps[(i0+ii)*65 + j0 + jj] = acc[ii][jj] * 0.125f;
    }
    __syncthreads();
    { // causal softmax: warp w handles rows w*8..w*8+7
        int w = t >> 5, lane = t & 31;
        #pragma unroll
        for (int rr = 0; rr < 8; rr++) {
            int i = w*8 + rr;
            float v0 = (lane <= i) ? Ps[i*65 + lane] : -1e30f;
            float v1 = (lane + 32 <= i) ? Ps[i*65 + lane + 32] : -1e30f;
            float m = fmaxf(v0, v1);
            #pragma unroll
            for (int o = 16; o > 0; o >>= 1) m = fmaxf(m, __shfl_xor_sync(0xffffffffu, m, o));
            float e0 = (lane <= i) ? __expf(v0 - m) : 0.f;
            float e1 = (lane + 32 <= i) ? __expf(v1 - m) : 0.f;
            float ssum = e0 + e1;
            #pragma unroll
            for (int o = 16; o > 0; o >>= 1) ssum += __shfl_xor_sync(0xffffffffu, ssum, o);
            float inv = 1.f / ssum;
            Ps[i*65 + lane] = e0 * inv;
            Ps[i*65 + lane + 32] = e1 * inv;
        }
    }
    __syncthreads();
    { // O = P V, convert to bf16 hi/lo, store
        int d0 = tx*4, i0 = ty*4;
        float acc[4][4] = {};
        #pragma unroll 8
        for (int j = 0; j < 64; j++) {
            float a[4], bj[4];
            #pragma unroll
            for (int ii = 0; ii < 4; ii++) a[ii]  = Ps[(i0+ii)*65 + j];
            #pragma unroll
            for (int jj = 0; jj < 4; jj++) bj[jj] = Vs[j*65 + d0 + jj];
            #pragma unroll
            for (int ii = 0; ii < 4; ii++)
                #pragma unroll
                for (int jj = 0; jj < 4; jj++) acc[ii][jj] += a[ii]*bj[jj];
        }
        #pragma unroll
        for (int ii = 0; ii < 4; ii++) {
            size_t base = (rbase + i0 + ii)*256 + h*64 + d0;
            __nv_bfloat16 hi[4], lo[4];
            #pragma unroll
            for (int jj = 0; jj < 4; jj++) {
                float o = acc[ii][jj];
                hi[jj] = __float2bfloat16(o);
                lo[jj] = __float2bfloat16(o - __bfloat162float(hi[jj]));
            }
            __nv_bfloat162 h0; h0.x = hi[0]; h0.y = hi[1];
            __nv_bfloat162 h1; h1.x = hi[2]; h1.y = hi[3];
            __nv_bfloat162 l0; l0.x = lo[0]; l0.y = lo[1];
            __nv_bfloat162 l1; l1.x = lo[2]; l1.y = lo[3];
            *(__nv_bfloat162*)(g_oh + base) = h0;
            *(__nv_bfloat162*)(g_oh + base + 2) = h1;
            *(__nv_bfloat162*)(g_ol + base) = l0;
            *(__nv_bfloat162*)(g_ol + base + 2) = l1;
        }
    }
}

// ------------------------------------------------------------------ K4: per-part FC  out[n,o,p]
__global__ __launch_bounds__(256) void k4_fc(const float* __restrict__ fc, float* __restrict__ out) {
    __shared__ float As[64*68];
    __shared__ float Bs[64*64];
    const int p = blockIdx.x, ot = blockIdx.y;
    const int t = threadIdx.x;
    const int tx = t & 15, ty = t >> 4;
    const int o0 = tx*4, n0 = ty*4;
    float acc[4][4] = {};
    for (int k0 = 0; k0 < 1024; k0 += 64) {
        __syncthreads();
        #pragma unroll
        for (int it = 0; it < 4; it++) {
            int idx = it*256 + t;
            int nn = idx >> 4, k4 = idx & 15;
            *(float4*)(As + nn*68 + k4*4) =
                *(const float4*)(g_clu + ((size_t)p*64 + nn)*1024 + k0 + k4*4);
        }
        #pragma unroll
        for (int it = 0; it < 4; it++) {
            int idx = it*256 + t;
            int kk = idx >> 4, d4 = idx & 15;
            *(float4*)(Bs + kk*64 + d4*4) =
                *(const float4*)(fc + ((size_t)p*1024 + k0 + kk)*256 + ot*64 + d4*4);
        }
        __syncthreads();
        #pragma unroll 4
        for (int kk = 0; kk < 64; kk++) {
            float a[4];
            #pragma unroll
            for (int ii = 0; ii < 4; ii++) a[ii] = As[(n0+ii)*68 + kk];
            float4 bv = *(const float4*)(Bs + kk*64 + o0);
            float bj[4] = {bv.x, bv.y, bv.z, bv.w};
            #pragma unroll
            for (int ii = 0; ii < 4; ii++)
                #pragma unroll
                for (int jj = 0; jj < 4; jj++) acc[ii][jj] += a[ii]*bj[jj];
        }
    }
    #pragma unroll
    for (int ii = 0; ii < 4; ii++)
        #pragma unroll
        for (int jj = 0; jj < 4; jj++)
            out[((size_t)(n0+ii)*256 + ot*64 + o0 + jj)*16 + p] = acc[ii][jj];
}

// ------------------------------------------------------------------ launch
extern "C" void kernel_launch(void* const* d_in, const int* in_sizes, int n_in,
                              void* d_out, int out_size) {
    const float* x     = (const float*)d_in[0];
    const float* proto = (const float*)d_in[1];
    const float* Wq    = (const float*)d_in[2];
    const float* bq    = (const float*)d_in[3];
    const float* Wk    = (const float*)d_in[4];
    const float* bk    = (const float*)d_in[5];
    const float* Wv    = (const float*)d_in[6];
    const float* bv    = (const float*)d_in[7];
    const float* Wo    = (const float*)d_in[8];
    const float* bo    = (const float*)d_in[9];
    const float* fc    = (const float*)d_in[10];
    float* out = (float*)d_out;

    cudaFuncSetAttribute(k0_transpose, cudaFuncAttributeMaxDynamicSharedMemorySize, 69632);
    cudaFuncSetAttribute(k1_assign,    cudaFuncAttributeMaxDynamicSharedMemorySize, 73728);
    cudaFuncSetAttribute(k_gemm,       cudaFuncAttributeMaxDynamicSharedMemorySize, GEMM_SMEM);
    cudaFuncSetAttribute(k_attn,       cudaFuncAttributeMaxDynamicSharedMemorySize, 4*64*65*4);

    k_wprep<<<1024, 256>>>(Wq, Wk, Wv, Wo, bq, bk, bv, bo);
    k0_transpose<<<dim3(16, 64), 256, 69632>>>(x);
    k1_assign<<<NB*PB, 256, (64*257 + 4*257 + 512) * sizeof(float)>>>(proto);
    int wtail = (out_size >= NB*CB*PB + NB*SB) ? 1 : 0;
    k2_mode<<<16, 256>>>(out, wtail);
    k_gemm<<<dim3(512, 6), 256, GEMM_SMEM>>>(0);                 // QKV projections
    k_attn<<<4096, 256, 4*64*65*4>>>();                          // attention core
    k_gemm<<<dim3(512, 2), 256, GEMM_SMEM>>>(1);                 // O@Wo + residual + pooling
    k4_fc<<<dim3(16, 4), 256>>>(fc, out);
}

// round 8
// speedup vs baseline: 2.1416x; 1.0079x over previous
#include <cuda_runtime.h>
#include <cuda_bf16.h>
#include <math.h>
#include <stdint.h>

#define NB 64
#define CB 256
#define SB 64
#define PB 16
#define KCL 4
#define RT (NB*PB*SB)          // 65536 total rows (b = n*16+p, s)

// ------------------------------------------------------------------ globals
__device__ float         g_xb[(size_t)RT*CB];     // X fp32 (b,s,c) exact
__device__ __nv_bfloat16 g_xh[(size_t)RT*CB];     // X hi
__device__ __nv_bfloat16 g_xl[(size_t)RT*CB];     // X lo
__device__ float         g_qkv[(size_t)RT*768];   // Q|K|V fp32
__device__ __nv_bfloat16 g_oh[(size_t)RT*CB];     // attn out hi
__device__ __nv_bfloat16 g_ol[(size_t)RT*CB];     // attn out lo
__device__ __nv_bfloat16 g_wh[1024*CB];           // weights hi: rows 0..767 = Wq|Wk|Wv^T, 768..1023 = Wo^T   [n][k]
__device__ __nv_bfloat16 g_wl[1024*CB];           // lo
__device__ float         g_biasv[1024];           // bq|bk|bv|bo
__device__ float         g_clu[PB*NB*KCL*CB];
__device__ unsigned char g_hidx[PB*NB*SB];

// ------------------------------------------------------------------ helpers
__device__ __forceinline__ uint32_t smem_u32(const void* p) {
    uint32_t a;
    asm("{ .reg .u64 t; cvta.to.shared.u64 t, %1; cvt.u32.u64 %0, t; }" : "=r"(a) : "l"(p));
    return a;
}
__device__ __forceinline__ void ldsm4(uint32_t a, uint32_t& r0, uint32_t& r1, uint32_t& r2, uint32_t& r3) {
    asm volatile("ldmatrix.sync.aligned.m8n8.x4.shared.b16 {%0,%1,%2,%3}, [%4];"
        : "=r"(r0), "=r"(r1), "=r"(r2), "=r"(r3) : "r"(a));
}
__device__ __forceinline__ void mma16816(float* d, const uint32_t* a, uint32_t b0, uint32_t b1) {
    asm volatile("mma.sync.aligned.m16n8k16.row.col.f32.bf16.bf16.f32 "
        "{%0,%1,%2,%3}, {%4,%5,%6,%7}, {%8,%9}, {%0,%1,%2,%3};"
        : "+f"(d[0]), "+f"(d[1]), "+f"(d[2]), "+f"(d[3])
        : "r"(a[0]), "r"(a[1]), "r"(a[2]), "r"(a[3]), "r"(b0), "r"(b1));
}
__device__ __forceinline__ void cp16(uint32_t sa, const void* ga) {
    asm volatile("cp.async.cg.shared.global [%0], [%1], 16;" :: "r"(sa), "l"(ga));
}

// ------------------------------------------------------------------ K0: transpose + bf16 split
__global__ __launch_bounds__(256) void k0_transpose(const float* __restrict__ x) {
    extern __shared__ float tile[];          // [(s*16+p)][17]
    const int cchunk = blockIdx.x, n = blockIdx.y;
    const int t = threadIdx.x;
    const int c0 = cchunk * 16;
    #pragma unroll
    for (int it = 0; it < 16; it++) {
        int idx = it * 256 + t;
        int ci = idx >> 8;
        int rem = idx & 255;
        int s = rem >> 2;
        int p4 = rem & 3;
        const float4 v = *(const float4*)(x + (((size_t)n*CB + c0 + ci)*SB + s)*PB + p4*4);
        int base = (s*16 + p4*4)*17 + ci;
        tile[base] = v.x; tile[base+17] = v.y; tile[base+34] = v.z; tile[base+51] = v.w;
    }
    __syncthreads();
    #pragma unroll
    for (int it = 0; it < 8; it++) {
        int idx = it * 256 + t;              // 2048: (s,p,vec8)
        int vec = idx & 1;
        int pr = idx >> 1;
        int s = pr >> 4, p = pr & 15;
        int base = (s*16 + p)*17 + vec*8;
        __align__(16) float f[8];
        __align__(16) __nv_bfloat16 hi[8];
        __align__(16) __nv_bfloat16 lo[8];
        #pragma unroll
        for (int u = 0; u < 8; u++) {
            float v = tile[base + u];
            f[u] = v;
            hi[u] = __float2bfloat16(v);
            lo[u] = __float2bfloat16(v - __bfloat162float(hi[u]));
        }
        size_t off = (((size_t)n*16 + p)*64 + s)*256 + c0 + vec*8;
        *(uint4*)(g_xb + off)     = *(uint4*)f;
        *(uint4*)(g_xb + off + 4) = *(uint4*)(f + 4);
        *(uint4*)(g_xh + off) = *(uint4*)hi;
        *(uint4*)(g_xl + off) = *(uint4*)lo;
    }
}

// ------------------------------------------------------------------ K_wprep
__global__ __launch_bounds__(256) void k_wprep(
    const float* __restrict__ Wq, const float* __restrict__ Wk,
    const float* __restrict__ Wv, const float* __restrict__ Wo,
    const float* __restrict__ bq, const float* __restrict__ bk,
    const float* __restrict__ bv, const float* __restrict__ bo)
{
    int nrow = blockIdx.x;     // 0..1023
    int k = threadIdx.x;       // 0..255
    float w;
    if (nrow < 256)      w = Wq[k*256 + nrow];
    else if (nrow < 512) w = Wk[k*256 + (nrow-256)];
    else if (nrow < 768) w = Wv[k*256 + (nrow-512)];
    else                 w = Wo[k*256 + (nrow-768)];
    __nv_bfloat16 h = __float2bfloat16(w);
    __nv_bfloat16 l = __float2bfloat16(w - __bfloat162float(h));
    g_wh[nrow*256 + k] = h;
    g_wl[nrow*256 + k] = l;
    if (k == 0) {
        float b;
        if (nrow < 256)      b = bq[nrow];
        else if (nrow < 512) b = bk[nrow-256];
        else if (nrow < 768) b = bv[nrow-512];
        else                 b = bo[nrow-768];
        g_biasv[nrow] = b;
    }
}

// ------------------------------------------------------------------ K1: instnorm + argmax assignment
__global__ __launch_bounds__(256) void k1_assign(const float* __restrict__ proto) {
    extern __shared__ float sm1[];
    float* xs = sm1;               // 64*257
    float* pn = xs + 64*257;       // 4*257
    float* mu = pn + 4*257;        // 256
    float* rv = mu + 256;          // 256
    __shared__ float nrm[4];
    const int b = blockIdx.x;
    const int n = b >> 4, p = b & 15;
    const int t = threadIdx.x;

    #pragma unroll
    for (int it = 0; it < 4; it++) {
        int i = it*256 + t; int k = i >> 8; int c = i & 255;
        pn[k*257 + c] = proto[((size_t)p*4 + k)*256 + c];
    }
    __syncthreads();
    if (t < 128) {
        int k = t >> 5, lane = t & 31; float s = 0.f;
        #pragma unroll
        for (int j = 0; j < 8; j++) { float v = pn[k*257 + lane + j*32]; s += v*v; }
        #pragma unroll
        for (int o = 16; o > 0; o >>= 1) s += __shfl_down_sync(0xffffffffu, s, o);
        if (lane == 0) nrm[k] = rsqrtf(s);
    }
    __syncthreads();
    #pragma unroll
    for (int it = 0; it < 4; it++) {
        int i = it*256 + t; int k = i >> 8; int c = i & 255;
        pn[k*257 + c] *= nrm[k];
    }
    const float* xg = g_xb + (size_t)b * SB * CB;
    for (int it = 0; it < 64; it++) {
        int i = it*256 + t; int s = i >> 8; int c = i & 255;
        xs[s*257 + c] = xg[i];
    }
    __syncthreads();
    {
        int c = t; float sum = 0.f;
        #pragma unroll 8
        for (int s = 0; s < 64; s++) sum += xs[s*257 + c];
        float m = sum * (1.f/64.f);
        float sq = 0.f;
        #pragma unroll 8
        for (int s = 0; s < 64; s++) { float d = xs[s*257 + c] - m; sq += d*d; }
        mu[c] = m;
        rv[c] = rsqrtf(sq * (1.f/64.f) + 1e-5f);
    }
    __syncthreads();
    {
        int s = t >> 2, k = t & 3;
        float acc = 0.f;
        #pragma unroll 8
        for (int c = 0; c < 256; c++)
            acc += (xs[s*257 + c] - mu[c]) * rv[c] * pn[k*257 + c];
        float a1 = __shfl_down_sync(0xffffffffu, acc, 1);
        float a2 = __shfl_down_sync(0xffffffffu, acc, 2);
        float a3 = __shfl_down_sync(0xffffffffu, acc, 3);
        if (k == 0) {
            int bi = 0; float bv = acc;
            if (a1 > bv) { bv = a1; bi = 1; }
            if (a2 > bv) { bv = a2; bi = 2; }
            if (a3 > bv) { bv = a3; bi = 3; }
            g_hidx[((size_t)p*64 + n)*64 + s] = (unsigned char)bi;
        }
    }
}

// ------------------------------------------------------------------ K2: mode over parts
__global__ void k2_mode(float* __restrict__ out, int doWrite) {
    int id = blockIdx.x * 256 + threadIdx.x;
    int n = id >> 6, s = id & 63;
    int cnt[4] = {0,0,0,0};
    #pragma unroll
    for (int p = 0; p < 16; p++) cnt[g_hidx[((size_t)p*64 + n)*64 + s]]++;
    int bi = 0, bv = cnt[0];
    if (cnt[1] > bv) { bv = cnt[1]; bi = 1; }
    if (cnt[2] > bv) { bv = cnt[2]; bi = 2; }
    if (cnt[3] > bv) { bv = cnt[3]; bi = 3; }
    if (doWrite) out[NB*CB*PB + id] = (float)bi;
}

// ------------------------------------------------------------------ k_gemm: A-resident warp-MMA
// A tile (128 x 256, hi+lo) stays in smem for the whole kernel; loop over
// N-blocks streaming only B (L2-hot weights) through a double buffer.
#define KC 64
#define LDA 264                 // bf16/row: 528B, conflict-free ldmatrix
#define A_TILE_B (128*LDA*2)    // 67584 per (hi|lo)
#define LDT 72                  // B tile row pitch
#define BTILE (128*LDT*2)       // 18432
#define BSTAGE (2*BTILE)        // hi+lo = 36864
#define SM_B0 (2*A_TILE_B)      // 135168
#define GEMM_SMEM (2*A_TILE_B + 2*BSTAGE)   // 208896
#define YLD 132

__device__ __forceinline__ void load_A_ca(const __nv_bfloat16* __restrict__ src,
        size_t row0, uint32_t dst_s, int t) {
    #pragma unroll
    for (int it = 0; it < 16; it++) {
        int v = it*256 + t;                  // 4096 vecs: 128 rows x 32
        int r = v >> 5, kv = (v & 31) << 3;
        cp16(dst_s + (uint32_t)(r*LDA + kv)*2, src + (row0 + r)*256 + kv);
    }
}
__device__ __forceinline__ void load_B_ca(const __nv_bfloat16* __restrict__ srcH,
        const __nv_bfloat16* __restrict__ srcL,
        int brow0, int k0, uint32_t dst_s, int t) {
    #pragma unroll
    for (int it = 0; it < 4; it++) {
        int v = it*256 + t;                  // 1024 vecs: 128 rows x 8
        int r = v >> 3, kv = (v & 7) << 3;
        cp16(dst_s + (uint32_t)(r*LDT + kv)*2, srcH + (size_t)(brow0 + r)*256 + k0 + kv);
        cp16(dst_s + BTILE + (uint32_t)(r*LDT + kv)*2, srcL + (size_t)(brow0 + r)*256 + k0 + kv);
    }
}

__global__ __launch_bounds__(256, 1) void k_gemm(int mode) {
    extern __shared__ char sm[];
    const uint32_t sb = smem_u32(sm);
    const int t = threadIdx.x;
    const int w = t >> 5, lane = t & 31;
    const int m0 = blockIdx.x * 128;
    const int wy = w >> 1, wx = w & 1;
    const int m_base = wy*32, n_base = wx*64;
    __shared__ unsigned char sidx[128];

    if (mode == 1 && t < 128) {
        int b = (m0 >> 6) + (t >> 6);
        sidx[t] = g_hidx[((size_t)(b & 15)*64 + (b >> 4))*64 + (t & 63)];
    }

    const __nv_bfloat16* Ah_src = (mode == 0) ? g_xh : g_oh;
    const __nv_bfloat16* Al_src = (mode == 0) ? g_xl : g_ol;
    const int NBLK = (mode == 0) ? 6 : 2;
    const int bbase = (mode == 0) ? 0 : 768;

    const int li = lane >> 3, lr = lane & 7;
    const int a_row = (li & 1)*8 + lr, a_kof = (li >> 1)*8;
    const int b_row = (li >> 1)*8 + lr, b_kof = (li & 1)*8;

    // prefetch A (resident) + B(nb=0, chunk 0)
    load_A_ca(Ah_src, (size_t)m0, sb, t);
    load_A_ca(Al_src, (size_t)m0, sb + A_TILE_B, t);
    load_B_ca(g_wh, g_wl, bbase, 0, sb + SM_B0, t);
    asm volatile("cp.async.commit_group;" ::: "memory");

    float* Ys = (float*)(sm + SM_B0);

    for (int nb = 0; nb < NBLK; nb++) {
        const int brow0 = bbase + nb*128;
        if (nb > 0) {
            load_B_ca(g_wh, g_wl, brow0, 0, sb + SM_B0, t);
            asm volatile("cp.async.commit_group;" ::: "memory");
        }
        float acc[2][8][4];
        #pragma unroll
        for (int i = 0; i < 2; i++)
            #pragma unroll
            for (int j = 0; j < 8; j++)
                #pragma unroll
                for (int q = 0; q < 4; q++) acc[i][j][q] = 0.f;

        #pragma unroll
        for (int c = 0; c < 4; c++) {
            if (c < 3) {
                load_B_ca(g_wh, g_wl, brow0, (c + 1)*KC, sb + SM_B0 + ((c + 1) & 1)*BSTAGE, t);
                asm volatile("cp.async.commit_group;" ::: "memory");
                asm volatile("cp.async.wait_group 1;" ::: "memory");
            } else {
                asm volatile("cp.async.wait_group 0;" ::: "memory");
            }
            __syncthreads();
            const uint32_t stB = sb + SM_B0 + (c & 1)*BSTAGE;
            #pragma unroll
            for (int ks = 0; ks < 4; ks++) {
                const int kk = c*KC + ks*16;
                uint32_t ah[2][4], al[2][4];
                #pragma unroll
                for (int mf = 0; mf < 2; mf++) {
                    uint32_t off = (uint32_t)((m_base + mf*16 + a_row)*LDA + kk + a_kof)*2;
                    ldsm4(sb + off, ah[mf][0], ah[mf][1], ah[mf][2], ah[mf][3]);
                    ldsm4(sb + A_TILE_B + off, al[mf][0], al[mf][1], al[mf][2], al[mf][3]);
                }
                #pragma unroll
                for (int nbf = 0; nbf < 4; nbf++) {
                    uint32_t off = (uint32_t)((n_base + nbf*16 + b_row)*LDT + ks*16 + b_kof)*2;
                    uint32_t bh0, bh1, bh2, bh3, bl0, bl1, bl2, bl3;
                    ldsm4(stB + off, bh0, bh1, bh2, bh3);
                    ldsm4(stB + BTILE + off, bl0, bl1, bl2, bl3);
                    #pragma unroll
                    for (int mf = 0; mf < 2; mf++) {
                        mma16816(acc[mf][nbf*2],     ah[mf], bh0, bh1);
                        mma16816(acc[mf][nbf*2 + 1], ah[mf], bh2, bh3);
                        mma16816(acc[mf][nbf*2],     ah[mf], bl0, bl1);
                        mma16816(acc[mf][nbf*2 + 1], ah[mf], bl2, bl3);
                        mma16816(acc[mf][nbf*2],     al[mf], bh0, bh1);
                        mma16816(acc[mf][nbf*2 + 1], al[mf], bh2, bh3);
                    }
                }
            }
            __syncthreads();
        }

        // epilogue: stage through Ys (retired B region)
        {
            const int mr = lane >> 2, nc = (lane & 3)*2;
            #pragma unroll
            for (int mf = 0; mf < 2; mf++)
                #pragma unroll
                for (int nf = 0; nf < 8; nf++) {
                    int m = m_base + mf*16 + mr;
                    int n = n_base + nf*8 + nc;
                    float b0 = g_biasv[brow0 + n], b1 = g_biasv[brow0 + n + 1];
                    Ys[m*YLD + n]           = acc[mf][nf][0] + b0;
                    Ys[m*YLD + n + 1]       = acc[mf][nf][1] + b1;
                    Ys[(m + 8)*YLD + n]     = acc[mf][nf][2] + b0;
                    Ys[(m + 8)*YLD + n + 1] = acc[mf][nf][3] + b1;
                }
        }
        __syncthreads();

        if (mode == 0) {
            for (int v = t; v < 4096; v += 256) {       // 128 rows x 32 float4
                int r = v >> 5, c4 = (v & 31) << 2;
                float4 val = make_float4(Ys[r*YLD + c4], Ys[r*YLD + c4 + 1],
                                         Ys[r*YLD + c4 + 2], Ys[r*YLD + c4 + 3]);
                *(float4*)(g_qkv + (size_t)(m0 + r)*768 + nb*128 + c4) = val;
            }
        } else {
            for (int v = t; v < 4096; v += 256) {
                int r = v >> 5, c4 = (v & 31) << 2;
                float4 rx = *(const float4*)(g_xb + (size_t)(m0 + r)*256 + nb*128 + c4);
                Ys[r*YLD + c4]     += rx.x;
                Ys[r*YLD + c4 + 1] += rx.y;
                Ys[r*YLD + c4 + 2] += rx.z;
                Ys[r*YLD + c4 + 3] += rx.w;
            }
            __syncthreads();
            for (int id = t; id < 1024; id += 256) {
                int bl = id >> 9, j = (id >> 7) & 3, c = id & 127;
                float m = -1e30f;
                #pragma unroll 8
                for (int s = 0; s < 64; s++) {
                    float v = (sidx[bl*64 + s] == j) ? Ys[(bl*64 + s)*YLD + c] : 0.f;
                    m = fmaxf(m, v);
                }
                int b = (m0 >> 6) + bl;
                int n = b >> 4, p = b & 15;
                g_clu[((size_t)p*64 + n)*1024 + j*256 + nb*128 + c] = m;
            }
        }
        __syncthreads();        // Ys readers done before next nb's B prefetch
    }
}

// ------------------------------------------------------------------ K_attn: SIMT attention core per (b, h)
__global__ __launch_bounds__(256) void k_attn() {
    extern __shared__ float sma[];
    float* Qs = sma;
    float* Ks = sma + 64*65;
    float* Vs = sma + 2*64*65;
    float* Ps = sma + 3*64*65;
    const int bid = blockIdx.x;
    const int b = bid >> 2, h = bid & 3;
    const int t = threadIdx.x;
    const size_t rbase = (size_t)b * 64;

    #pragma unroll
    for (int it = 0; it < 4; it++) {
        int idx = it*256 + t;                // 1024 = 64 s x 16 d4
        int s = idx >> 4, d4 = (idx & 15) << 2;
        const float* src = g_qkv + (rbase + s)*768 + h*64 + d4;
        float4 q = *(const float4*)src;
        float4 k = *(const float4*)(src + 256);
        float4 v = *(const float4*)(src + 512);
        Qs[s*65 + d4] = q.x; Qs[s*65 + d4 + 1] = q.y; Qs[s*65 + d4 + 2] = q.z; Qs[s*65 + d4 + 3] = q.w;
        Ks[s*65 + d4] = k.x; Ks[s*65 + d4 + 1] = k.y; Ks[s*65 + d4 + 2] = k.z; Ks[s*65 + d4 + 3] = k.w;
        Vs[s*65 + d4] = v.x; Vs[s*65 + d4 + 1] = v.y; Vs[s*65 + d4 + 2] = v.z; Vs[s*65 + d4 + 3] = v.w;
    }
    __syncthreads();
    const int tx = t & 15, ty = t >> 4;
    { // scores = Q K^T / 8
        int j0 = tx*4, i0 = ty*4;
        float acc[4][4] = {};
        #pragma unroll 8
        for (int d = 0; d < 64; d++) {
            float a[4], bj[4];
            #pragma unroll
            for (int ii = 0; ii < 4; ii++) a[ii]  = Qs[(i0+ii)*65 + d];
            #pragma unroll
            for (int jj = 0; jj < 4; jj++) bj[jj] = Ks[(j0+jj)*65 + d];
            #pragma unroll
            for (int ii = 0; ii < 4; ii++)
                #pragma unroll
                for (int jj = 0; jj < 4; jj++) acc[ii][jj] += a[ii]*bj[jj];
        }
        #pragma unroll
        for (int ii = 0; ii < 4; ii++)
            #pragma unroll
            for (int jj = 0; jj < 4; jj++)
                Ps[(i0+ii)*65 + j0 + jj] = acc[ii][jj] * 0.125f;
    }
    __syncthreads();
    { // causal softmax: warp w handles rows w*8..w*8+7
        int w = t >> 5, lane = t & 31;
        #pragma unroll
        for (int rr = 0; rr < 8; rr++) {
            int i = w*8 + rr;
            float v0 = (lane <= i) ? Ps[i*65 + lane] : -1e30f;
            float v1 = (lane + 32 <= i) ? Ps[i*65 + lane + 32] : -1e30f;
            float m = fmaxf(v0, v1);
            #pragma unroll
            for (int o = 16; o > 0; o >>= 1) m = fmaxf(m, __shfl_xor_sync(0xffffffffu, m, o));
            float e0 = (lane <= i) ? __expf(v0 - m) : 0.f;
            float e1 = (lane + 32 <= i) ? __expf(v1 - m) : 0.f;
            float ssum = e0 + e1;
            #pragma unroll
            for (int o = 16; o > 0; o >>= 1) ssum += __shfl_xor_sync(0xffffffffu, ssum, o);
            float inv = 1.f / ssum;
            Ps[i*65 + lane] = e0 * inv;
            Ps[i*65 + lane + 32] = e1 * inv;
        }
    }
    __syncthreads();
    { // O = P V, convert to bf16 hi/lo, store
        int d0 = tx*4, i0 = ty*4;
        float acc[4][4] = {};
        #pragma unroll 8
        for (int j = 0; j < 64; j++) {
            float a[4], bj[4];
            #pragma unroll
            for (int ii = 0; ii < 4; ii++) a[ii]  = Ps[(i0+ii)*65 + j];
            #pragma unroll
            for (int jj = 0; jj < 4; jj++) bj[jj] = Vs[j*65 + d0 + jj];
            #pragma unroll
            for (int ii = 0; ii < 4; ii++)
                #pragma unroll
                for (int jj = 0; jj < 4; jj++) acc[ii][jj] += a[ii]*bj[jj];
        }
        #pragma unroll
        for (int ii = 0; ii < 4; ii++) {
            size_t base = (rbase + i0 + ii)*256 + h*64 + d0;
            __nv_bfloat16 hi[4], lo[4];
            #pragma unroll
            for (int jj = 0; jj < 4; jj++) {
                float o = acc[ii][jj];
                hi[jj] = __float2bfloat16(o);
                lo[jj] = __float2bfloat16(o - __bfloat162float(hi[jj]));
            }
            __nv_bfloat162 h0; h0.x = hi[0]; h0.y = hi[1];
            __nv_bfloat162 h1; h1.x = hi[2]; h1.y = hi[3];
            __nv_bfloat162 l0; l0.x = lo[0]; l0.y = lo[1];
            __nv_bfloat162 l1; l1.x = lo[2]; l1.y = lo[3];
            *(__nv_bfloat162*)(g_oh + base) = h0;
            *(__nv_bfloat162*)(g_oh + base + 2) = h1;
            *(__nv_bfloat162*)(g_ol + base) = l0;
            *(__nv_bfloat162*)(g_ol + base + 2) = l1;
        }
    }
}

// ------------------------------------------------------------------ K4: per-part FC  out[n,o,p]
__global__ __launch_bounds__(256) void k4_fc(const float* __restrict__ fc, float* __restrict__ out) {
    __shared__ float As[64*68];
    __shared__ float Bs[64*64];
    const int p = blockIdx.x, ot = blockIdx.y;
    const int t = threadIdx.x;
    const int tx = t & 15, ty = t >> 4;
    const int o0 = tx*4, n0 = ty*4;
    float acc[4][4] = {};
    for (int k0 = 0; k0 < 1024; k0 += 64) {
        __syncthreads();
        #pragma unroll
        for (int it = 0; it < 4; it++) {
            int idx = it*256 + t;
            int nn = idx >> 4, k4 = idx & 15;
            *(float4*)(As + nn*68 + k4*4) =
                *(const float4*)(g_clu + ((size_t)p*64 + nn)*1024 + k0 + k4*4);
        }
        #pragma unroll
        for (int it = 0; it < 4; it++) {
            int idx = it*256 + t;
            int kk = idx >> 4, d4 = idx & 15;
            *(float4*)(Bs + kk*64 + d4*4) =
                *(const float4*)(fc + ((size_t)p*1024 + k0 + kk)*256 + ot*64 + d4*4);
        }
        __syncthreads();
        #pragma unroll 4
        for (int kk = 0; kk < 64; kk++) {
            float a[4];
            #pragma unroll
            for (int ii = 0; ii < 4; ii++) a[ii] = As[(n0+ii)*68 + kk];
            float4 bv = *(const float4*)(Bs + kk*64 + o0);
            float bj[4] = {bv.x, bv.y, bv.z, bv.w};
            #pragma unroll
            for (int ii = 0; ii < 4; ii++)
                #pragma unroll
                for (int jj = 0; jj < 4; jj++) acc[ii][jj] += a[ii]*bj[jj];
        }
    }
    #pragma unroll
    for (int ii = 0; ii < 4; ii++)
        #pragma unroll
        for (int jj = 0; jj < 4; jj++)
            out[((size_t)(n0+ii)*256 + ot*64 + o0 + jj)*16 + p] = acc[ii][jj];
}

// ------------------------------------------------------------------ launch
extern "C" void kernel_launch(void* const* d_in, const int* in_sizes, int n_in,
                              void* d_out, int out_size) {
    const float* x     = (const float*)d_in[0];
    const float* proto = (const float*)d_in[1];
    const float* Wq    = (const float*)d_in[2];
    const float* bq    = (const float*)d_in[3];
    const float* Wk    = (const float*)d_in[4];
    const float* bk    = (const float*)d_in[5];
    const float* Wv    = (const float*)d_in[6];
    const float* bv    = (const float*)d_in[7];
    const float* Wo    = (const float*)d_in[8];
    const float* bo    = (const float*)d_in[9];
    const float* fc    = (const float*)d_in[10];
    float* out = (float*)d_out;

    cudaFuncSetAttribute(k0_transpose, cudaFuncAttributeMaxDynamicSharedMemorySize, 69632);
    cudaFuncSetAttribute(k1_assign,    cudaFuncAttributeMaxDynamicSharedMemorySize, 73728);
    cudaFuncSetAttribute(k_gemm,       cudaFuncAttributeMaxDynamicSharedMemorySize, GEMM_SMEM);
    cudaFuncSetAttribute(k_attn,       cudaFuncAttributeMaxDynamicSharedMemorySize, 4*64*65*4);

    k_wprep<<<1024, 256>>>(Wq, Wk, Wv, Wo, bq, bk, bv, bo);
    k0_transpose<<<dim3(16, 64), 256, 69632>>>(x);
    k1_assign<<<NB*PB, 256, (64*257 + 4*257 + 512) * sizeof(float)>>>(proto);
    int wtail = (out_size >= NB*CB*PB + NB*SB) ? 1 : 0;
    k2_mode<<<16, 256>>>(out, wtail);
    k_gemm<<<512, 256, GEMM_SMEM>>>(0);                 // QKV projections (A-resident)
    k_attn<<<4096, 256, 4*64*65*4>>>();                 // attention core
    k_gemm<<<512, 256, GEMM_SMEM>>>(1);                 // O@Wo + residual + pooling
    k4_fc<<<dim3(16, 4), 256>>>(fc, out);
}

// round 9
// speedup vs baseline: 2.4517x; 1.1448x over previous
#include <cuda_runtime.h>
#include <cuda_bf16.h>
#include <math.h>
#include <stdint.h>

#define NB 64
#define CB 256
#define SB 64
#define PB 16
#define KCL 4
#define RT (NB*PB*SB)          // 65536 total rows (b = n*16+p, s)

// ------------------------------------------------------------------ globals
__device__ float         g_xb[(size_t)RT*CB];     // X fp32 (b,s,c) exact
__device__ __nv_bfloat16 g_xh[(size_t)RT*CB];     // X hi
__device__ __nv_bfloat16 g_xl[(size_t)RT*CB];     // X lo
__device__ float         g_qkv[(size_t)RT*768];   // Q|K|V fp32
__device__ __nv_bfloat16 g_oh[(size_t)RT*CB];     // attn out hi
__device__ __nv_bfloat16 g_ol[(size_t)RT*CB];     // attn out lo
__device__ __nv_bfloat16 g_wh[1024*CB];           // weights hi: rows 0..767 = Wq|Wk|Wv^T, 768..1023 = Wo^T   [n][k]
__device__ __nv_bfloat16 g_wl[1024*CB];           // lo
__device__ float         g_biasv[1024];           // bq|bk|bv|bo
__device__ float         g_clu[PB*NB*KCL*CB];
__device__ unsigned char g_hidx[PB*NB*SB];

// ------------------------------------------------------------------ helpers
__device__ __forceinline__ uint32_t smem_u32(const void* p) {
    uint32_t a;
    asm("{ .reg .u64 t; cvta.to.shared.u64 t, %1; cvt.u32.u64 %0, t; }" : "=r"(a) : "l"(p));
    return a;
}
__device__ __forceinline__ void ldsm4(uint32_t a, uint32_t& r0, uint32_t& r1, uint32_t& r2, uint32_t& r3) {
    asm volatile("ldmatrix.sync.aligned.m8n8.x4.shared.b16 {%0,%1,%2,%3}, [%4];"
        : "=r"(r0), "=r"(r1), "=r"(r2), "=r"(r3) : "r"(a));
}
__device__ __forceinline__ void ldsm4t(uint32_t a, uint32_t& r0, uint32_t& r1, uint32_t& r2, uint32_t& r3) {
    asm volatile("ldmatrix.sync.aligned.m8n8.x4.trans.shared.b16 {%0,%1,%2,%3}, [%4];"
        : "=r"(r0), "=r"(r1), "=r"(r2), "=r"(r3) : "r"(a));
}
__device__ __forceinline__ void mma16816(float* d, const uint32_t* a, uint32_t b0, uint32_t b1) {
    asm volatile("mma.sync.aligned.m16n8k16.row.col.f32.bf16.bf16.f32 "
        "{%0,%1,%2,%3}, {%4,%5,%6,%7}, {%8,%9}, {%0,%1,%2,%3};"
        : "+f"(d[0]), "+f"(d[1]), "+f"(d[2]), "+f"(d[3])
        : "r"(a[0]), "r"(a[1]), "r"(a[2]), "r"(a[3]), "r"(b0), "r"(b1));
}
__device__ __forceinline__ void cp16(uint32_t sa, const void* ga) {
    asm volatile("cp.async.cg.shared.global [%0], [%1], 16;" :: "r"(sa), "l"(ga));
}
__device__ __forceinline__ void split2(float x, float y, uint32_t& hi, uint32_t& lo) {
    __nv_bfloat16 hx = __float2bfloat16(x), hy = __float2bfloat16(y);
    __nv_bfloat16 lx = __float2bfloat16(x - __bfloat162float(hx));
    __nv_bfloat16 ly = __float2bfloat16(y - __bfloat162float(hy));
    __nv_bfloat162 H; H.x = hx; H.y = hy;
    __nv_bfloat162 L; L.x = lx; L.y = ly;
    hi = *(uint32_t*)&H; lo = *(uint32_t*)&L;
}

// ------------------------------------------------------------------ K0: transpose + bf16 split
__global__ __launch_bounds__(256) void k0_transpose(const float* __restrict__ x) {
    extern __shared__ float tile[];          // [(s*16+p)][17]
    const int cchunk = blockIdx.x, n = blockIdx.y;
    const int t = threadIdx.x;
    const int c0 = cchunk * 16;
    #pragma unroll
    for (int it = 0; it < 16; it++) {
        int idx = it * 256 + t;
        int ci = idx >> 8;
        int rem = idx & 255;
        int s = rem >> 2;
        int p4 = rem & 3;
        const float4 v = *(const float4*)(x + (((size_t)n*CB + c0 + ci)*SB + s)*PB + p4*4);
        int base = (s*16 + p4*4)*17 + ci;
        tile[base] = v.x; tile[base+17] = v.y; tile[base+34] = v.z; tile[base+51] = v.w;
    }
    __syncthreads();
    #pragma unroll
    for (int it = 0; it < 8; it++) {
        int idx = it * 256 + t;              // 2048: (s,p,vec8)
        int vec = idx & 1;
        int pr = idx >> 1;
        int s = pr >> 4, p = pr & 15;
        int base = (s*16 + p)*17 + vec*8;
        __align__(16) float f[8];
        __align__(16) __nv_bfloat16 hi[8];
        __align__(16) __nv_bfloat16 lo[8];
        #pragma unroll
        for (int u = 0; u < 8; u++) {
            float v = tile[base + u];
            f[u] = v;
            hi[u] = __float2bfloat16(v);
            lo[u] = __float2bfloat16(v - __bfloat162float(hi[u]));
        }
        size_t off = (((size_t)n*16 + p)*64 + s)*256 + c0 + vec*8;
        *(uint4*)(g_xb + off)     = *(uint4*)f;
        *(uint4*)(g_xb + off + 4) = *(uint4*)(f + 4);
        *(uint4*)(g_xh + off) = *(uint4*)hi;
        *(uint4*)(g_xl + off) = *(uint4*)lo;
    }
}

// ------------------------------------------------------------------ K_wprep: smem-tiled transpose, coalesced both sides
__global__ __launch_bounds__(256) void k_wprep(
    const float* __restrict__ Wq, const float* __restrict__ Wk,
    const float* __restrict__ Wv, const float* __restrict__ Wo,
    const float* __restrict__ bq, const float* __restrict__ bk,
    const float* __restrict__ bv, const float* __restrict__ bo)
{
    __shared__ float tile[64*68];
    const int bx = blockIdx.x;               // 64 blocks
    const int mat = bx >> 4, tl = bx & 15;
    const int kt = (tl >> 2) << 6, nt = (tl & 3) << 6;
    const float* W = (mat == 0) ? Wq : (mat == 1) ? Wk : (mat == 2) ? Wv : Wo;
    const int t = threadIdx.x;
    #pragma unroll
    for (int it = 0; it < 4; it++) {
        int v = it*256 + t;                  // 1024: 64 k-rows x 16 float4
        int r = v >> 4, c4 = (v & 15) << 2;
        float4 val = *(const float4*)(W + (size_t)(kt + r)*256 + nt + c4);
        tile[(c4+0)*68 + r] = val.x;
        tile[(c4+1)*68 + r] = val.y;
        tile[(c4+2)*68 + r] = val.z;
        tile[(c4+3)*68 + r] = val.w;
    }
    __syncthreads();
    #pragma unroll
    for (int it = 0; it < 2; it++) {
        int v = it*256 + t;                  // 512: 64 n-rows x 8 vec8
        int n = v >> 3, k8 = (v & 7) << 3;
        __align__(16) __nv_bfloat16 hi[8];
        __align__(16) __nv_bfloat16 lo[8];
        #pragma unroll
        for (int u = 0; u < 8; u++) {
            float w = tile[n*68 + k8 + u];
            hi[u] = __float2bfloat16(w);
            lo[u] = __float2bfloat16(w - __bfloat162float(hi[u]));
        }
        size_t off = (size_t)(mat*256 + nt + n)*256 + kt + k8;
        *(uint4*)(g_wh + off) = *(uint4*)hi;
        *(uint4*)(g_wl + off) = *(uint4*)lo;
    }
    if (tl == 0) {
        const float* bias = (mat == 0) ? bq : (mat == 1) ? bk : (mat == 2) ? bv : bo;
        g_biasv[mat*256 + t] = bias[t];
    }
}

// ------------------------------------------------------------------ K1: instnorm + argmax assignment
__global__ __launch_bounds__(256) void k1_assign(const float* __restrict__ proto) {
    extern __shared__ float sm1[];
    float* xs = sm1;               // 64*257
    float* pn = xs + 64*257;       // 4*257
    float* mu = pn + 4*257;        // 256
    float* rv = mu + 256;          // 256
    __shared__ float nrm[4];
    const int b = blockIdx.x;
    const int n = b >> 4, p = b & 15;
    const int t = threadIdx.x;

    #pragma unroll
    for (int it = 0; it < 4; it++) {
        int i = it*256 + t; int k = i >> 8; int c = i & 255;
        pn[k*257 + c] = proto[((size_t)p*4 + k)*256 + c];
    }
    __syncthreads();
    if (t < 128) {
        int k = t >> 5, lane = t & 31; float s = 0.f;
        #pragma unroll
        for (int j = 0; j < 8; j++) { float v = pn[k*257 + lane + j*32]; s += v*v; }
        #pragma unroll
        for (int o = 16; o > 0; o >>= 1) s += __shfl_down_sync(0xffffffffu, s, o);
        if (lane == 0) nrm[k] = rsqrtf(s);
    }
    __syncthreads();
    #pragma unroll
    for (int it = 0; it < 4; it++) {
        int i = it*256 + t; int k = i >> 8; int c = i & 255;
        pn[k*257 + c] *= nrm[k];
    }
    const float* xg = g_xb + (size_t)b * SB * CB;
    for (int it = 0; it < 64; it++) {
        int i = it*256 + t; int s = i >> 8; int c = i & 255;
        xs[s*257 + c] = xg[i];
    }
    __syncthreads();
    {
        int c = t; float sum = 0.f;
        #pragma unroll 8
        for (int s = 0; s < 64; s++) sum += xs[s*257 + c];
        float m = sum * (1.f/64.f);
        float sq = 0.f;
        #pragma unroll 8
        for (int s = 0; s < 64; s++) { float d = xs[s*257 + c] - m; sq += d*d; }
        mu[c] = m;
        rv[c] = rsqrtf(sq * (1.f/64.f) + 1e-5f);
    }
    __syncthreads();
    {
        int s = t >> 2, k = t & 3;
        float acc = 0.f;
        #pragma unroll 8
        for (int c = 0; c < 256; c++)
            acc += (xs[s*257 + c] - mu[c]) * rv[c] * pn[k*257 + c];
        float a1 = __shfl_down_sync(0xffffffffu, acc, 1);
        float a2 = __shfl_down_sync(0xffffffffu, acc, 2);
        float a3 = __shfl_down_sync(0xffffffffu, acc, 3);
        if (k == 0) {
            int bi = 0; float bv = acc;
            if (a1 > bv) { bv = a1; bi = 1; }
            if (a2 > bv) { bv = a2; bi = 2; }
            if (a3 > bv) { bv = a3; bi = 3; }
            g_hidx[((size_t)p*64 + n)*64 + s] = (unsigned char)bi;
        }
    }
}

// ------------------------------------------------------------------ K2: mode over parts
__global__ void k2_mode(float* __restrict__ out, int doWrite) {
    int id = blockIdx.x * 256 + threadIdx.x;
    int n = id >> 6, s = id & 63;
    int cnt[4] = {0,0,0,0};
    #pragma unroll
    for (int p = 0; p < 16; p++) cnt[g_hidx[((size_t)p*64 + n)*64 + s]]++;
    int bi = 0, bv = cnt[0];
    if (cnt[1] > bv) { bv = cnt[1]; bi = 1; }
    if (cnt[2] > bv) { bv = cnt[2]; bi = 2; }
    if (cnt[3] > bv) { bv = cnt[3]; bi = 3; }
    if (doWrite) out[NB*CB*PB + id] = (float)bi;
}

// ------------------------------------------------------------------ k_gemm: A-resident warp-MMA (unchanged from R8)
#define KC 64
#define LDA 264
#define A_TILE_B (128*LDA*2)    // 67584 per (hi|lo)
#define LDT 72
#define BTILE (128*LDT*2)       // 18432
#define BSTAGE (2*BTILE)        // 36864
#define SM_B0 (2*A_TILE_B)      // 135168
#define GEMM_SMEM (2*A_TILE_B + 2*BSTAGE)   // 208896
#define YLD 132

__device__ __forceinline__ void load_A_ca(const __nv_bfloat16* __restrict__ src,
        size_t row0, uint32_t dst_s, int t) {
    #pragma unroll
    for (int it = 0; it < 16; it++) {
        int v = it*256 + t;
        int r = v >> 5, kv = (v & 31) << 3;
        cp16(dst_s + (uint32_t)(r*LDA + kv)*2, src + (row0 + r)*256 + kv);
    }
}
__device__ __forceinline__ void load_B_ca(const __nv_bfloat16* __restrict__ srcH,
        const __nv_bfloat16* __restrict__ srcL,
        int brow0, int k0, uint32_t dst_s, int t) {
    #pragma unroll
    for (int it = 0; it < 4; it++) {
        int v = it*256 + t;
        int r = v >> 3, kv = (v & 7) << 3;
        cp16(dst_s + (uint32_t)(r*LDT + kv)*2, srcH + (size_t)(brow0 + r)*256 + k0 + kv);
        cp16(dst_s + BTILE + (uint32_t)(r*LDT + kv)*2, srcL + (size_t)(brow0 + r)*256 + k0 + kv);
    }
}

__global__ __launch_bounds__(256, 1) void k_gemm(int mode) {
    extern __shared__ char sm[];
    const uint32_t sb = smem_u32(sm);
    const int t = threadIdx.x;
    const int w = t >> 5, lane = t & 31;
    const int m0 = blockIdx.x * 128;
    const int wy = w >> 1, wx = w & 1;
    const int m_base = wy*32, n_base = wx*64;
    __shared__ unsigned char sidx[128];

    if (mode == 1 && t < 128) {
        int b = (m0 >> 6) + (t >> 6);
        sidx[t] = g_hidx[((size_t)(b & 15)*64 + (b >> 4))*64 + (t & 63)];
    }

    const __nv_bfloat16* Ah_src = (mode == 0) ? g_xh : g_oh;
    const __nv_bfloat16* Al_src = (mode == 0) ? g_xl : g_ol;
    const int NBLK = (mode == 0) ? 6 : 2;
    const int bbase = (mode == 0) ? 0 : 768;

    const int li = lane >> 3, lr = lane & 7;
    const int a_row = (li & 1)*8 + lr, a_kof = (li >> 1)*8;
    const int b_row = (li >> 1)*8 + lr, b_kof = (li & 1)*8;

    load_A_ca(Ah_src, (size_t)m0, sb, t);
    load_A_ca(Al_src, (size_t)m0, sb + A_TILE_B, t);
    load_B_ca(g_wh, g_wl, bbase, 0, sb + SM_B0, t);
    asm volatile("cp.async.commit_group;" ::: "memory");

    float* Ys = (float*)(sm + SM_B0);

    for (int nb = 0; nb < NBLK; nb++) {
        const int brow0 = bbase + nb*128;
        if (nb > 0) {
            load_B_ca(g_wh, g_wl, brow0, 0, sb + SM_B0, t);
            asm volatile("cp.async.commit_group;" ::: "memory");
        }
        float acc[2][8][4];
        #pragma unroll
        for (int i = 0; i < 2; i++)
            #pragma unroll
            for (int j = 0; j < 8; j++)
                #pragma unroll
                for (int q = 0; q < 4; q++) acc[i][j][q] = 0.f;

        #pragma unroll
        for (int c = 0; c < 4; c++) {
            if (c < 3) {
                load_B_ca(g_wh, g_wl, brow0, (c + 1)*KC, sb + SM_B0 + ((c + 1) & 1)*BSTAGE, t);
                asm volatile("cp.async.commit_group;" ::: "memory");
                asm volatile("cp.async.wait_group 1;" ::: "memory");
            } else {
                asm volatile("cp.async.wait_group 0;" ::: "memory");
            }
            __syncthreads();
            const uint32_t stB = sb + SM_B0 + (c & 1)*BSTAGE;
            #pragma unroll
            for (int ks = 0; ks < 4; ks++) {
                const int kk = c*KC + ks*16;
                uint32_t ah[2][4], al[2][4];
                #pragma unroll
                for (int mf = 0; mf < 2; mf++) {
                    uint32_t off = (uint32_t)((m_base + mf*16 + a_row)*LDA + kk + a_kof)*2;
                    ldsm4(sb + off, ah[mf][0], ah[mf][1], ah[mf][2], ah[mf][3]);
                    ldsm4(sb + A_TILE_B + off, al[mf][0], al[mf][1], al[mf][2], al[mf][3]);
                }
                #pragma unroll
                for (int nbf = 0; nbf < 4; nbf++) {
                    uint32_t off = (uint32_t)((n_base + nbf*16 + b_row)*LDT + ks*16 + b_kof)*2;
                    uint32_t bh0, bh1, bh2, bh3, bl0, bl1, bl2, bl3;
                    ldsm4(stB + off, bh0, bh1, bh2, bh3);
                    ldsm4(stB + BTILE + off, bl0, bl1, bl2, bl3);
                    #pragma unroll
                    for (int mf = 0; mf < 2; mf++) {
                        mma16816(acc[mf][nbf*2],     ah[mf], bh0, bh1);
                        mma16816(acc[mf][nbf*2 + 1], ah[mf], bh2, bh3);
                        mma16816(acc[mf][nbf*2],     ah[mf], bl0, bl1);
                        mma16816(acc[mf][nbf*2 + 1], ah[mf], bl2, bl3);
                        mma16816(acc[mf][nbf*2],     al[mf], bh0, bh1);
                        mma16816(acc[mf][nbf*2 + 1], al[mf], bh2, bh3);
                    }
                }
            }
            __syncthreads();
        }

        {
            const int mr = lane >> 2, nc = (lane & 3)*2;
            #pragma unroll
            for (int mf = 0; mf < 2; mf++)
                #pragma unroll
                for (int nf = 0; nf < 8; nf++) {
                    int m = m_base + mf*16 + mr;
                    int n = n_base + nf*8 + nc;
                    float b0 = g_biasv[brow0 + n], b1 = g_biasv[brow0 + n + 1];
                    Ys[m*YLD + n]           = acc[mf][nf][0] + b0;
                    Ys[m*YLD + n + 1]       = acc[mf][nf][1] + b1;
                    Ys[(m + 8)*YLD + n]     = acc[mf][nf][2] + b0;
                    Ys[(m + 8)*YLD + n + 1] = acc[mf][nf][3] + b1;
                }
        }
        __syncthreads();

        if (mode == 0) {
            for (int v = t; v < 4096; v += 256) {
                int r = v >> 5, c4 = (v & 31) << 2;
                float4 val = make_float4(Ys[r*YLD + c4], Ys[r*YLD + c4 + 1],
                                         Ys[r*YLD + c4 + 2], Ys[r*YLD + c4 + 3]);
                *(float4*)(g_qkv + (size_t)(m0 + r)*768 + nb*128 + c4) = val;
            }
        } else {
            for (int v = t; v < 4096; v += 256) {
                int r = v >> 5, c4 = (v & 31) << 2;
                float4 rx = *(const float4*)(g_xb + (size_t)(m0 + r)*256 + nb*128 + c4);
                Ys[r*YLD + c4]     += rx.x;
                Ys[r*YLD + c4 + 1] += rx.y;
                Ys[r*YLD + c4 + 2] += rx.z;
                Ys[r*YLD + c4 + 3] += rx.w;
            }
            __syncthreads();
            for (int id = t; id < 1024; id += 256) {
                int bl = id >> 9, j = (id >> 7) & 3, c = id & 127;
                float m = -1e30f;
                #pragma unroll 8
                for (int s = 0; s < 64; s++) {
                    float v = (sidx[bl*64 + s] == j) ? Ys[(bl*64 + s)*YLD + c] : 0.f;
                    m = fmaxf(m, v);
                }
                int b = (m0 >> 6) + bl;
                int n = b >> 4, p = b & 15;
                g_clu[((size_t)p*64 + n)*1024 + j*256 + nb*128 + c] = m;
            }
        }
        __syncthreads();
    }
}

// ------------------------------------------------------------------ K_attn: HMMA attention per (b, h), 128 threads
// smem: Qh Ql Kh Kl Vh Vl tiles, 64 x LDV bf16 each
#define LDV 72
#define AT_TILE (64*LDV*2)      // 9216
#define ATTN_SMEM (6*AT_TILE)   // 55296

__global__ __launch_bounds__(128) void k_attn() {
    extern __shared__ char sma[];
    const uint32_t sb = smem_u32(sma);
    const uint32_t sQh = sb, sQl = sb + AT_TILE, sKh = sb + 2*AT_TILE,
                   sKl = sb + 3*AT_TILE, sVh = sb + 4*AT_TILE, sVl = sb + 5*AT_TILE;
    __nv_bfloat16* pQh = (__nv_bfloat16*)sma;
    const int bid = blockIdx.x;
    const int b = bid >> 2, h = bid & 3;
    const int t = threadIdx.x;
    const int w = t >> 5, lane = t & 31;
    const size_t rbase = (size_t)b * 64;

    // load Q,K,V (fp32) -> split bf16 hi/lo tiles; fold 1/8 score scale into Q
    for (int idx = t; idx < 1024; idx += 128) {
        int row = idx >> 4, d4 = (idx & 15) << 2;
        const float* src = g_qkv + (rbase + row)*768 + h*64 + d4;
        float4 q = *(const float4*)src;
        float4 k = *(const float4*)(src + 256);
        float4 v = *(const float4*)(src + 512);
        q.x *= 0.125f; q.y *= 0.125f; q.z *= 0.125f; q.w *= 0.125f;
        int eo = row*LDV + d4;
        uint32_t hi, lo;
        split2(q.x, q.y, hi, lo);
        *(uint32_t*)(pQh + eo) = hi;                       *(uint32_t*)(pQh + (AT_TILE/2) + eo) = lo;
        split2(q.z, q.w, hi, lo);
        *(uint32_t*)(pQh + eo + 2) = hi;                   *(uint32_t*)(pQh + (AT_TILE/2) + eo + 2) = lo;
        split2(k.x, k.y, hi, lo);
        *(uint32_t*)(pQh + AT_TILE + eo) = hi;             *(uint32_t*)(pQh + (3*AT_TILE/2) + eo) = lo;
        split2(k.z, k.w, hi, lo);
        *(uint32_t*)(pQh + AT_TILE + eo + 2) = hi;         *(uint32_t*)(pQh + (3*AT_TILE/2) + eo + 2) = lo;
        split2(v.x, v.y, hi, lo);
        *(uint32_t*)(pQh + 2*AT_TILE + eo) = hi;           *(uint32_t*)(pQh + (5*AT_TILE/2) + eo) = lo;
        split2(v.z, v.w, hi, lo);
        *(uint32_t*)(pQh + 2*AT_TILE + eo + 2) = hi;       *(uint32_t*)(pQh + (5*AT_TILE/2) + eo + 2) = lo;
    }
    __syncthreads();

    const int r0 = w * 16;
    const int li = lane >> 3, lr = lane & 7;
    const int t_row = (li & 1)*8 + lr, t_col = (li >> 1)*8;   // A / V(trans) pattern
    const int b_row = (li >> 1)*8 + lr, b_col = (li & 1)*8;   // B(K) pattern

    // ---- scores = (Q/8) K^T  (3-term split) ----
    float sc[4][8];
    #pragma unroll
    for (int i = 0; i < 4; i++)
        #pragma unroll
        for (int j = 0; j < 8; j++) sc[i][j] = 0.f;

    #pragma unroll
    for (int kb = 0; kb < 4; kb++) {
        uint32_t aoff = (uint32_t)((r0 + t_row)*LDV + kb*16 + t_col)*2;
        uint32_t qh[4], ql[4];
        ldsm4(sQh + aoff, qh[0], qh[1], qh[2], qh[3]);
        ldsm4(sQl + aoff, ql[0], ql[1], ql[2], ql[3]);
        #pragma unroll
        for (int nb = 0; nb < 4; nb++) {
            uint32_t boff = (uint32_t)((nb*16 + b_row)*LDV + kb*16 + b_col)*2;
            uint32_t kh0, kh1, kh2, kh3, kl0, kl1, kl2, kl3;
            ldsm4(sKh + boff, kh0, kh1, kh2, kh3);
            ldsm4(sKl + boff, kl0, kl1, kl2, kl3);
            mma16816(sc[nb],     qh, kh0, kh1);
            mma16816(sc[nb] + 4, qh, kh2, kh3);
            mma16816(sc[nb],     qh, kl0, kl1);
            mma16816(sc[nb] + 4, qh, kl2, kl3);
            mma16816(sc[nb],     ql, kh0, kh1);
            mma16816(sc[nb] + 4, ql, kh2, kh3);
        }
    }

    // ---- causal softmax in registers ----
    // thread holds rows gr0 = r0 + (lane>>2), gr1 = gr0+8; cols nb*16 + 8*blk + 2q + {0,1}
    {
        const int r = lane >> 2, q2 = (lane & 3)*2;
        const int gr0 = r0 + r, gr1 = gr0 + 8;
        float m0 = -1e30f, m1 = -1e30f;
        #pragma unroll
        for (int nb = 0; nb < 4; nb++) {
            int c0 = nb*16 + q2, c8 = c0 + 8;
            if (c0     > gr0) sc[nb][0] = -1e30f;
            if (c0 + 1 > gr0) sc[nb][1] = -1e30f;
            if (c8     > gr0) sc[nb][4] = -1e30f;
            if (c8 + 1 > gr0) sc[nb][5] = -1e30f;
            if (c0     > gr1) sc[nb][2] = -1e30f;
            if (c0 + 1 > gr1) sc[nb][3] = -1e30f;
            if (c8     > gr1) sc[nb][6] = -1e30f;
            if (c8 + 1 > gr1) sc[nb][7] = -1e30f;
            m0 = fmaxf(m0, fmaxf(fmaxf(sc[nb][0], sc[nb][1]), fmaxf(sc[nb][4], sc[nb][5])));
            m1 = fmaxf(m1, fmaxf(fmaxf(sc[nb][2], sc[nb][3]), fmaxf(sc[nb][6], sc[nb][7])));
        }
        #pragma unroll
        for (int o = 1; o < 4; o <<= 1) {
            m0 = fmaxf(m0, __shfl_xor_sync(0xffffffffu, m0, o));
            m1 = fmaxf(m1, __shfl_xor_sync(0xffffffffu, m1, o));
        }
        float s0 = 0.f, s1 = 0.f;
        #pragma unroll
        for (int nb = 0; nb < 4; nb++) {
            sc[nb][0] = __expf(sc[nb][0] - m0); s0 += sc[nb][0];
            sc[nb][1] = __expf(sc[nb][1] - m0); s0 += sc[nb][1];
            sc[nb][4] = __expf(sc[nb][4] - m0); s0 += sc[nb][4];
            sc[nb][5] = __expf(sc[nb][5] - m0); s0 += sc[nb][5];
            sc[nb][2] = __expf(sc[nb][2] - m1); s1 += sc[nb][2];
            sc[nb][3] = __expf(sc[nb][3] - m1); s1 += sc[nb][3];
            sc[nb][6] = __expf(sc[nb][6] - m1); s1 += sc[nb][6];
            sc[nb][7] = __expf(sc[nb][7] - m1); s1 += sc[nb][7];
        }
        #pragma unroll
        for (int o = 1; o < 4; o <<= 1) {
            s0 += __shfl_xor_sync(0xffffffffu, s0, o);
            s1 += __shfl_xor_sync(0xffffffffu, s1, o);
        }
        float i0 = 1.f / s0, i1 = 1.f / s1;
        #pragma unroll
        for (int nb = 0; nb < 4; nb++) {
            sc[nb][0] *= i0; sc[nb][1] *= i0; sc[nb][4] *= i0; sc[nb][5] *= i0;
            sc[nb][2] *= i1; sc[nb][3] *= i1; sc[nb][6] *= i1; sc[nb][7] *= i1;
        }
    }

    // ---- O = P V (P register-resident, 3-term split; V via ldmatrix.trans) ----
    float o[4][8];
    #pragma unroll
    for (int i = 0; i < 4; i++)
        #pragma unroll
        for (int j = 0; j < 8; j++) o[i][j] = 0.f;

    #pragma unroll
    for (int kb = 0; kb < 4; kb++) {
        uint32_t ph[4], pl[4];
        split2(sc[kb][0], sc[kb][1], ph[0], pl[0]);
        split2(sc[kb][2], sc[kb][3], ph[1], pl[1]);
        split2(sc[kb][4], sc[kb][5], ph[2], pl[2]);
        split2(sc[kb][6], sc[kb][7], ph[3], pl[3]);
        #pragma unroll
        for (int nbo = 0; nbo < 4; nbo++) {
            uint32_t voff = (uint32_t)((kb*16 + t_row)*LDV + nbo*16 + t_col)*2;
            uint32_t vh0, vh1, vh2, vh3, vl0, vl1, vl2, vl3;
            ldsm4t(sVh + voff, vh0, vh1, vh2, vh3);
            ldsm4t(sVl + voff, vl0, vl1, vl2, vl3);
            mma16816(o[nbo],     ph, vh0, vh1);
            mma16816(o[nbo] + 4, ph, vh2, vh3);
            mma16816(o[nbo],     ph, vl0, vl1);
            mma16816(o[nbo] + 4, ph, vl2, vl3);
            mma16816(o[nbo],     pl, vh0, vh1);
            mma16816(o[nbo] + 4, pl, vh2, vh3);
        }
    }

    // ---- store O as bf16 hi/lo ----
    {
        const int r = lane >> 2, q2 = (lane & 3)*2;
        const size_t base0 = (rbase + r0 + r)*256 + h*64;
        const size_t base1 = base0 + 8*256;
        #pragma unroll
        for (int nbo = 0; nbo < 4; nbo++) {
            int c = nbo*16 + q2;
            uint32_t hi, lo;
            split2(o[nbo][0], o[nbo][1], hi, lo);
            *(uint32_t*)(g_oh + base0 + c) = hi;     *(uint32_t*)(g_ol + base0 + c) = lo;
            split2(o[nbo][4], o[nbo][5], hi, lo);
            *(uint32_t*)(g_oh + base0 + c + 8) = hi; *(uint32_t*)(g_ol + base0 + c + 8) = lo;
            split2(o[nbo][2], o[nbo][3], hi, lo);
            *(uint32_t*)(g_oh + base1 + c) = hi;     *(uint32_t*)(g_ol + base1 + c) = lo;
            split2(o[nbo][6], o[nbo][7], hi, lo);
            *(uint32_t*)(g_oh + base1 + c + 8) = hi; *(uint32_t*)(g_ol + base1 + c + 8) = lo;
        }
    }
}

// ------------------------------------------------------------------ K4: per-part FC  out[n,o,p]
__global__ __launch_bounds__(256) void k4_fc(const float* __restrict__ fc, float* __restrict__ out) {
    __shared__ float As[64*68];
    __shared__ float Bs[64*64];
    const int p = blockIdx.x, ot = blockIdx.y;
    const int t = threadIdx.x;
    const int tx = t & 15, ty = t >> 4;
    const int o0 = tx*4, n0 = ty*4;
    float acc[4][4] = {};
    for (int k0 = 0; k0 < 1024; k0 += 64) {
        __syncthreads();
        #pragma unroll
        for (int it = 0; it < 4; it++) {
            int idx = it*256 + t;
            int nn = idx >> 4, k4 = idx & 15;
            *(float4*)(As + nn*68 + k4*4) =
                *(const float4*)(g_clu + ((size_t)p*64 + nn)*1024 + k0 + k4*4);
        }
        #pragma unroll
        for (int it = 0; it < 4; it++) {
            int idx = it*256 + t;
            int kk = idx >> 4, d4 = idx & 15;
            *(float4*)(Bs + kk*64 + d4*4) =
                *(const float4*)(fc + ((size_t)p*1024 + k0 + kk)*256 + ot*64 + d4*4);
        }
        __syncthreads();
        #pragma unroll 4
        for (int kk = 0; kk < 64; kk++) {
            float a[4];
            #pragma unroll
            for (int ii = 0; ii < 4; ii++) a[ii] = As[(n0+ii)*68 + kk];
            float4 bv = *(const float4*)(Bs + kk*64 + o0);
            float bj[4] = {bv.x, bv.y, bv.z, bv.w};
            #pragma unroll
            for (int ii = 0; ii < 4; ii++)
                #pragma unroll
                for (int jj = 0; jj < 4; jj++) acc[ii][jj] += a[ii]*bj[jj];
        }
    }
    #pragma unroll
    for (int ii = 0; ii < 4; ii++)
        #pragma unroll
        for (int jj = 0; jj < 4; jj++)
            out[((size_t)(n0+ii)*256 + ot*64 + o0 + jj)*16 + p] = acc[ii][jj];
}

// ------------------------------------------------------------------ launch
extern "C" void kernel_launch(void* const* d_in, const int* in_sizes, int n_in,
                              void* d_out, int out_size) {
    const float* x     = (const float*)d_in[0];
    const float* proto = (const float*)d_in[1];
    const float* Wq    = (const float*)d_in[2];
    const float* bq    = (const float*)d_in[3];
    const float* Wk    = (const float*)d_in[4];
    const float* bk    = (const float*)d_in[5];
    const float* Wv    = (const float*)d_in[6];
    const float* bv    = (const float*)d_in[7];
    const float* Wo    = (const float*)d_in[8];
    const float* bo    = (const float*)d_in[9];
    const float* fc    = (const float*)d_in[10];
    float* out = (float*)d_out;

    cudaFuncSetAttribute(k0_transpose, cudaFuncAttributeMaxDynamicSharedMemorySize, 69632);
    cudaFuncSetAttribute(k1_assign,    cudaFuncAttributeMaxDynamicSharedMemorySize, 73728);
    cudaFuncSetAttribute(k_gemm,       cudaFuncAttributeMaxDynamicSharedMemorySize, GEMM_SMEM);
    cudaFuncSetAttribute(k_attn,       cudaFuncAttributeMaxDynamicSharedMemorySize, ATTN_SMEM);

    k_wprep<<<64, 256>>>(Wq, Wk, Wv, Wo, bq, bk, bv, bo);
    k0_transpose<<<dim3(16, 64), 256, 69632>>>(x);
    k1_assign<<<NB*PB, 256, (64*257 + 4*257 + 512) * sizeof(float)>>>(proto);
    int wtail = (out_size >= NB*CB*PB + NB*SB) ? 1 : 0;
    k2_mode<<<16, 256>>>(out, wtail);
    k_gemm<<<512, 256, GEMM_SMEM>>>(0);                 // QKV projections (A-resident)
    k_attn<<<4096, 128, ATTN_SMEM>>>();                 // HMMA attention core
    k_gemm<<<512, 256, GEMM_SMEM>>>(1);                 // O@Wo + residual + pooling
    k4_fc<<<dim3(16, 4), 256>>>(fc, out);
}

// round 10
// speedup vs baseline: 2.5960x; 1.0589x over previous
#include <cuda_runtime.h>
#include <cuda_bf16.h>
#include <math.h>
#include <stdint.h>

#define NB 64
#define CB 256
#define SB 64
#define PB 16
#define KCL 4
#define RT (NB*PB*SB)          // 65536 total rows (b = n*16+p, s)

// ------------------------------------------------------------------ globals
__device__ float         g_xb[(size_t)RT*CB];     // X fp32 (b,s,c) exact
__device__ __nv_bfloat16 g_xh[(size_t)RT*CB];     // X hi
__device__ __nv_bfloat16 g_xl[(size_t)RT*CB];     // X lo
__device__ __nv_bfloat16 g_ph[(size_t)RT*768];    // Q|K|V hi (Q pre-scaled by 1/8)
__device__ __nv_bfloat16 g_pl[(size_t)RT*768];    // Q|K|V lo
__device__ __nv_bfloat16 g_oh[(size_t)RT*CB];     // attn out hi
__device__ __nv_bfloat16 g_ol[(size_t)RT*CB];     // attn out lo
__device__ __nv_bfloat16 g_wh[1024*CB];           // weights hi: rows 0..767 = Wq|Wk|Wv^T, 768..1023 = Wo^T   [n][k]
__device__ __nv_bfloat16 g_wl[1024*CB];           // lo
__device__ float         g_biasv[1024];           // bq|bk|bv|bo
__device__ float         g_clu[PB*NB*KCL*CB];
__device__ unsigned char g_hidx[PB*NB*SB];

// ------------------------------------------------------------------ helpers
__device__ __forceinline__ uint32_t smem_u32(const void* p) {
    uint32_t a;
    asm("{ .reg .u64 t; cvta.to.shared.u64 t, %1; cvt.u32.u64 %0, t; }" : "=r"(a) : "l"(p));
    return a;
}
__device__ __forceinline__ void ldsm4(uint32_t a, uint32_t& r0, uint32_t& r1, uint32_t& r2, uint32_t& r3) {
    asm volatile("ldmatrix.sync.aligned.m8n8.x4.shared.b16 {%0,%1,%2,%3}, [%4];"
        : "=r"(r0), "=r"(r1), "=r"(r2), "=r"(r3) : "r"(a));
}
__device__ __forceinline__ void ldsm4t(uint32_t a, uint32_t& r0, uint32_t& r1, uint32_t& r2, uint32_t& r3) {
    asm volatile("ldmatrix.sync.aligned.m8n8.x4.trans.shared.b16 {%0,%1,%2,%3}, [%4];"
        : "=r"(r0), "=r"(r1), "=r"(r2), "=r"(r3) : "r"(a));
}
__device__ __forceinline__ void mma16816(float* d, const uint32_t* a, uint32_t b0, uint32_t b1) {
    asm volatile("mma.sync.aligned.m16n8k16.row.col.f32.bf16.bf16.f32 "
        "{%0,%1,%2,%3}, {%4,%5,%6,%7}, {%8,%9}, {%0,%1,%2,%3};"
        : "+f"(d[0]), "+f"(d[1]), "+f"(d[2]), "+f"(d[3])
        : "r"(a[0]), "r"(a[1]), "r"(a[2]), "r"(a[3]), "r"(b0), "r"(b1));
}
__device__ __forceinline__ void cp16(uint32_t sa, const void* ga) {
    asm volatile("cp.async.cg.shared.global [%0], [%1], 16;" :: "r"(sa), "l"(ga));
}
__device__ __forceinline__ void split2(float x, float y, uint32_t& hi, uint32_t& lo) {
    __nv_bfloat16 hx = __float2bfloat16(x), hy = __float2bfloat16(y);
    __nv_bfloat16 lx = __float2bfloat16(x - __bfloat162float(hx));
    __nv_bfloat16 ly = __float2bfloat16(y - __bfloat162float(hy));
    __nv_bfloat162 H; H.x = hx; H.y = hy;
    __nv_bfloat162 L; L.x = lx; L.y = ly;
    hi = *(uint32_t*)&H; lo = *(uint32_t*)&L;
}

// ------------------------------------------------------------------ K0: transpose + bf16 split
__global__ __launch_bounds__(256) void k0_transpose(const float* __restrict__ x) {
    extern __shared__ float tile[];          // [(s*16+p)][17]
    const int cchunk = blockIdx.x, n = blockIdx.y;
    const int t = threadIdx.x;
    const int c0 = cchunk * 16;
    #pragma unroll
    for (int it = 0; it < 16; it++) {
        int idx = it * 256 + t;
        int ci = idx >> 8;
        int rem = idx & 255;
        int s = rem >> 2;
        int p4 = rem & 3;
        const float4 v = *(const float4*)(x + (((size_t)n*CB + c0 + ci)*SB + s)*PB + p4*4);
        int base = (s*16 + p4*4)*17 + ci;
        tile[base] = v.x; tile[base+17] = v.y; tile[base+34] = v.z; tile[base+51] = v.w;
    }
    __syncthreads();
    #pragma unroll
    for (int it = 0; it < 8; it++) {
        int idx = it * 256 + t;              // 2048: (s,p,vec8)
        int vec = idx & 1;
        int pr = idx >> 1;
        int s = pr >> 4, p = pr & 15;
        int base = (s*16 + p)*17 + vec*8;
        __align__(16) float f[8];
        __align__(16) __nv_bfloat16 hi[8];
        __align__(16) __nv_bfloat16 lo[8];
        #pragma unroll
        for (int u = 0; u < 8; u++) {
            float v = tile[base + u];
            f[u] = v;
            hi[u] = __float2bfloat16(v);
            lo[u] = __float2bfloat16(v - __bfloat162float(hi[u]));
        }
        size_t off = (((size_t)n*16 + p)*64 + s)*256 + c0 + vec*8;
        *(uint4*)(g_xb + off)     = *(uint4*)f;
        *(uint4*)(g_xb + off + 4) = *(uint4*)(f + 4);
        *(uint4*)(g_xh + off) = *(uint4*)hi;
        *(uint4*)(g_xl + off) = *(uint4*)lo;
    }
}

// ------------------------------------------------------------------ K_wprep: smem-tiled transpose, coalesced both sides
__global__ __launch_bounds__(256) void k_wprep(
    const float* __restrict__ Wq, const float* __restrict__ Wk,
    const float* __restrict__ Wv, const float* __restrict__ Wo,
    const float* __restrict__ bq, const float* __restrict__ bk,
    const float* __restrict__ bv, const float* __restrict__ bo)
{
    __shared__ float tile[64*68];
    const int bx = blockIdx.x;               // 64 blocks
    const int mat = bx >> 4, tl = bx & 15;
    const int kt = (tl >> 2) << 6, nt = (tl & 3) << 6;
    const float* W = (mat == 0) ? Wq : (mat == 1) ? Wk : (mat == 2) ? Wv : Wo;
    const int t = threadIdx.x;
    #pragma unroll
    for (int it = 0; it < 4; it++) {
        int v = it*256 + t;                  // 1024: 64 k-rows x 16 float4
        int r = v >> 4, c4 = (v & 15) << 2;
        float4 val = *(const float4*)(W + (size_t)(kt + r)*256 + nt + c4);
        tile[(c4+0)*68 + r] = val.x;
        tile[(c4+1)*68 + r] = val.y;
        tile[(c4+2)*68 + r] = val.z;
        tile[(c4+3)*68 + r] = val.w;
    }
    __syncthreads();
    #pragma unroll
    for (int it = 0; it < 2; it++) {
        int v = it*256 + t;                  // 512: 64 n-rows x 8 vec8
        int n = v >> 3, k8 = (v & 7) << 3;
        __align__(16) __nv_bfloat16 hi[8];
        __align__(16) __nv_bfloat16 lo[8];
        #pragma unroll
        for (int u = 0; u < 8; u++) {
            float w = tile[n*68 + k8 + u];
            hi[u] = __float2bfloat16(w);
            lo[u] = __float2bfloat16(w - __bfloat162float(hi[u]));
        }
        size_t off = (size_t)(mat*256 + nt + n)*256 + kt + k8;
        *(uint4*)(g_wh + off) = *(uint4*)hi;
        *(uint4*)(g_wl + off) = *(uint4*)lo;
    }
    if (tl == 0) {
        const float* bias = (mat == 0) ? bq : (mat == 1) ? bk : (mat == 2) ? bv : bo;
        g_biasv[mat*256 + t] = bias[t];
    }
}

// ------------------------------------------------------------------ K1: instnorm + argmax assignment
__global__ __launch_bounds__(256) void k1_assign(const float* __restrict__ proto) {
    extern __shared__ float sm1[];
    float* xs = sm1;               // 64*257
    float* pn = xs + 64*257;       // 4*257
    float* mu = pn + 4*257;        // 256
    float* rv = mu + 256;          // 256
    __shared__ float nrm[4];
    const int b = blockIdx.x;
    const int n = b >> 4, p = b & 15;
    const int t = threadIdx.x;

    #pragma unroll
    for (int it = 0; it < 4; it++) {
        int i = it*256 + t; int k = i >> 8; int c = i & 255;
        pn[k*257 + c] = proto[((size_t)p*4 + k)*256 + c];
    }
    __syncthreads();
    if (t < 128) {
        int k = t >> 5, lane = t & 31; float s = 0.f;
        #pragma unroll
        for (int j = 0; j < 8; j++) { float v = pn[k*257 + lane + j*32]; s += v*v; }
        #pragma unroll
        for (int o = 16; o > 0; o >>= 1) s += __shfl_down_sync(0xffffffffu, s, o);
        if (lane == 0) nrm[k] = rsqrtf(s);
    }
    __syncthreads();
    #pragma unroll
    for (int it = 0; it < 4; it++) {
        int i = it*256 + t; int k = i >> 8; int c = i & 255;
        pn[k*257 + c] *= nrm[k];
    }
    const float* xg = g_xb + (size_t)b * SB * CB;
    for (int it = 0; it < 64; it++) {
        int i = it*256 + t; int s = i >> 8; int c = i & 255;
        xs[s*257 + c] = xg[i];
    }
    __syncthreads();
    {
        int c = t; float sum = 0.f;
        #pragma unroll 8
        for (int s = 0; s < 64; s++) sum += xs[s*257 + c];
        float m = sum * (1.f/64.f);
        float sq = 0.f;
        #pragma unroll 8
        for (int s = 0; s < 64; s++) { float d = xs[s*257 + c] - m; sq += d*d; }
        mu[c] = m;
        rv[c] = rsqrtf(sq * (1.f/64.f) + 1e-5f);
    }
    __syncthreads();
    {
        int s = t >> 2, k = t & 3;
        float acc = 0.f;
        #pragma unroll 8
        for (int c = 0; c < 256; c++)
            acc += (xs[s*257 + c] - mu[c]) * rv[c] * pn[k*257 + c];
        float a1 = __shfl_down_sync(0xffffffffu, acc, 1);
        float a2 = __shfl_down_sync(0xffffffffu, acc, 2);
        float a3 = __shfl_down_sync(0xffffffffu, acc, 3);
        if (k == 0) {
            int bi = 0; float bv = acc;
            if (a1 > bv) { bv = a1; bi = 1; }
            if (a2 > bv) { bv = a2; bi = 2; }
            if (a3 > bv) { bv = a3; bi = 3; }
            g_hidx[((size_t)p*64 + n)*64 + s] = (unsigned char)bi;
        }
    }
}

// ------------------------------------------------------------------ K2: mode over parts
__global__ void k2_mode(float* __restrict__ out, int doWrite) {
    int id = blockIdx.x * 256 + threadIdx.x;
    int n = id >> 6, s = id & 63;
    int cnt[4] = {0,0,0,0};
    #pragma unroll
    for (int p = 0; p < 16; p++) cnt[g_hidx[((size_t)p*64 + n)*64 + s]]++;
    int bi = 0, bv = cnt[0];
    if (cnt[1] > bv) { bv = cnt[1]; bi = 1; }
    if (cnt[2] > bv) { bv = cnt[2]; bi = 2; }
    if (cnt[3] > bv) { bv = cnt[3]; bi = 3; }
    if (doWrite) out[NB*CB*PB + id] = (float)bi;
}

// ------------------------------------------------------------------ k_gemm: A-resident warp-MMA
#define KC 64
#define LDA 264
#define A_TILE_B (128*LDA*2)    // 67584 per (hi|lo)
#define LDT 72
#define BTILE (128*LDT*2)       // 18432
#define BSTAGE (2*BTILE)        // 36864
#define SM_B0 (2*A_TILE_B)      // 135168
#define GEMM_SMEM (2*A_TILE_B + 2*BSTAGE)   // 208896
#define YLD 132

__device__ __forceinline__ void load_A_ca(const __nv_bfloat16* __restrict__ src,
        size_t row0, uint32_t dst_s, int t) {
    #pragma unroll
    for (int it = 0; it < 16; it++) {
        int v = it*256 + t;
        int r = v >> 5, kv = (v & 31) << 3;
        cp16(dst_s + (uint32_t)(r*LDA + kv)*2, src + (row0 + r)*256 + kv);
    }
}
__device__ __forceinline__ void load_B_ca(const __nv_bfloat16* __restrict__ srcH,
        const __nv_bfloat16* __restrict__ srcL,
        int brow0, int k0, uint32_t dst_s, int t) {
    #pragma unroll
    for (int it = 0; it < 4; it++) {
        int v = it*256 + t;
        int r = v >> 3, kv = (v & 7) << 3;
        cp16(dst_s + (uint32_t)(r*LDT + kv)*2, srcH + (size_t)(brow0 + r)*256 + k0 + kv);
        cp16(dst_s + BTILE + (uint32_t)(r*LDT + kv)*2, srcL + (size_t)(brow0 + r)*256 + k0 + kv);
    }
}

__global__ __launch_bounds__(256, 1) void k_gemm(int mode) {
    extern __shared__ char sm[];
    const uint32_t sb = smem_u32(sm);
    const int t = threadIdx.x;
    const int w = t >> 5, lane = t & 31;
    const int m0 = blockIdx.x * 128;
    const int wy = w >> 1, wx = w & 1;
    const int m_base = wy*32, n_base = wx*64;
    __shared__ unsigned char sidx[128];

    if (mode == 1 && t < 128) {
        int b = (m0 >> 6) + (t >> 6);
        sidx[t] = g_hidx[((size_t)(b & 15)*64 + (b >> 4))*64 + (t & 63)];
    }

    const __nv_bfloat16* Ah_src = (mode == 0) ? g_xh : g_oh;
    const __nv_bfloat16* Al_src = (mode == 0) ? g_xl : g_ol;
    const int NBLK = (mode == 0) ? 6 : 2;
    const int bbase = (mode == 0) ? 0 : 768;

    const int li = lane >> 3, lr = lane & 7;
    const int a_row = (li & 1)*8 + lr, a_kof = (li >> 1)*8;
    const int b_row = (li >> 1)*8 + lr, b_kof = (li & 1)*8;

    load_A_ca(Ah_src, (size_t)m0, sb, t);
    load_A_ca(Al_src, (size_t)m0, sb + A_TILE_B, t);
    load_B_ca(g_wh, g_wl, bbase, 0, sb + SM_B0, t);
    asm volatile("cp.async.commit_group;" ::: "memory");

    float* Ys = (float*)(sm + SM_B0);

    for (int nb = 0; nb < NBLK; nb++) {
        const int brow0 = bbase + nb*128;
        if (nb > 0) {
            load_B_ca(g_wh, g_wl, brow0, 0, sb + SM_B0, t);
            asm volatile("cp.async.commit_group;" ::: "memory");
        }
        float acc[2][8][4];
        #pragma unroll
        for (int i = 0; i < 2; i++)
            #pragma unroll
            for (int j = 0; j < 8; j++)
                #pragma unroll
                for (int q = 0; q < 4; q++) acc[i][j][q] = 0.f;

        #pragma unroll
        for (int c = 0; c < 4; c++) {
            if (c < 3) {
                load_B_ca(g_wh, g_wl, brow0, (c + 1)*KC, sb + SM_B0 + ((c + 1) & 1)*BSTAGE, t);
                asm volatile("cp.async.commit_group;" ::: "memory");
                asm volatile("cp.async.wait_group 1;" ::: "memory");
            } else {
                asm volatile("cp.async.wait_group 0;" ::: "memory");
            }
            __syncthreads();
            const uint32_t stB = sb + SM_B0 + (c & 1)*BSTAGE;
            #pragma unroll
            for (int ks = 0; ks < 4; ks++) {
                const int kk = c*KC + ks*16;
                uint32_t ah[2][4], al[2][4];
                #pragma unroll
                for (int mf = 0; mf < 2; mf++) {
                    uint32_t off = (uint32_t)((m_base + mf*16 + a_row)*LDA + kk + a_kof)*2;
                    ldsm4(sb + off, ah[mf][0], ah[mf][1], ah[mf][2], ah[mf][3]);
                    ldsm4(sb + A_TILE_B + off, al[mf][0], al[mf][1], al[mf][2], al[mf][3]);
                }
                #pragma unroll
                for (int nbf = 0; nbf < 4; nbf++) {
                    uint32_t off = (uint32_t)((n_base + nbf*16 + b_row)*LDT + ks*16 + b_kof)*2;
                    uint32_t bh0, bh1, bh2, bh3, bl0, bl1, bl2, bl3;
                    ldsm4(stB + off, bh0, bh1, bh2, bh3);
                    ldsm4(stB + BTILE + off, bl0, bl1, bl2, bl3);
                    #pragma unroll
                    for (int mf = 0; mf < 2; mf++) {
                        mma16816(acc[mf][nbf*2],     ah[mf], bh0, bh1);
                        mma16816(acc[mf][nbf*2 + 1], ah[mf], bh2, bh3);
                        mma16816(acc[mf][nbf*2],     ah[mf], bl0, bl1);
                        mma16816(acc[mf][nbf*2 + 1], ah[mf], bl2, bl3);
                        mma16816(acc[mf][nbf*2],     al[mf], bh0, bh1);
                        mma16816(acc[mf][nbf*2 + 1], al[mf], bh2, bh3);
                    }
                }
            }
            __syncthreads();
        }

        {
            const int mr = lane >> 2, nc = (lane & 3)*2;
            #pragma unroll
            for (int mf = 0; mf < 2; mf++)
                #pragma unroll
                for (int nf = 0; nf < 8; nf++) {
                    int m = m_base + mf*16 + mr;
                    int n = n_base + nf*8 + nc;
                    float b0 = g_biasv[brow0 + n], b1 = g_biasv[brow0 + n + 1];
                    Ys[m*YLD + n]           = acc[mf][nf][0] + b0;
                    Ys[m*YLD + n + 1]       = acc[mf][nf][1] + b1;
                    Ys[(m + 8)*YLD + n]     = acc[mf][nf][2] + b0;
                    Ys[(m + 8)*YLD + n + 1] = acc[mf][nf][3] + b1;
                }
        }
        __syncthreads();

        if (mode == 0) {
            // convert to split bf16, Q (nb<2) pre-scaled by 1/8
            const float qscale = (nb < 2) ? 0.125f : 1.f;
            for (int v = t; v < 2048; v += 256) {       // 128 rows x 16 vec8
                int r = v >> 4, c8 = (v & 15) << 3;
                uint32_t hi4[4], lo4[4];
                #pragma unroll
                for (int u = 0; u < 4; u++) {
                    float fa = Ys[r*YLD + c8 + 2*u]     * qscale;
                    float fb = Ys[r*YLD + c8 + 2*u + 1] * qscale;
                    split2(fa, fb, hi4[u], lo4[u]);
                }
                size_t off = (size_t)(m0 + r)*768 + nb*128 + c8;
                *(uint4*)(g_ph + off) = *(uint4*)hi4;
                *(uint4*)(g_pl + off) = *(uint4*)lo4;
            }
        } else {
            for (int v = t; v < 4096; v += 256) {
                int r = v >> 5, c4 = (v & 31) << 2;
                float4 rx = *(const float4*)(g_xb + (size_t)(m0 + r)*256 + nb*128 + c4);
                Ys[r*YLD + c4]     += rx.x;
                Ys[r*YLD + c4 + 1] += rx.y;
                Ys[r*YLD + c4 + 2] += rx.z;
                Ys[r*YLD + c4 + 3] += rx.w;
            }
            __syncthreads();
            for (int id = t; id < 1024; id += 256) {
                int bl = id >> 9, j = (id >> 7) & 3, c = id & 127;
                float m = -1e30f;
                #pragma unroll 8
                for (int s = 0; s < 64; s++) {
                    float v = (sidx[bl*64 + s] == j) ? Ys[(bl*64 + s)*YLD + c] : 0.f;
                    m = fmaxf(m, v);
                }
                int b = (m0 >> 6) + bl;
                int n = b >> 4, p = b & 15;
                g_clu[((size_t)p*64 + n)*1024 + j*256 + nb*128 + c] = m;
            }
        }
        __syncthreads();
    }
}

// ------------------------------------------------------------------ K_attn: HMMA attention per (b, h), 128 threads
#define LDV 72
#define AT_TILE (64*LDV*2)      // 9216
#define ATTN_SMEM (6*AT_TILE)   // 55296

__global__ __launch_bounds__(128) void k_attn() {
    extern __shared__ char sma[];
    const uint32_t sb = smem_u32(sma);
    const uint32_t sQh = sb, sQl = sb + AT_TILE, sKh = sb + 2*AT_TILE,
                   sKl = sb + 3*AT_TILE, sVh = sb + 4*AT_TILE, sVl = sb + 5*AT_TILE;
    const int bid = blockIdx.x;
    const int b = bid >> 2, h = bid & 3;
    const int t = threadIdx.x;
    const int w = t >> 5, lane = t & 31;
    const size_t rbase = (size_t)b * 64;

    // load split Q,K,V tiles straight from g_ph/g_pl via cp.async
    #pragma unroll
    for (int q = 0; q < 3; q++) {
        for (int idx = t; idx < 512; idx += 128) {
            int r = idx >> 3, kv = (idx & 7) << 3;
            size_t go = (rbase + r)*768 + q*256 + h*64 + kv;
            uint32_t so = (uint32_t)(r*LDV + kv)*2;
            cp16(sb + (2*q)*AT_TILE + so,     g_ph + go);
            cp16(sb + (2*q + 1)*AT_TILE + so, g_pl + go);
        }
    }
    asm volatile("cp.async.commit_group;" ::: "memory");
    asm volatile("cp.async.wait_group 0;" ::: "memory");
    __syncthreads();

    const int r0 = w * 16;
    const int li = lane >> 3, lr = lane & 7;
    const int t_row = (li & 1)*8 + lr, t_col = (li >> 1)*8;   // A / V(trans) pattern
    const int b_row = (li >> 1)*8 + lr, b_col = (li & 1)*8;   // B(K) pattern

    // ---- scores = (Q/8) K^T  (3-term split) ----
    float sc[4][8];
    #pragma unroll
    for (int i = 0; i < 4; i++)
        #pragma unroll
        for (int j = 0; j < 8; j++) sc[i][j] = 0.f;

    #pragma unroll
    for (int kb = 0; kb < 4; kb++) {
        uint32_t aoff = (uint32_t)((r0 + t_row)*LDV + kb*16 + t_col)*2;
        uint32_t qh[4], ql[4];
        ldsm4(sQh + aoff, qh[0], qh[1], qh[2], qh[3]);
        ldsm4(sQl + aoff, ql[0], ql[1], ql[2], ql[3]);
        #pragma unroll
        for (int nb = 0; nb < 4; nb++) {
            uint32_t boff = (uint32_t)((nb*16 + b_row)*LDV + kb*16 + b_col)*2;
            uint32_t kh0, kh1, kh2, kh3, kl0, kl1, kl2, kl3;
            ldsm4(sKh + boff, kh0, kh1, kh2, kh3);
            ldsm4(sKl + boff, kl0, kl1, kl2, kl3);
            mma16816(sc[nb],     qh, kh0, kh1);
            mma16816(sc[nb] + 4, qh, kh2, kh3);
            mma16816(sc[nb],     qh, kl0, kl1);
            mma16816(sc[nb] + 4, qh, kl2, kl3);
            mma16816(sc[nb],     ql, kh0, kh1);
            mma16816(sc[nb] + 4, ql, kh2, kh3);
        }
    }

    // ---- causal softmax in registers ----
    {
        const int r = lane >> 2, q2 = (lane & 3)*2;
        const int gr0 = r0 + r, gr1 = gr0 + 8;
        float m0 = -1e30f, m1 = -1e30f;
        #pragma unroll
        for (int nb = 0; nb < 4; nb++) {
            int c0 = nb*16 + q2, c8 = c0 + 8;
            if (c0     > gr0) sc[nb][0] = -1e30f;
            if (c0 + 1 > gr0) sc[nb][1] = -1e30f;
            if (c8     > gr0) sc[nb][4] = -1e30f;
            if (c8 + 1 > gr0) sc[nb][5] = -1e30f;
            if (c0     > gr1) sc[nb][2] = -1e30f;
            if (c0 + 1 > gr1) sc[nb][3] = -1e30f;
            if (c8     > gr1) sc[nb][6] = -1e30f;
            if (c8 + 1 > gr1) sc[nb][7] = -1e30f;
            m0 = fmaxf(m0, fmaxf(fmaxf(sc[nb][0], sc[nb][1]), fmaxf(sc[nb][4], sc[nb][5])));
            m1 = fmaxf(m1, fmaxf(fmaxf(sc[nb][2], sc[nb][3]), fmaxf(sc[nb][6], sc[nb][7])));
        }
        #pragma unroll
        for (int o = 1; o < 4; o <<= 1) {
            m0 = fmaxf(m0, __shfl_xor_sync(0xffffffffu, m0, o));
            m1 = fmaxf(m1, __shfl_xor_sync(0xffffffffu, m1, o));
        }
        float s0 = 0.f, s1 = 0.f;
        #pragma unroll
        for (int nb = 0; nb < 4; nb++) {
            sc[nb][0] = __expf(sc[nb][0] - m0); s0 += sc[nb][0];
            sc[nb][1] = __expf(sc[nb][1] - m0); s0 += sc[nb][1];
            sc[nb][4] = __expf(sc[nb][4] - m0); s0 += sc[nb][4];
            sc[nb][5] = __expf(sc[nb][5] - m0); s0 += sc[nb][5];
            sc[nb][2] = __expf(sc[nb][2] - m1); s1 += sc[nb][2];
            sc[nb][3] = __expf(sc[nb][3] - m1); s1 += sc[nb][3];
            sc[nb][6] = __expf(sc[nb][6] - m1); s1 += sc[nb][6];
            sc[nb][7] = __expf(sc[nb][7] - m1); s1 += sc[nb][7];
        }
        #pragma unroll
        for (int o = 1; o < 4; o <<= 1) {
            s0 += __shfl_xor_sync(0xffffffffu, s0, o);
            s1 += __shfl_xor_sync(0xffffffffu, s1, o);
        }
        float i0 = 1.f / s0, i1 = 1.f / s1;
        #pragma unroll
        for (int nb = 0; nb < 4; nb++) {
            sc[nb][0] *= i0; sc[nb][1] *= i0; sc[nb][4] *= i0; sc[nb][5] *= i0;
            sc[nb][2] *= i1; sc[nb][3] *= i1; sc[nb][6] *= i1; sc[nb][7] *= i1;
        }
    }

    // ---- O = P V (P register-resident, 3-term split; V via ldmatrix.trans) ----
    float o[4][8];
    #pragma unroll
    for (int i = 0; i < 4; i++)
        #pragma unroll
        for (int j = 0; j < 8; j++) o[i][j] = 0.f;

    #pragma unroll
    for (int kb = 0; kb < 4; kb++) {
        uint32_t ph[4], pl[4];
        split2(sc[kb][0], sc[kb][1], ph[0], pl[0]);
        split2(sc[kb][2], sc[kb][3], ph[1], pl[1]);
        split2(sc[kb][4], sc[kb][5], ph[2], pl[2]);
        split2(sc[kb][6], sc[kb][7], ph[3], pl[3]);
        #pragma unroll
        for (int nbo = 0; nbo < 4; nbo++) {
            uint32_t voff = (uint32_t)((kb*16 + t_row)*LDV + nbo*16 + t_col)*2;
            uint32_t vh0, vh1, vh2, vh3, vl0, vl1, vl2, vl3;
            ldsm4t(sVh + voff, vh0, vh1, vh2, vh3);
            ldsm4t(sVl + voff, vl0, vl1, vl2, vl3);
            mma16816(o[nbo],     ph, vh0, vh1);
            mma16816(o[nbo] + 4, ph, vh2, vh3);
            mma16816(o[nbo],     ph, vl0, vl1);
            mma16816(o[nbo] + 4, ph, vl2, vl3);
            mma16816(o[nbo],     pl, vh0, vh1);
            mma16816(o[nbo] + 4, pl, vh2, vh3);
        }
    }

    // ---- store O as bf16 hi/lo ----
    {
        const int r = lane >> 2, q2 = (lane & 3)*2;
        const size_t base0 = (rbase + r0 + r)*256 + h*64;
        const size_t base1 = base0 + 8*256;
        #pragma unroll
        for (int nbo = 0; nbo < 4; nbo++) {
            int c = nbo*16 + q2;
            uint32_t hi, lo;
            split2(o[nbo][0], o[nbo][1], hi, lo);
            *(uint32_t*)(g_oh + base0 + c) = hi;     *(uint32_t*)(g_ol + base0 + c) = lo;
            split2(o[nbo][4], o[nbo][5], hi, lo);
            *(uint32_t*)(g_oh + base0 + c + 8) = hi; *(uint32_t*)(g_ol + base0 + c + 8) = lo;
            split2(o[nbo][2], o[nbo][3], hi, lo);
            *(uint32_t*)(g_oh + base1 + c) = hi;     *(uint32_t*)(g_ol + base1 + c) = lo;
            split2(o[nbo][6], o[nbo][7], hi, lo);
            *(uint32_t*)(g_oh + base1 + c + 8) = hi; *(uint32_t*)(g_ol + base1 + c + 8) = lo;
        }
    }
}

// ------------------------------------------------------------------ K4: per-part FC  out[n,o,p]
__global__ __launch_bounds__(256) void k4_fc(const float* __restrict__ fc, float* __restrict__ out) {
    __shared__ float As[64*68];
    __shared__ float Bs[64*64];
    const int p = blockIdx.x, ot = blockIdx.y;
    const int t = threadIdx.x;
    const int tx = t & 15, ty = t >> 4;
    const int o0 = tx*4, n0 = ty*4;
    float acc[4][4] = {};
    for (int k0 = 0; k0 < 1024; k0 += 64) {
        __syncthreads();
        #pragma unroll
        for (int it = 0; it < 4; it++) {
            int idx = it*256 + t;
            int nn = idx >> 4, k4 = idx & 15;
            *(float4*)(As + nn*68 + k4*4) =
                *(const float4*)(g_clu + ((size_t)p*64 + nn)*1024 + k0 + k4*4);
        }
        #pragma unroll
        for (int it = 0; it < 4; it++) {
            int idx = it*256 + t;
            int kk = idx >> 4, d4 = idx & 15;
            *(float4*)(Bs + kk*64 + d4*4) =
                *(const float4*)(fc + ((size_t)p*1024 + k0 + kk)*256 + ot*64 + d4*4);
        }
        __syncthreads();
        #pragma unroll 4
        for (int kk = 0; kk < 64; kk++) {
            float a[4];
            #pragma unroll
            for (int ii = 0; ii < 4; ii++) a[ii] = As[(n0+ii)*68 + kk];
            float4 bv = *(const float4*)(Bs + kk*64 + o0);
            float bj[4] = {bv.x, bv.y, bv.z, bv.w};
            #pragma unroll
            for (int ii = 0; ii < 4; ii++)
                #pragma unroll
                for (int jj = 0; jj < 4; jj++) acc[ii][jj] += a[ii]*bj[jj];
        }
    }
    #pragma unroll
    for (int ii = 0; ii < 4; ii++)
        #pragma unroll
        for (int jj = 0; jj < 4; jj++)
            out[((size_t)(n0+ii)*256 + ot*64 + o0 + jj)*16 + p] = acc[ii][jj];
}

// ------------------------------------------------------------------ launch (fork-join over streams; capture-legal pattern)
extern "C" void kernel_launch(void* const* d_in, const int* in_sizes, int n_in,
                              void* d_out, int out_size) {
    const float* x     = (const float*)d_in[0];
    const float* proto = (const float*)d_in[1];
    const float* Wq    = (const float*)d_in[2];
    const float* bq    = (const float*)d_in[3];
    const float* Wk    = (const float*)d_in[4];
    const float* bk    = (const float*)d_in[5];
    const float* Wv    = (const float*)d_in[6];
    const float* bv    = (const float*)d_in[7];
    const float* Wo    = (const float*)d_in[8];
    const float* bo    = (const float*)d_in[9];
    const float* fc    = (const float*)d_in[10];
    float* out = (float*)d_out;

    cudaFuncSetAttribute(k0_transpose, cudaFuncAttributeMaxDynamicSharedMemorySize, 69632);
    cudaFuncSetAttribute(k1_assign,    cudaFuncAttributeMaxDynamicSharedMemorySize, 73728);
    cudaFuncSetAttribute(k_gemm,       cudaFuncAttributeMaxDynamicSharedMemorySize, GEMM_SMEM);
    cudaFuncSetAttribute(k_attn,       cudaFuncAttributeMaxDynamicSharedMemorySize, ATTN_SMEM);

    cudaStream_t s1, s2;
    cudaStreamCreate(&s1);
    cudaStreamCreate(&s2);
    cudaEvent_t eFork, eW, e0, eK;
    cudaEventCreateWithFlags(&eFork, cudaEventDisableTiming);
    cudaEventCreateWithFlags(&eW,    cudaEventDisableTiming);
    cudaEventCreateWithFlags(&e0,    cudaEventDisableTiming);
    cudaEventCreateWithFlags(&eK,    cudaEventDisableTiming);

    int wtail = (out_size >= NB*CB*PB + NB*SB) ? 1 : 0;

    // fork s1: weight prep runs beside k0
    cudaEventRecord(eFork, 0);
    cudaStreamWaitEvent(s1, eFork, 0);
    k_wprep<<<64, 256, 0, s1>>>(Wq, Wk, Wv, Wo, bq, bk, bv, bo);
    cudaEventRecord(eW, s1);

    k0_transpose<<<dim3(16, 64), 256, 69632>>>(x);
    cudaEventRecord(e0, 0);

    // fork s2: assignment path overlaps gemm0 (both depend only on k0)
    cudaStreamWaitEvent(s2, e0, 0);
    k1_assign<<<NB*PB, 256, (64*257 + 4*257 + 512) * sizeof(float), s2>>>(proto);
    k2_mode<<<16, 256, 0, s2>>>(out, wtail);
    cudaEventRecord(eK, s2);

    cudaStreamWaitEvent(0, eW, 0);
    k_gemm<<<512, 256, GEMM_SMEM>>>(0);                 // QKV projections -> split bf16
    k_attn<<<4096, 128, ATTN_SMEM>>>();                 // HMMA attention core
    cudaStreamWaitEvent(0, eK, 0);                      // join assignment path (g_hidx)
    k_gemm<<<512, 256, GEMM_SMEM>>>(1);                 // O@Wo + residual + pooling
    k4_fc<<<dim3(16, 4), 256>>>(fc, out);

    cudaEventDestroy(eFork);
    cudaEventDestroy(eW);
    cudaEventDestroy(e0);
    cudaEventDestroy(eK);
    cudaStreamDestroy(s1);
    cudaStreamDestroy(s2);
}

// round 11
// speedup vs baseline: 2.6838x; 1.0338x over previous
#include <cuda_runtime.h>
#include <cuda_bf16.h>
#include <math.h>
#include <stdint.h>

#define NB 64
#define CB 256
#define SB 64
#define PB 16
#define KCL 4
#define RT (NB*PB*SB)          // 65536 total rows (b = n*16+p, s)

// ------------------------------------------------------------------ globals
__device__ float         g_xb[(size_t)RT*CB];     // X fp32 (b,s,c) exact
__device__ __nv_bfloat16 g_xh[(size_t)RT*CB];     // X hi
__device__ __nv_bfloat16 g_xl[(size_t)RT*CB];     // X lo
__device__ __nv_bfloat16 g_ph[(size_t)RT*768];    // Q|K|V hi (Q pre-scaled by 1/8)
__device__ __nv_bfloat16 g_pl[(size_t)RT*768];    // Q|K|V lo
__device__ __nv_bfloat16 g_oh[(size_t)RT*CB];     // attn out hi
__device__ __nv_bfloat16 g_ol[(size_t)RT*CB];     // attn out lo
__device__ __nv_bfloat16 g_wh[1024*CB];           // weights hi: rows 0..767 = Wq|Wk|Wv^T, 768..1023 = Wo^T   [n][k]
__device__ __nv_bfloat16 g_wl[1024*CB];           // lo
__device__ float         g_biasv[1024];           // bq|bk|bv|bo
__device__ float         g_clu[PB*NB*KCL*CB];
__device__ unsigned char g_hidx[PB*NB*SB];

// ------------------------------------------------------------------ helpers
__device__ __forceinline__ uint32_t smem_u32(const void* p) {
    uint32_t a;
    asm("{ .reg .u64 t; cvta.to.shared.u64 t, %1; cvt.u32.u64 %0, t; }" : "=r"(a) : "l"(p));
    return a;
}
__device__ __forceinline__ void ldsm4(uint32_t a, uint32_t& r0, uint32_t& r1, uint32_t& r2, uint32_t& r3) {
    asm volatile("ldmatrix.sync.aligned.m8n8.x4.shared.b16 {%0,%1,%2,%3}, [%4];"
        : "=r"(r0), "=r"(r1), "=r"(r2), "=r"(r3) : "r"(a));
}
__device__ __forceinline__ void ldsm4t(uint32_t a, uint32_t& r0, uint32_t& r1, uint32_t& r2, uint32_t& r3) {
    asm volatile("ldmatrix.sync.aligned.m8n8.x4.trans.shared.b16 {%0,%1,%2,%3}, [%4];"
        : "=r"(r0), "=r"(r1), "=r"(r2), "=r"(r3) : "r"(a));
}
__device__ __forceinline__ void mma16816(float* d, const uint32_t* a, uint32_t b0, uint32_t b1) {
    asm volatile("mma.sync.aligned.m16n8k16.row.col.f32.bf16.bf16.f32 "
        "{%0,%1,%2,%3}, {%4,%5,%6,%7}, {%8,%9}, {%0,%1,%2,%3};"
        : "+f"(d[0]), "+f"(d[1]), "+f"(d[2]), "+f"(d[3])
        : "r"(a[0]), "r"(a[1]), "r"(a[2]), "r"(a[3]), "r"(b0), "r"(b1));
}
__device__ __forceinline__ void cp16(uint32_t sa, const void* ga) {
    asm volatile("cp.async.cg.shared.global [%0], [%1], 16;" :: "r"(sa), "l"(ga));
}
__device__ __forceinline__ void split2(float x, float y, uint32_t& hi, uint32_t& lo) {
    __nv_bfloat16 hx = __float2bfloat16(x), hy = __float2bfloat16(y);
    __nv_bfloat16 lx = __float2bfloat16(x - __bfloat162float(hx));
    __nv_bfloat16 ly = __float2bfloat16(y - __bfloat162float(hy));
    __nv_bfloat162 H; H.x = hx; H.y = hy;
    __nv_bfloat162 L; L.x = lx; L.y = ly;
    hi = *(uint32_t*)&H; lo = *(uint32_t*)&L;
}

// ------------------------------------------------------------------ K0: transpose + bf16 split
__global__ __launch_bounds__(256) void k0_transpose(const float* __restrict__ x) {
    extern __shared__ float tile[];          // [(s*16+p)][17]
    const int cchunk = blockIdx.x, n = blockIdx.y;
    const int t = threadIdx.x;
    const int c0 = cchunk * 16;
    #pragma unroll
    for (int it = 0; it < 16; it++) {
        int idx = it * 256 + t;
        int ci = idx >> 8;
        int rem = idx & 255;
        int s = rem >> 2;
        int p4 = rem & 3;
        const float4 v = *(const float4*)(x + (((size_t)n*CB + c0 + ci)*SB + s)*PB + p4*4);
        int base = (s*16 + p4*4)*17 + ci;
        tile[base] = v.x; tile[base+17] = v.y; tile[base+34] = v.z; tile[base+51] = v.w;
    }
    __syncthreads();
    #pragma unroll
    for (int it = 0; it < 8; it++) {
        int idx = it * 256 + t;              // 2048: (s,p,vec8)
        int vec = idx & 1;
        int pr = idx >> 1;
        int s = pr >> 4, p = pr & 15;
        int base = (s*16 + p)*17 + vec*8;
        __align__(16) float f[8];
        __align__(16) __nv_bfloat16 hi[8];
        __align__(16) __nv_bfloat16 lo[8];
        #pragma unroll
        for (int u = 0; u < 8; u++) {
            float v = tile[base + u];
            f[u] = v;
            hi[u] = __float2bfloat16(v);
            lo[u] = __float2bfloat16(v - __bfloat162float(hi[u]));
        }
        size_t off = (((size_t)n*16 + p)*64 + s)*256 + c0 + vec*8;
        *(uint4*)(g_xb + off)     = *(uint4*)f;
        *(uint4*)(g_xb + off + 4) = *(uint4*)(f + 4);
        *(uint4*)(g_xh + off) = *(uint4*)hi;
        *(uint4*)(g_xl + off) = *(uint4*)lo;
    }
}

// ------------------------------------------------------------------ K_wprep: smem-tiled transpose
__global__ __launch_bounds__(256) void k_wprep(
    const float* __restrict__ Wq, const float* __restrict__ Wk,
    const float* __restrict__ Wv, const float* __restrict__ Wo,
    const float* __restrict__ bq, const float* __restrict__ bk,
    const float* __restrict__ bv, const float* __restrict__ bo)
{
    __shared__ float tile[64*68];
    const int bx = blockIdx.x;               // 64 blocks
    const int mat = bx >> 4, tl = bx & 15;
    const int kt = (tl >> 2) << 6, nt = (tl & 3) << 6;
    const float* W = (mat == 0) ? Wq : (mat == 1) ? Wk : (mat == 2) ? Wv : Wo;
    const int t = threadIdx.x;
    #pragma unroll
    for (int it = 0; it < 4; it++) {
        int v = it*256 + t;
        int r = v >> 4, c4 = (v & 15) << 2;
        float4 val = *(const float4*)(W + (size_t)(kt + r)*256 + nt + c4);
        tile[(c4+0)*68 + r] = val.x;
        tile[(c4+1)*68 + r] = val.y;
        tile[(c4+2)*68 + r] = val.z;
        tile[(c4+3)*68 + r] = val.w;
    }
    __syncthreads();
    #pragma unroll
    for (int it = 0; it < 2; it++) {
        int v = it*256 + t;
        int n = v >> 3, k8 = (v & 7) << 3;
        __align__(16) __nv_bfloat16 hi[8];
        __align__(16) __nv_bfloat16 lo[8];
        #pragma unroll
        for (int u = 0; u < 8; u++) {
            float w = tile[n*68 + k8 + u];
            hi[u] = __float2bfloat16(w);
            lo[u] = __float2bfloat16(w - __bfloat162float(hi[u]));
        }
        size_t off = (size_t)(mat*256 + nt + n)*256 + kt + k8;
        *(uint4*)(g_wh + off) = *(uint4*)hi;
        *(uint4*)(g_wl + off) = *(uint4*)lo;
    }
    if (tl == 0) {
        const float* bias = (mat == 0) ? bq : (mat == 1) ? bk : (mat == 2) ? bv : bo;
        g_biasv[mat*256 + t] = bias[t];
    }
}

// ------------------------------------------------------------------ K1: instnorm + argmax assignment
__global__ __launch_bounds__(256) void k1_assign(const float* __restrict__ proto) {
    extern __shared__ float sm1[];
    float* xs = sm1;               // 64*257
    float* pn = xs + 64*257;       // 4*257
    float* mu = pn + 4*257;        // 256
    float* rv = mu + 256;          // 256
    __shared__ float nrm[4];
    const int b = blockIdx.x;
    const int n = b >> 4, p = b & 15;
    const int t = threadIdx.x;

    #pragma unroll
    for (int it = 0; it < 4; it++) {
        int i = it*256 + t; int k = i >> 8; int c = i & 255;
        pn[k*257 + c] = proto[((size_t)p*4 + k)*256 + c];
    }
    __syncthreads();
    if (t < 128) {
        int k = t >> 5, lane = t & 31; float s = 0.f;
        #pragma unroll
        for (int j = 0; j < 8; j++) { float v = pn[k*257 + lane + j*32]; s += v*v; }
        #pragma unroll
        for (int o = 16; o > 0; o >>= 1) s += __shfl_down_sync(0xffffffffu, s, o);
        if (lane == 0) nrm[k] = rsqrtf(s);
    }
    __syncthreads();
    #pragma unroll
    for (int it = 0; it < 4; it++) {
        int i = it*256 + t; int k = i >> 8; int c = i & 255;
        pn[k*257 + c] *= nrm[k];
    }
    const float* xg = g_xb + (size_t)b * SB * CB;
    for (int it = 0; it < 64; it++) {
        int i = it*256 + t; int s = i >> 8; int c = i & 255;
        xs[s*257 + c] = xg[i];
    }
    __syncthreads();
    {
        int c = t; float sum = 0.f;
        #pragma unroll 8
        for (int s = 0; s < 64; s++) sum += xs[s*257 + c];
        float m = sum * (1.f/64.f);
        float sq = 0.f;
        #pragma unroll 8
        for (int s = 0; s < 64; s++) { float d = xs[s*257 + c] - m; sq += d*d; }
        mu[c] = m;
        rv[c] = rsqrtf(sq * (1.f/64.f) + 1e-5f);
    }
    __syncthreads();
    {
        int s = t >> 2, k = t & 3;
        float acc = 0.f;
        #pragma unroll 8
        for (int c = 0; c < 256; c++)
            acc += (xs[s*257 + c] - mu[c]) * rv[c] * pn[k*257 + c];
        float a1 = __shfl_down_sync(0xffffffffu, acc, 1);
        float a2 = __shfl_down_sync(0xffffffffu, acc, 2);
        float a3 = __shfl_down_sync(0xffffffffu, acc, 3);
        if (k == 0) {
            int bi = 0; float bv = acc;
            if (a1 > bv) { bv = a1; bi = 1; }
            if (a2 > bv) { bv = a2; bi = 2; }
            if (a3 > bv) { bv = a3; bi = 3; }
            g_hidx[((size_t)p*64 + n)*64 + s] = (unsigned char)bi;
        }
    }
}

// ------------------------------------------------------------------ K2: mode over parts
__global__ void k2_mode(float* __restrict__ out, int doWrite) {
    int id = blockIdx.x * 256 + threadIdx.x;
    int n = id >> 6, s = id & 63;
    int cnt[4] = {0,0,0,0};
    #pragma unroll
    for (int p = 0; p < 16; p++) cnt[g_hidx[((size_t)p*64 + n)*64 + s]]++;
    int bi = 0, bv = cnt[0];
    if (cnt[1] > bv) { bv = cnt[1]; bi = 1; }
    if (cnt[2] > bv) { bv = cnt[2]; bi = 2; }
    if (cnt[3] > bv) { bv = cnt[3]; bi = 3; }
    if (doWrite) out[NB*CB*PB + id] = (float)bi;
}

// ------------------------------------------------------------------ k_gemm: occupancy-first warp-MMA (2 CTAs/SM)
// K chunked at 32, 2-stage ping-pong; stage = A(hi,lo)+B(hi,lo) @ LDC=40 pitch.
#define KCH 32
#define LDC 40                  // bf16 row pitch: word-stride 20 -> conflict-free ldmatrix
#define CTILE (128*LDC*2)       // 10240 bytes per array
#define STG (4*CTILE)           // 40960
#define GEMM_SMEM (2*STG)       // 81920
#define YLD 132

__device__ __forceinline__ void load_stage(const __nv_bfloat16* __restrict__ Ah,
        const __nv_bfloat16* __restrict__ Al, size_t arow0,
        int brow0, int k0, uint32_t st, int t) {
    #pragma unroll
    for (int it = 0; it < 2; it++) {
        int v = it*256 + t;                  // 512: 128 rows x 4 vec8
        int r = v >> 2, kv = (v & 3) << 3;
        uint32_t so = (uint32_t)(r*LDC + kv)*2;
        size_t aoff = (arow0 + r)*256 + k0 + kv;
        size_t boff = (size_t)(brow0 + r)*256 + k0 + kv;
        cp16(st + so,            Ah + aoff);
        cp16(st + CTILE + so,    Al + aoff);
        cp16(st + 2*CTILE + so,  g_wh + boff);
        cp16(st + 3*CTILE + so,  g_wl + boff);
    }
}

__global__ __launch_bounds__(256, 2) void k_gemm(int mode) {
    extern __shared__ char sm[];
    const uint32_t sb = smem_u32(sm);
    const int t = threadIdx.x;
    const int w = t >> 5, lane = t & 31;
    const int m0 = blockIdx.x * 128;
    const int wy = w >> 1, wx = w & 1;
    const int m_base = wy*32, n_base = wx*64;
    __shared__ unsigned char sidx[128];

    if (mode == 1 && t < 128) {
        int b = (m0 >> 6) + (t >> 6);
        sidx[t] = g_hidx[((size_t)(b & 15)*64 + (b >> 4))*64 + (t & 63)];
    }

    const __nv_bfloat16* Ah_src = (mode == 0) ? g_xh : g_oh;
    const __nv_bfloat16* Al_src = (mode == 0) ? g_xl : g_ol;
    const int NBLK = (mode == 0) ? 6 : 2;
    const int bbase = (mode == 0) ? 0 : 768;

    const int li = lane >> 3, lr = lane & 7;
    const int a_row = (li & 1)*8 + lr, a_kof = (li >> 1)*8;
    const int b_row = (li >> 1)*8 + lr, b_kof = (li & 1)*8;

    float* Ys = (float*)sm;

    for (int nb = 0; nb < NBLK; nb++) {
        const int brow0 = bbase + nb*128;
        __syncthreads();                     // Ys readers / prev-nb consumers done
        load_stage(Ah_src, Al_src, (size_t)m0, brow0, 0, sb, t);
        asm volatile("cp.async.commit_group;" ::: "memory");

        float acc[2][8][4];
        #pragma unroll
        for (int i = 0; i < 2; i++)
            #pragma unroll
            for (int j = 0; j < 8; j++)
                #pragma unroll
                for (int q = 0; q < 4; q++) acc[i][j][q] = 0.f;

        #pragma unroll
        for (int c = 0; c < 8; c++) {
            if (c < 7) {
                load_stage(Ah_src, Al_src, (size_t)m0, brow0, (c + 1)*KCH,
                           sb + ((c + 1) & 1)*STG, t);
                asm volatile("cp.async.commit_group;" ::: "memory");
                asm volatile("cp.async.wait_group 1;" ::: "memory");
            } else {
                asm volatile("cp.async.wait_group 0;" ::: "memory");
            }
            __syncthreads();
            const uint32_t st = sb + (c & 1)*STG;
            #pragma unroll
            for (int ks = 0; ks < 2; ks++) {
                const int kk = ks*16;
                uint32_t ah[2][4], al[2][4];
                #pragma unroll
                for (int mf = 0; mf < 2; mf++) {
                    uint32_t off = (uint32_t)((m_base + mf*16 + a_row)*LDC + kk + a_kof)*2;
                    ldsm4(st + off, ah[mf][0], ah[mf][1], ah[mf][2], ah[mf][3]);
                    ldsm4(st + CTILE + off, al[mf][0], al[mf][1], al[mf][2], al[mf][3]);
                }
                #pragma unroll
                for (int nbf = 0; nbf < 4; nbf++) {
                    uint32_t off = (uint32_t)((n_base + nbf*16 + b_row)*LDC + kk + b_kof)*2;
                    uint32_t bh0, bh1, bh2, bh3, bl0, bl1, bl2, bl3;
                    ldsm4(st + 2*CTILE + off, bh0, bh1, bh2, bh3);
                    ldsm4(st + 3*CTILE + off, bl0, bl1, bl2, bl3);
                    #pragma unroll
                    for (int mf = 0; mf < 2; mf++) {
                        mma16816(acc[mf][nbf*2],     ah[mf], bh0, bh1);
                        mma16816(acc[mf][nbf*2 + 1], ah[mf], bh2, bh3);
                        mma16816(acc[mf][nbf*2],     ah[mf], bl0, bl1);
                        mma16816(acc[mf][nbf*2 + 1], ah[mf], bl2, bl3);
                        mma16816(acc[mf][nbf*2],     al[mf], bh0, bh1);
                        mma16816(acc[mf][nbf*2 + 1], al[mf], bh2, bh3);
                    }
                }
            }
            __syncthreads();                 // stage readers done before overwrite
        }

        // epilogue: accumulators + bias -> Ys (pipeline drained; smem reusable)
        {
            const int mr = lane >> 2, nc = (lane & 3)*2;
            #pragma unroll
            for (int mf = 0; mf < 2; mf++)
                #pragma unroll
                for (int nf = 0; nf < 8; nf++) {
                    int m = m_base + mf*16 + mr;
                    int n = n_base + nf*8 + nc;
                    float b0 = g_biasv[brow0 + n], b1 = g_biasv[brow0 + n + 1];
                    Ys[m*YLD + n]           = acc[mf][nf][0] + b0;
                    Ys[m*YLD + n + 1]       = acc[mf][nf][1] + b1;
                    Ys[(m + 8)*YLD + n]     = acc[mf][nf][2] + b0;
                    Ys[(m + 8)*YLD + n + 1] = acc[mf][nf][3] + b1;
                }
        }
        __syncthreads();

        if (mode == 0) {
            const float qscale = (nb < 2) ? 0.125f : 1.f;
            for (int v = t; v < 2048; v += 256) {       // 128 rows x 16 vec8
                int r = v >> 4, c8 = (v & 15) << 3;
                uint32_t hi4[4], lo4[4];
                #pragma unroll
                for (int u = 0; u < 4; u++) {
                    float fa = Ys[r*YLD + c8 + 2*u]     * qscale;
                    float fb = Ys[r*YLD + c8 + 2*u + 1] * qscale;
                    split2(fa, fb, hi4[u], lo4[u]);
                }
                size_t off = (size_t)(m0 + r)*768 + nb*128 + c8;
                *(uint4*)(g_ph + off) = *(uint4*)hi4;
                *(uint4*)(g_pl + off) = *(uint4*)lo4;
            }
        } else {
            for (int v = t; v < 4096; v += 256) {
                int r = v >> 5, c4 = (v & 31) << 2;
                float4 rx = *(const float4*)(g_xb + (size_t)(m0 + r)*256 + nb*128 + c4);
                Ys[r*YLD + c4]     += rx.x;
                Ys[r*YLD + c4 + 1] += rx.y;
                Ys[r*YLD + c4 + 2] += rx.z;
                Ys[r*YLD + c4 + 3] += rx.w;
            }
            __syncthreads();
            for (int id = t; id < 1024; id += 256) {
                int bl = id >> 9, j = (id >> 7) & 3, c = id & 127;
                float m = -1e30f;
                #pragma unroll 8
                for (int s = 0; s < 64; s++) {
                    float v = (sidx[bl*64 + s] == j) ? Ys[(bl*64 + s)*YLD + c] : 0.f;
                    m = fmaxf(m, v);
                }
                int b = (m0 >> 6) + bl;
                int n = b >> 4, p = b & 15;
                g_clu[((size_t)p*64 + n)*1024 + j*256 + nb*128 + c] = m;
            }
        }
    }
}

// ------------------------------------------------------------------ K_attn: HMMA attention per (b, h), 128 threads
#define LDV 72
#define AT_TILE (64*LDV*2)      // 9216
#define ATTN_SMEM (6*AT_TILE)   // 55296

__global__ __launch_bounds__(128) void k_attn() {
    extern __shared__ char sma[];
    const uint32_t sb = smem_u32(sma);
    const uint32_t sQh = sb, sQl = sb + AT_TILE, sKh = sb + 2*AT_TILE,
                   sKl = sb + 3*AT_TILE, sVh = sb + 4*AT_TILE, sVl = sb + 5*AT_TILE;
    const int bid = blockIdx.x;
    const int b = bid >> 2, h = bid & 3;
    const int t = threadIdx.x;
    const int w = t >> 5, lane = t & 31;
    const size_t rbase = (size_t)b * 64;

    #pragma unroll
    for (int q = 0; q < 3; q++) {
        for (int idx = t; idx < 512; idx += 128) {
            int r = idx >> 3, kv = (idx & 7) << 3;
            size_t go = (rbase + r)*768 + q*256 + h*64 + kv;
            uint32_t so = (uint32_t)(r*LDV + kv)*2;
            cp16(sb + (2*q)*AT_TILE + so,     g_ph + go);
            cp16(sb + (2*q + 1)*AT_TILE + so, g_pl + go);
        }
    }
    asm volatile("cp.async.commit_group;" ::: "memory");
    asm volatile("cp.async.wait_group 0;" ::: "memory");
    __syncthreads();

    const int r0 = w * 16;
    const int li = lane >> 3, lr = lane & 7;
    const int t_row = (li & 1)*8 + lr, t_col = (li >> 1)*8;
    const int b_row = (li >> 1)*8 + lr, b_col = (li & 1)*8;

    float sc[4][8];
    #pragma unroll
    for (int i = 0; i < 4; i++)
        #pragma unroll
        for (int j = 0; j < 8; j++) sc[i][j] = 0.f;

    #pragma unroll
    for (int kb = 0; kb < 4; kb++) {
        uint32_t aoff = (uint32_t)((r0 + t_row)*LDV + kb*16 + t_col)*2;
        uint32_t qh[4], ql[4];
        ldsm4(sQh + aoff, qh[0], qh[1], qh[2], qh[3]);
        ldsm4(sQl + aoff, ql[0], ql[1], ql[2], ql[3]);
        #pragma unroll
        for (int nb = 0; nb < 4; nb++) {
            uint32_t boff = (uint32_t)((nb*16 + b_row)*LDV + kb*16 + b_col)*2;
            uint32_t kh0, kh1, kh2, kh3, kl0, kl1, kl2, kl3;
            ldsm4(sKh + boff, kh0, kh1, kh2, kh3);
            ldsm4(sKl + boff, kl0, kl1, kl2, kl3);
            mma16816(sc[nb],     qh, kh0, kh1);
            mma16816(sc[nb] + 4, qh, kh2, kh3);
            mma16816(sc[nb],     qh, kl0, kl1);
            mma16816(sc[nb] + 4, qh, kl2, kl3);
            mma16816(sc[nb],     ql, kh0, kh1);
            mma16816(sc[nb] + 4, ql, kh2, kh3);
        }
    }

    {
        const int r = lane >> 2, q2 = (lane & 3)*2;
        const int gr0 = r0 + r, gr1 = gr0 + 8;
        float m0 = -1e30f, m1 = -1e30f;
        #pragma unroll
        for (int nb = 0; nb < 4; nb++) {
            int c0 = nb*16 + q2, c8 = c0 + 8;
            if (c0     > gr0) sc[nb][0] = -1e30f;
            if (c0 + 1 > gr0) sc[nb][1] = -1e30f;
            if (c8     > gr0) sc[nb][4] = -1e30f;
            if (c8 + 1 > gr0) sc[nb][5] = -1e30f;
            if (c0     > gr1) sc[nb][2] = -1e30f;
            if (c0 + 1 > gr1) sc[nb][3] = -1e30f;
            if (c8     > gr1) sc[nb][6] = -1e30f;
            if (c8 + 1 > gr1) sc[nb][7] = -1e30f;
            m0 = fmaxf(m0, fmaxf(fmaxf(sc[nb][0], sc[nb][1]), fmaxf(sc[nb][4], sc[nb][5])));
            m1 = fmaxf(m1, fmaxf(fmaxf(sc[nb][2], sc[nb][3]), fmaxf(sc[nb][6], sc[nb][7])));
        }
        #pragma unroll
        for (int o = 1; o < 4; o <<= 1) {
            m0 = fmaxf(m0, __shfl_xor_sync(0xffffffffu, m0, o));
            m1 = fmaxf(m1, __shfl_xor_sync(0xffffffffu, m1, o));
        }
        float s0 = 0.f, s1 = 0.f;
        #pragma unroll
        for (int nb = 0; nb < 4; nb++) {
            sc[nb][0] = __expf(sc[nb][0] - m0); s0 += sc[nb][0];
            sc[nb][1] = __expf(sc[nb][1] - m0); s0 += sc[nb][1];
            sc[nb][4] = __expf(sc[nb][4] - m0); s0 += sc[nb][4];
            sc[nb][5] = __expf(sc[nb][5] - m0); s0 += sc[nb][5];
            sc[nb][2] = __expf(sc[nb][2] - m1); s1 += sc[nb][2];
            sc[nb][3] = __expf(sc[nb][3] - m1); s1 += sc[nb][3];
            sc[nb][6] = __expf(sc[nb][6] - m1); s1 += sc[nb][6];
            sc[nb][7] = __expf(sc[nb][7] - m1); s1 += sc[nb][7];
        }
        #pragma unroll
        for (int o = 1; o < 4; o <<= 1) {
            s0 += __shfl_xor_sync(0xffffffffu, s0, o);
            s1 += __shfl_xor_sync(0xffffffffu, s1, o);
        }
        float i0 = 1.f / s0, i1 = 1.f / s1;
        #pragma unroll
        for (int nb = 0; nb < 4; nb++) {
            sc[nb][0] *= i0; sc[nb][1] *= i0; sc[nb][4] *= i0; sc[nb][5] *= i0;
            sc[nb][2] *= i1; sc[nb][3] *= i1; sc[nb][6] *= i1; sc[nb][7] *= i1;
        }
    }

    float o[4][8];
    #pragma unroll
    for (int i = 0; i < 4; i++)
        #pragma unroll
        for (int j = 0; j < 8; j++) o[i][j] = 0.f;

    #pragma unroll
    for (int kb = 0; kb < 4; kb++) {
        uint32_t ph[4], pl[4];
        split2(sc[kb][0], sc[kb][1], ph[0], pl[0]);
        split2(sc[kb][2], sc[kb][3], ph[1], pl[1]);
        split2(sc[kb][4], sc[kb][5], ph[2], pl[2]);
        split2(sc[kb][6], sc[kb][7], ph[3], pl[3]);
        #pragma unroll
        for (int nbo = 0; nbo < 4; nbo++) {
            uint32_t voff = (uint32_t)((kb*16 + t_row)*LDV + nbo*16 + t_col)*2;
            uint32_t vh0, vh1, vh2, vh3, vl0, vl1, vl2, vl3;
            ldsm4t(sVh + voff, vh0, vh1, vh2, vh3);
            ldsm4t(sVl + voff, vl0, vl1, vl2, vl3);
            mma16816(o[nbo],     ph, vh0, vh1);
            mma16816(o[nbo] + 4, ph, vh2, vh3);
            mma16816(o[nbo],     ph, vl0, vl1);
            mma16816(o[nbo] + 4, ph, vl2, vl3);
            mma16816(o[nbo],     pl, vh0, vh1);
            mma16816(o[nbo] + 4, pl, vh2, vh3);
        }
    }

    {
        const int r = lane >> 2, q2 = (lane & 3)*2;
        const size_t base0 = (rbase + r0 + r)*256 + h*64;
        const size_t base1 = base0 + 8*256;
        #pragma unroll
        for (int nbo = 0; nbo < 4; nbo++) {
            int c = nbo*16 + q2;
            uint32_t hi, lo;
            split2(o[nbo][0], o[nbo][1], hi, lo);
            *(uint32_t*)(g_oh + base0 + c) = hi;     *(uint32_t*)(g_ol + base0 + c) = lo;
            split2(o[nbo][4], o[nbo][5], hi, lo);
            *(uint32_t*)(g_oh + base0 + c + 8) = hi; *(uint32_t*)(g_ol + base0 + c + 8) = lo;
            split2(o[nbo][2], o[nbo][3], hi, lo);
            *(uint32_t*)(g_oh + base1 + c) = hi;     *(uint32_t*)(g_ol + base1 + c) = lo;
            split2(o[nbo][6], o[nbo][7], hi, lo);
            *(uint32_t*)(g_oh + base1 + c + 8) = hi; *(uint32_t*)(g_ol + base1 + c + 8) = lo;
        }
    }
}

// ------------------------------------------------------------------ K4: per-part FC  out[n,o,p]
__global__ __launch_bounds__(256) void k4_fc(const float* __restrict__ fc, float* __restrict__ out) {
    __shared__ float As[64*68];
    __shared__ float Bs[64*64];
    const int p = blockIdx.x, ot = blockIdx.y;
    const int t = threadIdx.x;
    const int tx = t & 15, ty = t >> 4;
    const int o0 = tx*4, n0 = ty*4;
    float acc[4][4] = {};
    for (int k0 = 0; k0 < 1024; k0 += 64) {
        __syncthreads();
        #pragma unroll
        for (int it = 0; it < 4; it++) {
            int idx = it*256 + t;
            int nn = idx >> 4, k4 = idx & 15;
            *(float4*)(As + nn*68 + k4*4) =
                *(const float4*)(g_clu + ((size_t)p*64 + nn)*1024 + k0 + k4*4);
        }
        #pragma unroll
        for (int it = 0; it < 4; it++) {
            int idx = it*256 + t;
            int kk = idx >> 4, d4 = idx & 15;
            *(float4*)(Bs + kk*64 + d4*4) =
                *(const float4*)(fc + ((size_t)p*1024 + k0 + kk)*256 + ot*64 + d4*4);
        }
        __syncthreads();
        #pragma unroll 4
        for (int kk = 0; kk < 64; kk++) {
            float a[4];
            #pragma unroll
            for (int ii = 0; ii < 4; ii++) a[ii] = As[(n0+ii)*68 + kk];
            float4 bv = *(const float4*)(Bs + kk*64 + o0);
            float bj[4] = {bv.x, bv.y, bv.z, bv.w};
            #pragma unroll
            for (int ii = 0; ii < 4; ii++)
                #pragma unroll
                for (int jj = 0; jj < 4; jj++) acc[ii][jj] += a[ii]*bj[jj];
        }
    }
    #pragma unroll
    for (int ii = 0; ii < 4; ii++)
        #pragma unroll
        for (int jj = 0; jj < 4; jj++)
            out[((size_t)(n0+ii)*256 + ot*64 + o0 + jj)*16 + p] = acc[ii][jj];
}

// ------------------------------------------------------------------ launch (fork-join over streams)
extern "C" void kernel_launch(void* const* d_in, const int* in_sizes, int n_in,
                              void* d_out, int out_size) {
    const float* x     = (const float*)d_in[0];
    const float* proto = (const float*)d_in[1];
    const float* Wq    = (const float*)d_in[2];
    const float* bq    = (const float*)d_in[3];
    const float* Wk    = (const float*)d_in[4];
    const float* bk    = (const float*)d_in[5];
    const float* Wv    = (const float*)d_in[6];
    const float* bv    = (const float*)d_in[7];
    const float* Wo    = (const float*)d_in[8];
    const float* bo    = (const float*)d_in[9];
    const float* fc    = (const float*)d_in[10];
    float* out = (float*)d_out;

    cudaFuncSetAttribute(k0_transpose, cudaFuncAttributeMaxDynamicSharedMemorySize, 69632);
    cudaFuncSetAttribute(k1_assign,    cudaFuncAttributeMaxDynamicSharedMemorySize, 73728);
    cudaFuncSetAttribute(k_gemm,       cudaFuncAttributeMaxDynamicSharedMemorySize, GEMM_SMEM);
    cudaFuncSetAttribute(k_attn,       cudaFuncAttributeMaxDynamicSharedMemorySize, ATTN_SMEM);

    cudaStream_t s1, s2;
    cudaStreamCreate(&s1);
    cudaStreamCreate(&s2);
    cudaEvent_t eFork, eW, e0, eK;
    cudaEventCreateWithFlags(&eFork, cudaEventDisableTiming);
    cudaEventCreateWithFlags(&eW,    cudaEventDisableTiming);
    cudaEventCreateWithFlags(&e0,    cudaEventDisableTiming);
    cudaEventCreateWithFlags(&eK,    cudaEventDisableTiming);

    int wtail = (out_size >= NB*CB*PB + NB*SB) ? 1 : 0;

    cudaEventRecord(eFork, 0);
    cudaStreamWaitEvent(s1, eFork, 0);
    k_wprep<<<64, 256, 0, s1>>>(Wq, Wk, Wv, Wo, bq, bk, bv, bo);
    cudaEventRecord(eW, s1);

    k0_transpose<<<dim3(16, 64), 256, 69632>>>(x);
    cudaEventRecord(e0, 0);

    cudaStreamWaitEvent(s2, e0, 0);
    k1_assign<<<NB*PB, 256, (64*257 + 4*257 + 512) * sizeof(float), s2>>>(proto);
    k2_mode<<<16, 256, 0, s2>>>(out, wtail);
    cudaEventRecord(eK, s2);

    cudaStreamWaitEvent(0, eW, 0);
    k_gemm<<<512, 256, GEMM_SMEM>>>(0);                 // QKV projections -> split bf16
    k_attn<<<4096, 128, ATTN_SMEM>>>();                 // HMMA attention core
    cudaStreamWaitEvent(0, eK, 0);                      // join assignment path (g_hidx)
    k_gemm<<<512, 256, GEMM_SMEM>>>(1);                 // O@Wo + residual + pooling
    k4_fc<<<dim3(16, 4), 256>>>(fc, out);

    cudaEventDestroy(eFork);
    cudaEventDestroy(eW);
    cudaEventDestroy(e0);
    cudaEventDestroy(eK);
    cudaStreamDestroy(s1);
    cudaStreamDestroy(s2);
}

// round 12
// speedup vs baseline: 2.7672x; 1.0311x over previous
#include <cuda_runtime.h>
#include <cuda_bf16.h>
#include <math.h>
#include <stdint.h>

#define NB 64
#define CB 256
#define SB 64
#define PB 16
#define KCL 4
#define RT (NB*PB*SB)          // 65536 total rows (b = n*16+p, s)

// ------------------------------------------------------------------ globals
__device__ float         g_xb[(size_t)RT*CB];     // X fp32 (b,s,c) exact
__device__ __nv_bfloat16 g_xh[(size_t)RT*CB];     // X hi
__device__ __nv_bfloat16 g_xl[(size_t)RT*CB];     // X lo
__device__ __nv_bfloat16 g_ph[(size_t)RT*768];    // Q|K|V hi (Q pre-scaled by 1/8)
__device__ __nv_bfloat16 g_pl[(size_t)RT*768];    // Q|K|V lo
__device__ __nv_bfloat16 g_oh[(size_t)RT*CB];     // attn out hi
__device__ __nv_bfloat16 g_ol[(size_t)RT*CB];     // attn out lo
__device__ __nv_bfloat16 g_wh[1024*CB];           // weights hi: rows 0..767 = Wq|Wk|Wv^T, 768..1023 = Wo^T   [n][k]
__device__ __nv_bfloat16 g_wl[1024*CB];           // lo
__device__ float         g_biasv[1024];           // bq|bk|bv|bo
__device__ float         g_clu[PB*NB*KCL*CB];
__device__ unsigned char g_hidx[PB*NB*SB];

// ------------------------------------------------------------------ helpers
__device__ __forceinline__ uint32_t smem_u32(const void* p) {
    uint32_t a;
    asm("{ .reg .u64 t; cvta.to.shared.u64 t, %1; cvt.u32.u64 %0, t; }" : "=r"(a) : "l"(p));
    return a;
}
__device__ __forceinline__ void ldsm4(uint32_t a, uint32_t& r0, uint32_t& r1, uint32_t& r2, uint32_t& r3) {
    asm volatile("ldmatrix.sync.aligned.m8n8.x4.shared.b16 {%0,%1,%2,%3}, [%4];"
        : "=r"(r0), "=r"(r1), "=r"(r2), "=r"(r3) : "r"(a));
}
__device__ __forceinline__ void ldsm4t(uint32_t a, uint32_t& r0, uint32_t& r1, uint32_t& r2, uint32_t& r3) {
    asm volatile("ldmatrix.sync.aligned.m8n8.x4.trans.shared.b16 {%0,%1,%2,%3}, [%4];"
        : "=r"(r0), "=r"(r1), "=r"(r2), "=r"(r3) : "r"(a));
}
__device__ __forceinline__ void mma16816(float* d, const uint32_t* a, uint32_t b0, uint32_t b1) {
    asm volatile("mma.sync.aligned.m16n8k16.row.col.f32.bf16.bf16.f32 "
        "{%0,%1,%2,%3}, {%4,%5,%6,%7}, {%8,%9}, {%0,%1,%2,%3};"
        : "+f"(d[0]), "+f"(d[1]), "+f"(d[2]), "+f"(d[3])
        : "r"(a[0]), "r"(a[1]), "r"(a[2]), "r"(a[3]), "r"(b0), "r"(b1));
}
__device__ __forceinline__ void cp16(uint32_t sa, const void* ga) {
    asm volatile("cp.async.cg.shared.global [%0], [%1], 16;" :: "r"(sa), "l"(ga));
}
__device__ __forceinline__ void split2(float x, float y, uint32_t& hi, uint32_t& lo) {
    __nv_bfloat16 hx = __float2bfloat16(x), hy = __float2bfloat16(y);
    __nv_bfloat16 lx = __float2bfloat16(x - __bfloat162float(hx));
    __nv_bfloat16 ly = __float2bfloat16(y - __bfloat162float(hy));
    __nv_bfloat162 H; H.x = hx; H.y = hy;
    __nv_bfloat162 L; L.x = lx; L.y = ly;
    hi = *(uint32_t*)&H; lo = *(uint32_t*)&L;
}

// ------------------------------------------------------------------ K0: transpose + bf16 split
__global__ __launch_bounds__(256) void k0_transpose(const float* __restrict__ x) {
    extern __shared__ float tile[];          // [(s*16+p)][17]
    const int cchunk = blockIdx.x, n = blockIdx.y;
    const int t = threadIdx.x;
    const int c0 = cchunk * 16;
    #pragma unroll
    for (int it = 0; it < 16; it++) {
        int idx = it * 256 + t;
        int ci = idx >> 8;
        int rem = idx & 255;
        int s = rem >> 2;
        int p4 = rem & 3;
        const float4 v = *(const float4*)(x + (((size_t)n*CB + c0 + ci)*SB + s)*PB + p4*4);
        int base = (s*16 + p4*4)*17 + ci;
        tile[base] = v.x; tile[base+17] = v.y; tile[base+34] = v.z; tile[base+51] = v.w;
    }
    __syncthreads();
    #pragma unroll
    for (int it = 0; it < 8; it++) {
        int idx = it * 256 + t;              // 2048: (s,p,vec8)
        int vec = idx & 1;
        int pr = idx >> 1;
        int s = pr >> 4, p = pr & 15;
        int base = (s*16 + p)*17 + vec*8;
        __align__(16) float f[8];
        __align__(16) __nv_bfloat16 hi[8];
        __align__(16) __nv_bfloat16 lo[8];
        #pragma unroll
        for (int u = 0; u < 8; u++) {
            float v = tile[base + u];
            f[u] = v;
            hi[u] = __float2bfloat16(v);
            lo[u] = __float2bfloat16(v - __bfloat162float(hi[u]));
        }
        size_t off = (((size_t)n*16 + p)*64 + s)*256 + c0 + vec*8;
        *(uint4*)(g_xb + off)     = *(uint4*)f;
        *(uint4*)(g_xb + off + 4) = *(uint4*)(f + 4);
        *(uint4*)(g_xh + off) = *(uint4*)hi;
        *(uint4*)(g_xl + off) = *(uint4*)lo;
    }
}

// ------------------------------------------------------------------ K_wprep: smem-tiled transpose
__global__ __launch_bounds__(256) void k_wprep(
    const float* __restrict__ Wq, const float* __restrict__ Wk,
    const float* __restrict__ Wv, const float* __restrict__ Wo,
    const float* __restrict__ bq, const float* __restrict__ bk,
    const float* __restrict__ bv, const float* __restrict__ bo)
{
    __shared__ float tile[64*68];
    const int bx = blockIdx.x;               // 64 blocks
    const int mat = bx >> 4, tl = bx & 15;
    const int kt = (tl >> 2) << 6, nt = (tl & 3) << 6;
    const float* W = (mat == 0) ? Wq : (mat == 1) ? Wk : (mat == 2) ? Wv : Wo;
    const int t = threadIdx.x;
    #pragma unroll
    for (int it = 0; it < 4; it++) {
        int v = it*256 + t;
        int r = v >> 4, c4 = (v & 15) << 2;
        float4 val = *(const float4*)(W + (size_t)(kt + r)*256 + nt + c4);
        tile[(c4+0)*68 + r] = val.x;
        tile[(c4+1)*68 + r] = val.y;
        tile[(c4+2)*68 + r] = val.z;
        tile[(c4+3)*68 + r] = val.w;
    }
    __syncthreads();
    #pragma unroll
    for (int it = 0; it < 2; it++) {
        int v = it*256 + t;
        int n = v >> 3, k8 = (v & 7) << 3;
        __align__(16) __nv_bfloat16 hi[8];
        __align__(16) __nv_bfloat16 lo[8];
        #pragma unroll
        for (int u = 0; u < 8; u++) {
            float w = tile[n*68 + k8 + u];
            hi[u] = __float2bfloat16(w);
            lo[u] = __float2bfloat16(w - __bfloat162float(hi[u]));
        }
        size_t off = (size_t)(mat*256 + nt + n)*256 + kt + k8;
        *(uint4*)(g_wh + off) = *(uint4*)hi;
        *(uint4*)(g_wl + off) = *(uint4*)lo;
    }
    if (tl == 0) {
        const float* bias = (mat == 0) ? bq : (mat == 1) ? bk : (mat == 2) ? bv : bo;
        g_biasv[mat*256 + t] = bias[t];
    }
}

// ------------------------------------------------------------------ K1: instnorm + argmax assignment
__global__ __launch_bounds__(256) void k1_assign(const float* __restrict__ proto) {
    extern __shared__ float sm1[];
    float* xs = sm1;               // 64*257
    float* pn = xs + 64*257;       // 4*257
    float* mu = pn + 4*257;        // 256
    float* rv = mu + 256;          // 256
    __shared__ float nrm[4];
    const int b = blockIdx.x;
    const int n = b >> 4, p = b & 15;
    const int t = threadIdx.x;

    #pragma unroll
    for (int it = 0; it < 4; it++) {
        int i = it*256 + t; int k = i >> 8; int c = i & 255;
        pn[k*257 + c] = proto[((size_t)p*4 + k)*256 + c];
    }
    __syncthreads();
    if (t < 128) {
        int k = t >> 5, lane = t & 31; float s = 0.f;
        #pragma unroll
        for (int j = 0; j < 8; j++) { float v = pn[k*257 + lane + j*32]; s += v*v; }
        #pragma unroll
        for (int o = 16; o > 0; o >>= 1) s += __shfl_down_sync(0xffffffffu, s, o);
        if (lane == 0) nrm[k] = rsqrtf(s);
    }
    __syncthreads();
    #pragma unroll
    for (int it = 0; it < 4; it++) {
        int i = it*256 + t; int k = i >> 8; int c = i & 255;
        pn[k*257 + c] *= nrm[k];
    }
    const float* xg = g_xb + (size_t)b * SB * CB;
    for (int it = 0; it < 64; it++) {
        int i = it*256 + t; int s = i >> 8; int c = i & 255;
        xs[s*257 + c] = xg[i];
    }
    __syncthreads();
    {
        int c = t; float sum = 0.f;
        #pragma unroll 8
        for (int s = 0; s < 64; s++) sum += xs[s*257 + c];
        float m = sum * (1.f/64.f);
        float sq = 0.f;
        #pragma unroll 8
        for (int s = 0; s < 64; s++) { float d = xs[s*257 + c] - m; sq += d*d; }
        mu[c] = m;
        rv[c] = rsqrtf(sq * (1.f/64.f) + 1e-5f);
    }
    __syncthreads();
    {
        int s = t >> 2, k = t & 3;
        float acc = 0.f;
        #pragma unroll 8
        for (int c = 0; c < 256; c++)
            acc += (xs[s*257 + c] - mu[c]) * rv[c] * pn[k*257 + c];
        float a1 = __shfl_down_sync(0xffffffffu, acc, 1);
        float a2 = __shfl_down_sync(0xffffffffu, acc, 2);
        float a3 = __shfl_down_sync(0xffffffffu, acc, 3);
        if (k == 0) {
            int bi = 0; float bv = acc;
            if (a1 > bv) { bv = a1; bi = 1; }
            if (a2 > bv) { bv = a2; bi = 2; }
            if (a3 > bv) { bv = a3; bi = 3; }
            g_hidx[((size_t)p*64 + n)*64 + s] = (unsigned char)bi;
        }
    }
}

// ------------------------------------------------------------------ K2: mode over parts
__global__ void k2_mode(float* __restrict__ out, int doWrite) {
    int id = blockIdx.x * 256 + threadIdx.x;
    int n = id >> 6, s = id & 63;
    int cnt[4] = {0,0,0,0};
    #pragma unroll
    for (int p = 0; p < 16; p++) cnt[g_hidx[((size_t)p*64 + n)*64 + s]]++;
    int bi = 0, bv = cnt[0];
    if (cnt[1] > bv) { bv = cnt[1]; bi = 1; }
    if (cnt[2] > bv) { bv = cnt[2]; bi = 2; }
    if (cnt[3] > bv) { bv = cnt[3]; bi = 3; }
    if (doWrite) out[NB*CB*PB + id] = (float)bi;
}

// ------------------------------------------------------------------ k_gemm: occupancy-first warp-MMA (2 CTAs/SM)
#define KCH 32
#define LDC 40
#define CTILE (128*LDC*2)       // 10240 bytes per array
#define STG (4*CTILE)           // 40960
#define GEMM_SMEM (2*STG)       // 81920
#define YLD 132

__device__ __forceinline__ void load_stage(const __nv_bfloat16* __restrict__ Ah,
        const __nv_bfloat16* __restrict__ Al, size_t arow0,
        int brow0, int k0, uint32_t st, int t) {
    #pragma unroll
    for (int it = 0; it < 2; it++) {
        int v = it*256 + t;                  // 512: 128 rows x 4 vec8
        int r = v >> 2, kv = (v & 3) << 3;
        uint32_t so = (uint32_t)(r*LDC + kv)*2;
        size_t aoff = (arow0 + r)*256 + k0 + kv;
        size_t boff = (size_t)(brow0 + r)*256 + k0 + kv;
        cp16(st + so,            Ah + aoff);
        cp16(st + CTILE + so,    Al + aoff);
        cp16(st + 2*CTILE + so,  g_wh + boff);
        cp16(st + 3*CTILE + so,  g_wl + boff);
    }
}

__global__ __launch_bounds__(256, 2) void k_gemm(int mode, int mbase) {
    extern __shared__ char sm[];
    const uint32_t sb = smem_u32(sm);
    const int t = threadIdx.x;
    const int w = t >> 5, lane = t & 31;
    const int m0 = (mbase + blockIdx.x) * 128;
    const int wy = w >> 1, wx = w & 1;
    const int m_base = wy*32, n_base = wx*64;
    __shared__ unsigned char sidx[128];

    if (mode == 1 && t < 128) {
        int b = (m0 >> 6) + (t >> 6);
        sidx[t] = g_hidx[((size_t)(b & 15)*64 + (b >> 4))*64 + (t & 63)];
    }

    const __nv_bfloat16* Ah_src = (mode == 0) ? g_xh : g_oh;
    const __nv_bfloat16* Al_src = (mode == 0) ? g_xl : g_ol;
    const int NBLK = (mode == 0) ? 6 : 2;
    const int bbase = (mode == 0) ? 0 : 768;

    const int li = lane >> 3, lr = lane & 7;
    const int a_row = (li & 1)*8 + lr, a_kof = (li >> 1)*8;
    const int b_row = (li >> 1)*8 + lr, b_kof = (li & 1)*8;

    float* Ys = (float*)sm;

    for (int nb = 0; nb < NBLK; nb++) {
        const int brow0 = bbase + nb*128;
        __syncthreads();
        load_stage(Ah_src, Al_src, (size_t)m0, brow0, 0, sb, t);
        asm volatile("cp.async.commit_group;" ::: "memory");

        float acc[2][8][4];
        #pragma unroll
        for (int i = 0; i < 2; i++)
            #pragma unroll
            for (int j = 0; j < 8; j++)
                #pragma unroll
                for (int q = 0; q < 4; q++) acc[i][j][q] = 0.f;

        #pragma unroll
        for (int c = 0; c < 8; c++) {
            if (c < 7) {
                load_stage(Ah_src, Al_src, (size_t)m0, brow0, (c + 1)*KCH,
                           sb + ((c + 1) & 1)*STG, t);
                asm volatile("cp.async.commit_group;" ::: "memory");
                asm volatile("cp.async.wait_group 1;" ::: "memory");
            } else {
                asm volatile("cp.async.wait_group 0;" ::: "memory");
            }
            __syncthreads();
            const uint32_t st = sb + (c & 1)*STG;
            #pragma unroll
            for (int ks = 0; ks < 2; ks++) {
                const int kk = ks*16;
                uint32_t ah[2][4], al[2][4];
                #pragma unroll
                for (int mf = 0; mf < 2; mf++) {
                    uint32_t off = (uint32_t)((m_base + mf*16 + a_row)*LDC + kk + a_kof)*2;
                    ldsm4(st + off, ah[mf][0], ah[mf][1], ah[mf][2], ah[mf][3]);
                    ldsm4(st + CTILE + off, al[mf][0], al[mf][1], al[mf][2], al[mf][3]);
                }
                #pragma unroll
                for (int nbf = 0; nbf < 4; nbf++) {
                    uint32_t off = (uint32_t)((n_base + nbf*16 + b_row)*LDC + kk + b_kof)*2;
                    uint32_t bh0, bh1, bh2, bh3, bl0, bl1, bl2, bl3;
                    ldsm4(st + 2*CTILE + off, bh0, bh1, bh2, bh3);
                    ldsm4(st + 3*CTILE + off, bl0, bl1, bl2, bl3);
                    #pragma unroll
                    for (int mf = 0; mf < 2; mf++) {
                        mma16816(acc[mf][nbf*2],     ah[mf], bh0, bh1);
                        mma16816(acc[mf][nbf*2 + 1], ah[mf], bh2, bh3);
                        mma16816(acc[mf][nbf*2],     ah[mf], bl0, bl1);
                        mma16816(acc[mf][nbf*2 + 1], ah[mf], bl2, bl3);
                        mma16816(acc[mf][nbf*2],     al[mf], bh0, bh1);
                        mma16816(acc[mf][nbf*2 + 1], al[mf], bh2, bh3);
                    }
                }
            }
            __syncthreads();
        }

        {
            const int mr = lane >> 2, nc = (lane & 3)*2;
            #pragma unroll
            for (int mf = 0; mf < 2; mf++)
                #pragma unroll
                for (int nf = 0; nf < 8; nf++) {
                    int m = m_base + mf*16 + mr;
                    int n = n_base + nf*8 + nc;
                    float b0 = g_biasv[brow0 + n], b1 = g_biasv[brow0 + n + 1];
                    Ys[m*YLD + n]           = acc[mf][nf][0] + b0;
                    Ys[m*YLD + n + 1]       = acc[mf][nf][1] + b1;
                    Ys[(m + 8)*YLD + n]     = acc[mf][nf][2] + b0;
                    Ys[(m + 8)*YLD + n + 1] = acc[mf][nf][3] + b1;
                }
        }
        __syncthreads();

        if (mode == 0) {
            const float qscale = (nb < 2) ? 0.125f : 1.f;
            for (int v = t; v < 2048; v += 256) {       // 128 rows x 16 vec8
                int r = v >> 4, c8 = (v & 15) << 3;
                uint32_t hi4[4], lo4[4];
                #pragma unroll
                for (int u = 0; u < 4; u++) {
                    float fa = Ys[r*YLD + c8 + 2*u]     * qscale;
                    float fb = Ys[r*YLD + c8 + 2*u + 1] * qscale;
                    split2(fa, fb, hi4[u], lo4[u]);
                }
                size_t off = (size_t)(m0 + r)*768 + nb*128 + c8;
                *(uint4*)(g_ph + off) = *(uint4*)hi4;
                *(uint4*)(g_pl + off) = *(uint4*)lo4;
            }
        } else {
            for (int v = t; v < 4096; v += 256) {
                int r = v >> 5, c4 = (v & 31) << 2;
                float4 rx = *(const float4*)(g_xb + (size_t)(m0 + r)*256 + nb*128 + c4);
                Ys[r*YLD + c4]     += rx.x;
                Ys[r*YLD + c4 + 1] += rx.y;
                Ys[r*YLD + c4 + 2] += rx.z;
                Ys[r*YLD + c4 + 3] += rx.w;
            }
            __syncthreads();
            for (int id = t; id < 1024; id += 256) {
                int bl = id >> 9, j = (id >> 7) & 3, c = id & 127;
                float m = -1e30f;
                #pragma unroll 8
                for (int s = 0; s < 64; s++) {
                    float v = (sidx[bl*64 + s] == j) ? Ys[(bl*64 + s)*YLD + c] : 0.f;
                    m = fmaxf(m, v);
                }
                int b = (m0 >> 6) + bl;
                int n = b >> 4, p = b & 15;
                g_clu[((size_t)p*64 + n)*1024 + j*256 + nb*128 + c] = m;
            }
        }
    }
}

// ------------------------------------------------------------------ K_attn: HMMA attention per (b, h), 128 threads
// smem 4 tiles: Q(hi,lo)+K(hi,lo); V(hi,lo) reuses Q region after scores.
#define LDV 72
#define AT_TILE (64*LDV*2)      // 9216
#define ATTN_SMEM (4*AT_TILE)   // 36864

__global__ __launch_bounds__(128) void k_attn(int boff) {
    extern __shared__ char sma[];
    const uint32_t sb = smem_u32(sma);
    const uint32_t sQh = sb, sQl = sb + AT_TILE, sKh = sb + 2*AT_TILE, sKl = sb + 3*AT_TILE;
    const uint32_t sVh = sb, sVl = sb + AT_TILE;      // reuse Q region
    const int bid = blockIdx.x + boff;
    const int b = bid >> 2, h = bid & 3;
    const int t = threadIdx.x;
    const int w = t >> 5, lane = t & 31;
    const size_t rbase = (size_t)b * 64;

    // load split Q,K tiles
    #pragma unroll
    for (int q = 0; q < 2; q++) {
        for (int idx = t; idx < 512; idx += 128) {
            int r = idx >> 3, kv = (idx & 7) << 3;
            size_t go = (rbase + r)*768 + q*256 + h*64 + kv;
            uint32_t so = (uint32_t)(r*LDV + kv)*2;
            cp16(sb + (2*q)*AT_TILE + so,     g_ph + go);
            cp16(sb + (2*q + 1)*AT_TILE + so, g_pl + go);
        }
    }
    asm volatile("cp.async.commit_group;" ::: "memory");
    asm volatile("cp.async.wait_group 0;" ::: "memory");
    __syncthreads();

    const int r0 = w * 16;
    const int li = lane >> 3, lr = lane & 7;
    const int t_row = (li & 1)*8 + lr, t_col = (li >> 1)*8;
    const int b_row = (li >> 1)*8 + lr, b_col = (li & 1)*8;

    // ---- scores = (Q/8) K^T (3-term split) ----
    float sc[4][8];
    #pragma unroll
    for (int i = 0; i < 4; i++)
        #pragma unroll
        for (int j = 0; j < 8; j++) sc[i][j] = 0.f;

    #pragma unroll
    for (int kb = 0; kb < 4; kb++) {
        uint32_t aoff = (uint32_t)((r0 + t_row)*LDV + kb*16 + t_col)*2;
        uint32_t qh[4], ql[4];
        ldsm4(sQh + aoff, qh[0], qh[1], qh[2], qh[3]);
        ldsm4(sQl + aoff, ql[0], ql[1], ql[2], ql[3]);
        #pragma unroll
        for (int nb = 0; nb < 4; nb++) {
            uint32_t boff2 = (uint32_t)((nb*16 + b_row)*LDV + kb*16 + b_col)*2;
            uint32_t kh0, kh1, kh2, kh3, kl0, kl1, kl2, kl3;
            ldsm4(sKh + boff2, kh0, kh1, kh2, kh3);
            ldsm4(sKl + boff2, kl0, kl1, kl2, kl3);
            mma16816(sc[nb],     qh, kh0, kh1);
            mma16816(sc[nb] + 4, qh, kh2, kh3);
            mma16816(sc[nb],     qh, kl0, kl1);
            mma16816(sc[nb] + 4, qh, kl2, kl3);
            mma16816(sc[nb],     ql, kh0, kh1);
            mma16816(sc[nb] + 4, ql, kh2, kh3);
        }
    }
    __syncthreads();                         // all warps done reading Q (V overwrites it)

    // issue V load now; softmax (register-only) hides the latency
    for (int idx = t; idx < 512; idx += 128) {
        int r = idx >> 3, kv = (idx & 7) << 3;
        size_t go = (rbase + r)*768 + 2*256 + h*64 + kv;
        uint32_t so = (uint32_t)(r*LDV + kv)*2;
        cp16(sVh + so, g_ph + go);
        cp16(sVl + so, g_pl + go);
    }
    asm volatile("cp.async.commit_group;" ::: "memory");

    // ---- causal softmax in registers ----
    {
        const int r = lane >> 2, q2 = (lane & 3)*2;
        const int gr0 = r0 + r, gr1 = gr0 + 8;
        float m0 = -1e30f, m1 = -1e30f;
        #pragma unroll
        for (int nb = 0; nb < 4; nb++) {
            int c0 = nb*16 + q2, c8 = c0 + 8;
            if (c0     > gr0) sc[nb][0] = -1e30f;
            if (c0 + 1 > gr0) sc[nb][1] = -1e30f;
            if (c8     > gr0) sc[nb][4] = -1e30f;
            if (c8 + 1 > gr0) sc[nb][5] = -1e30f;
            if (c0     > gr1) sc[nb][2] = -1e30f;
            if (c0 + 1 > gr1) sc[nb][3] = -1e30f;
            if (c8     > gr1) sc[nb][6] = -1e30f;
            if (c8 + 1 > gr1) sc[nb][7] = -1e30f;
            m0 = fmaxf(m0, fmaxf(fmaxf(sc[nb][0], sc[nb][1]), fmaxf(sc[nb][4], sc[nb][5])));
            m1 = fmaxf(m1, fmaxf(fmaxf(sc[nb][2], sc[nb][3]), fmaxf(sc[nb][6], sc[nb][7])));
        }
        #pragma unroll
        for (int o = 1; o < 4; o <<= 1) {
            m0 = fmaxf(m0, __shfl_xor_sync(0xffffffffu, m0, o));
            m1 = fmaxf(m1, __shfl_xor_sync(0xffffffffu, m1, o));
        }
        float s0 = 0.f, s1 = 0.f;
        #pragma unroll
        for (int nb = 0; nb < 4; nb++) {
            sc[nb][0] = __expf(sc[nb][0] - m0); s0 += sc[nb][0];
            sc[nb][1] = __expf(sc[nb][1] - m0); s0 += sc[nb][1];
            sc[nb][4] = __expf(sc[nb][4] - m0); s0 += sc[nb][4];
            sc[nb][5] = __expf(sc[nb][5] - m0); s0 += sc[nb][5];
            sc[nb][2] = __expf(sc[nb][2] - m1); s1 += sc[nb][2];
            sc[nb][3] = __expf(sc[nb][3] - m1); s1 += sc[nb][3];
            sc[nb][6] = __expf(sc[nb][6] - m1); s1 += sc[nb][6];
            sc[nb][7] = __expf(sc[nb][7] - m1); s1 += sc[nb][7];
        }
        #pragma unroll
        for (int o = 1; o < 4; o <<= 1) {
            s0 += __shfl_xor_sync(0xffffffffu, s0, o);
            s1 += __shfl_xor_sync(0xffffffffu, s1, o);
        }
        float i0 = 1.f / s0, i1 = 1.f / s1;
        #pragma unroll
        for (int nb = 0; nb < 4; nb++) {
            sc[nb][0] *= i0; sc[nb][1] *= i0; sc[nb][4] *= i0; sc[nb][5] *= i0;
            sc[nb][2] *= i1; sc[nb][3] *= i1; sc[nb][6] *= i1; sc[nb][7] *= i1;
        }
    }

    asm volatile("cp.async.wait_group 0;" ::: "memory");
    __syncthreads();                         // V tiles ready

    // ---- O = P V ----
    float o[4][8];
    #pragma unroll
    for (int i = 0; i < 4; i++)
        #pragma unroll
        for (int j = 0; j < 8; j++) o[i][j] = 0.f;

    #pragma unroll
    for (int kb = 0; kb < 4; kb++) {
        uint32_t ph[4], pl[4];
        split2(sc[kb][0], sc[kb][1], ph[0], pl[0]);
        split2(sc[kb][2], sc[kb][3], ph[1], pl[1]);
        split2(sc[kb][4], sc[kb][5], ph[2], pl[2]);
        split2(sc[kb][6], sc[kb][7], ph[3], pl[3]);
        #pragma unroll
        for (int nbo = 0; nbo < 4; nbo++) {
            uint32_t voff = (uint32_t)((kb*16 + t_row)*LDV + nbo*16 + t_col)*2;
            uint32_t vh0, vh1, vh2, vh3, vl0, vl1, vl2, vl3;
            ldsm4t(sVh + voff, vh0, vh1, vh2, vh3);
            ldsm4t(sVl + voff, vl0, vl1, vl2, vl3);
            mma16816(o[nbo],     ph, vh0, vh1);
            mma16816(o[nbo] + 4, ph, vh2, vh3);
            mma16816(o[nbo],     ph, vl0, vl1);
            mma16816(o[nbo] + 4, ph, vl2, vl3);
            mma16816(o[nbo],     pl, vh0, vh1);
            mma16816(o[nbo] + 4, pl, vh2, vh3);
        }
    }

    {
        const int r = lane >> 2, q2 = (lane & 3)*2;
        const size_t base0 = (rbase + r0 + r)*256 + h*64;
        const size_t base1 = base0 + 8*256;
        #pragma unroll
        for (int nbo = 0; nbo < 4; nbo++) {
            int c = nbo*16 + q2;
            uint32_t hi, lo;
            split2(o[nbo][0], o[nbo][1], hi, lo);
            *(uint32_t*)(g_oh + base0 + c) = hi;     *(uint32_t*)(g_ol + base0 + c) = lo;
            split2(o[nbo][4], o[nbo][5], hi, lo);
            *(uint32_t*)(g_oh + base0 + c + 8) = hi; *(uint32_t*)(g_ol + base0 + c + 8) = lo;
            split2(o[nbo][2], o[nbo][3], hi, lo);
            *(uint32_t*)(g_oh + base1 + c) = hi;     *(uint32_t*)(g_ol + base1 + c) = lo;
            split2(o[nbo][6], o[nbo][7], hi, lo);
            *(uint32_t*)(g_oh + base1 + c + 8) = hi; *(uint32_t*)(g_ol + base1 + c + 8) = lo;
        }
    }
}

// ------------------------------------------------------------------ K4: per-part FC  out[n,o,p]
__global__ __launch_bounds__(256) void k4_fc(const float* __restrict__ fc, float* __restrict__ out) {
    __shared__ float As[64*68];
    __shared__ float Bs[64*64];
    const int p = blockIdx.x, ot = blockIdx.y;
    const int t = threadIdx.x;
    const int tx = t & 15, ty = t >> 4;
    const int o0 = tx*4, n0 = ty*4;
    float acc[4][4] = {};
    for (int k0 = 0; k0 < 1024; k0 += 64) {
        __syncthreads();
        #pragma unroll
        for (int it = 0; it < 4; it++) {
            int idx = it*256 + t;
            int nn = idx >> 4, k4 = idx & 15;
            *(float4*)(As + nn*68 + k4*4) =
                *(const float4*)(g_clu + ((size_t)p*64 + nn)*1024 + k0 + k4*4);
        }
        #pragma unroll
        for (int it = 0; it < 4; it++) {
            int idx = it*256 + t;
            int kk = idx >> 4, d4 = idx & 15;
            *(float4*)(Bs + kk*64 + d4*4) =
                *(const float4*)(fc + ((size_t)p*1024 + k0 + kk)*256 + ot*64 + d4*4);
        }
        __syncthreads();
        #pragma unroll 4
        for (int kk = 0; kk < 64; kk++) {
            float a[4];
            #pragma unroll
            for (int ii = 0; ii < 4; ii++) a[ii] = As[(n0+ii)*68 + kk];
            float4 bv = *(const float4*)(Bs + kk*64 + o0);
            float bj[4] = {bv.x, bv.y, bv.z, bv.w};
            #pragma unroll
            for (int ii = 0; ii < 4; ii++)
                #pragma unroll
                for (int jj = 0; jj < 4; jj++) acc[ii][jj] += a[ii]*bj[jj];
        }
    }
    #pragma unroll
    for (int ii = 0; ii < 4; ii++)
        #pragma unroll
        for (int jj = 0; jj < 4; jj++)
            out[((size_t)(n0+ii)*256 + ot*64 + o0 + jj)*16 + p] = acc[ii][jj];
}

// ------------------------------------------------------------------ launch (pipelined halves across streams)
extern "C" void kernel_launch(void* const* d_in, const int* in_sizes, int n_in,
                              void* d_out, int out_size) {
    const float* x     = (const float*)d_in[0];
    const float* proto = (const float*)d_in[1];
    const float* Wq    = (const float*)d_in[2];
    const float* bq    = (const float*)d_in[3];
    const float* Wk    = (const float*)d_in[4];
    const float* bk    = (const float*)d_in[5];
    const float* Wv    = (const float*)d_in[6];
    const float* bv    = (const float*)d_in[7];
    const float* Wo    = (const float*)d_in[8];
    const float* bo    = (const float*)d_in[9];
    const float* fc    = (const float*)d_in[10];
    float* out = (float*)d_out;

    cudaFuncSetAttribute(k0_transpose, cudaFuncAttributeMaxDynamicSharedMemorySize, 69632);
    cudaFuncSetAttribute(k1_assign,    cudaFuncAttributeMaxDynamicSharedMemorySize, 73728);
    cudaFuncSetAttribute(k_gemm,       cudaFuncAttributeMaxDynamicSharedMemorySize, GEMM_SMEM);
    cudaFuncSetAttribute(k_attn,       cudaFuncAttributeMaxDynamicSharedMemorySize, ATTN_SMEM);

    cudaStream_t s1, s2;
    cudaStreamCreate(&s1);
    cudaStreamCreate(&s2);
    cudaEvent_t eFork, eW, e0, eK, eG0A, eS2;
    cudaEventCreateWithFlags(&eFork, cudaEventDisableTiming);
    cudaEventCreateWithFlags(&eW,    cudaEventDisableTiming);
    cudaEventCreateWithFlags(&e0,    cudaEventDisableTiming);
    cudaEventCreateWithFlags(&eK,    cudaEventDisableTiming);
    cudaEventCreateWithFlags(&eG0A,  cudaEventDisableTiming);
    cudaEventCreateWithFlags(&eS2,   cudaEventDisableTiming);

    int wtail = (out_size >= NB*CB*PB + NB*SB) ? 1 : 0;

    cudaEventRecord(eFork, 0);
    cudaStreamWaitEvent(s1, eFork, 0);
    k_wprep<<<64, 256, 0, s1>>>(Wq, Wk, Wv, Wo, bq, bk, bv, bo);
    cudaEventRecord(eW, s1);

    k0_transpose<<<dim3(16, 64), 256, 69632>>>(x);
    cudaEventRecord(e0, 0);

    cudaStreamWaitEvent(s2, e0, 0);
    k1_assign<<<NB*PB, 256, (64*257 + 4*257 + 512) * sizeof(float), s2>>>(proto);
    cudaEventRecord(eK, s2);

    cudaStreamWaitEvent(0, eW, 0);
    k_gemm<<<256, 256, GEMM_SMEM>>>(0, 0);           // gemm0 A (b 0..511)
    cudaEventRecord(eG0A, 0);
    k_gemm<<<256, 256, GEMM_SMEM>>>(0, 256);         // gemm0 B (b 512..1023)

    // side pipeline: attnA + gemm1A overlap gemm0B / attnB
    cudaStreamWaitEvent(s2, eG0A, 0);
    k_attn<<<2048, 128, ATTN_SMEM, s2>>>(0);         // attn A
    k_gemm<<<256, 256, GEMM_SMEM, s2>>>(1, 0);       // gemm1 A (after k1 + attnA, both on s2)
    cudaEventRecord(eS2, s2);

    k_attn<<<2048, 128, ATTN_SMEM>>>(2048);          // attn B
    cudaStreamWaitEvent(0, eK, 0);                   // g_hidx ready
    k_gemm<<<256, 256, GEMM_SMEM>>>(1, 256);         // gemm1 B
    cudaStreamWaitEvent(0, eS2, 0);                  // join gemm1 A
    k4_fc<<<dim3(16, 4), 256>>>(fc, out);
    k2_mode<<<16, 256>>>(out, wtail);                // tail write; no downstream deps

    cudaEventDestroy(eFork);
    cudaEventDestroy(eW);
    cudaEventDestroy(e0);
    cudaEventDestroy(eK);
    cudaEventDestroy(eG0A);
    cudaEventDestroy(eS2);
    cudaStreamDestroy(s1);
    cudaStreamDestroy(s2);
}